// round 12
// baseline (speedup 1.0000x reference)
#include <cuda_runtime.h>
#include <cuda_bf16.h>
#include <math.h>
#include <stdint.h>

#define BDIM   32
#define TIN    1000
#define TA     400
#define FDIM   256
#define HDIM   256
#define FRAME  320
#define SHIFT  160
#define LSIG   160000
#define LAUX   64000
#define NCLS   101
#define NSLC   8
#define SLC    (TA / NSLC)
#define MP_IN  1024
#define MP_AX  448
#define LS_PAD 160256
#define LA_PAD 64256

// ---------------- fp32 scratch ----------------
__device__ float g_out   [BDIM * MP_IN * FDIM];
__device__ float g_out2  [BDIM * MP_IN * FDIM];
__device__ float g_aux   [BDIM * MP_AX * FDIM];
__device__ float g_h     [BDIM * MP_AX * HDIM];
__device__ float g_logits[BDIM * MP_AX * HDIM];
__device__ float g_y     [BDIM * MP_IN * FRAME];
__device__ float g_bias2 [BDIM * HDIM];
__device__ float g_emb   [BDIM * FDIM];
__device__ float g_evec  [4 * BDIM * FDIM];
__device__ float g_glnp  [BDIM * 16 * 2];
__device__ float g_hpart [BDIM * NSLC * HDIM * 2];
__device__ float g_ppart [BDIM * NSLC * HDIM * 4];
__device__ float g_uv    [2 * HDIM];

// ---------------- bf16 activation planes ----------------
__device__ __nv_bfloat16 a_sig_hi[BDIM * LS_PAD + 8192];
__device__ __nv_bfloat16 a_sig_lo[BDIM * LS_PAD + 8192];
__device__ __nv_bfloat16 a_anc_hi[BDIM * LA_PAD + 8192];
__device__ __nv_bfloat16 a_anc_lo[BDIM * LA_PAD + 8192];
__device__ __nv_bfloat16 a_out_hi [BDIM * MP_IN * FDIM];
__device__ __nv_bfloat16 a_out_lo [BDIM * MP_IN * FDIM];
__device__ __nv_bfloat16 a_out2_hi[BDIM * MP_IN * FDIM];
__device__ __nv_bfloat16 a_out2_lo[BDIM * MP_IN * FDIM];
__device__ __nv_bfloat16 a_aux_hi[BDIM * MP_AX * FDIM];
__device__ __nv_bfloat16 a_aux_lo[BDIM * MP_AX * FDIM];
__device__ __nv_bfloat16 a_h_hi  [BDIM * MP_AX * HDIM];
__device__ __nv_bfloat16 a_h_lo  [BDIM * MP_AX * HDIM];
__device__ __nv_bfloat16 a_a_hi  [BDIM * MP_AX * HDIM];
__device__ __nv_bfloat16 a_a_lo  [BDIM * MP_AX * HDIM];

// ---------------- bf16 split weight planes, layout [N][K] ----------------
__device__ __nv_bfloat16 w_in_hi [256 * 320];
__device__ __nv_bfloat16 w_in_lo [256 * 320];
__device__ __nv_bfloat16 w_ec_hi [256 * 256];
__device__ __nv_bfloat16 w_ec_lo [256 * 256];
__device__ __nv_bfloat16 w_a1_hi [256 * 256];
__device__ __nv_bfloat16 w_a1_lo [256 * 256];
__device__ __nv_bfloat16 w_a2_hi [256 * 256];
__device__ __nv_bfloat16 w_a2_lo [256 * 256];
__device__ __nv_bfloat16 w_arn_hi[4 * 256 * 256];
__device__ __nv_bfloat16 w_arn_lo[4 * 256 * 256];
__device__ __nv_bfloat16 w_out_hi[320 * 256];
__device__ __nv_bfloat16 w_out_lo[320 * 256];

// ---------------- helpers ----------------
__device__ __forceinline__ uint32_t smem_u32(const void* p) {
    uint32_t a;
    asm("{ .reg .u64 t; cvta.to.shared.u64 t, %1; cvt.u32.u64 %0, t; }" : "=r"(a) : "l"(p));
    return a;
}
__device__ __forceinline__ void ldmx4(uint32_t* r, uint32_t addr) {
    asm volatile("ldmatrix.sync.aligned.m8n8.x4.shared.b16 {%0,%1,%2,%3}, [%4];"
                 : "=r"(r[0]), "=r"(r[1]), "=r"(r[2]), "=r"(r[3]) : "r"(addr));
}
__device__ __forceinline__ void ldmx2(uint32_t* r, uint32_t addr) {
    asm volatile("ldmatrix.sync.aligned.m8n8.x2.shared.b16 {%0,%1}, [%2];"
                 : "=r"(r[0]), "=r"(r[1]) : "r"(addr));
}
__device__ __forceinline__ void mma_bf16(float* c, const uint32_t* a, const uint32_t* b) {
    asm volatile("mma.sync.aligned.m16n8k16.row.col.f32.bf16.bf16.f32 "
                 "{%0,%1,%2,%3}, {%4,%5,%6,%7}, {%8,%9}, {%0,%1,%2,%3};"
                 : "+f"(c[0]), "+f"(c[1]), "+f"(c[2]), "+f"(c[3])
                 : "r"(a[0]), "r"(a[1]), "r"(a[2]), "r"(a[3]), "r"(b[0]), "r"(b[1]));
}
__device__ __forceinline__ void cp16(uint32_t saddr, const void* gaddr) {
    asm volatile("cp.async.ca.shared.global [%0], [%1], 16;" :: "r"(saddr), "l"(gaddr));
}
__device__ __forceinline__ void cp_commit() { asm volatile("cp.async.commit_group;" ::: "memory"); }
template<int W> __device__ __forceinline__ void cp_wait() {
    asm volatile("cp.async.wait_group %0;" :: "n"(W) : "memory");
}
__device__ __forceinline__ uint32_t SWZ(int row, int chunk) {
    return ((uint32_t)row << 7) + ((uint32_t)((chunk ^ (row & 7)) & 7) << 4);
}

// ---------------- weight prep ----------------
struct PrepArgs {
    const float* src[10];
    const float* scl[10];
    __nv_bfloat16* hi[10];
    __nv_bfloat16* lo[10];
    int K[10];
    int N[10];
    int toff[11];
};
__global__ __launch_bounds__(256) void k_prep_all(PrepArgs a)
{
    __shared__ float tile[32][33];
    int tb = blockIdx.x;
    int r = 0;
    while (tb >= a.toff[r + 1]) r++;
    int ti = tb - a.toff[r];
    const int K = a.K[r], N = a.N[r];
    const int ntn = N / 32;
    const int tk = ti / ntn, tn = ti - tk * ntn;
    const int ty = threadIdx.x >> 5, tx = threadIdx.x & 31;
    const float* scl = a.scl[r];
    #pragma unroll
    for (int q = 0; q < 4; q++) {
        const int k = tk * 32 + ty + q * 8;
        float x = a.src[r][(size_t)k * N + tn * 32 + tx];
        if (scl) x *= scl[k];
        tile[ty + q * 8][tx] = x;
    }
    __syncthreads();
    #pragma unroll
    for (int q = 0; q < 4; q++) {
        const int n = tn * 32 + ty + q * 8;
        float x = tile[tx][ty + q * 8];
        __nv_bfloat16 h = __float2bfloat16(x);
        const size_t o = (size_t)n * K + tk * 32 + tx;
        a.hi[r][o] = h;
        a.lo[r][o] = __float2bfloat16(x - __bfloat162float(h));
    }
}

// ---------------- u/v vectors for folded GLN ----------------
__global__ __launch_bounds__(256) void k_uv(const float* __restrict__ W,
                                            const float* __restrict__ gg,
                                            const float* __restrict__ gb)
{
    const int j = threadIdx.x;
    float u = 0.f, v = 0.f;
    for (int k = 0; k < FDIM; k++) {
        float w = W[(size_t)k * HDIM + j];
        u += gb[k] * w;
        v += gg[k] * w;
    }
    g_uv[j] = u;
    g_uv[HDIM + j] = v;
}

// ---------------- signal -> bf16 hi/lo planes ----------------
__global__ __launch_bounds__(256) void k_sigprep(const float* __restrict__ x,
                                                 __nv_bfloat16* __restrict__ hi,
                                                 __nv_bfloat16* __restrict__ lo,
                                                 int L, int LP, int total)
{
    int idx = blockIdx.x * 256 + threadIdx.x;
    if (idx >= total) return;
    float v = 0.f;
    if (idx < BDIM * LP) {
        int b = idx / LP, i = idx - b * LP;
        if (i < L) v = x[(size_t)b * L + i];
    }
    __nv_bfloat16 h = __float2bfloat16(v);
    hi[idx] = h;
    lo[idx] = __float2bfloat16(v - __bfloat162float(h));
}

// ---------------- GEMM args ----------------
struct GArgs {
    const __nv_bfloat16 *Ahi, *Alo;
    const float *Ares;
    const __nv_bfloat16 *Bhi, *Blo;
    float *C;
    __nv_bfloat16 *Chi, *Clo;
    const float *e0, *e1;
    const int *aux_len;
    int Apad, Cpad, M, K, Nfull, arn_i;
    const __nv_bfloat16 *A2hi, *A2lo;
    float *C2;
    __nv_bfloat16 *C2hi, *C2lo;
    int A2pad, C2pad, M2, split;
};

// ---------------- GEMM: single-stage cp.async, 3 CTAs/SM ----------------
template<int NT, int MODE>
__global__ void __launch_bounds__(256, 3) k_tgemm(GArgs g)
{
    constexpr int MT  = 64;
    constexpr int WN  = NT / 4;
    constexpr int NF  = WN / 8;
    constexpr int MI  = 2;
    constexpr int APL = MT * 128;
    constexpr int BPL = NT * 128;
    constexpr bool HASC = (MODE != 2);
    constexpr bool HASP = (MODE == 0 || MODE == 1 || MODE == 2 || MODE == 4);

    extern __shared__ char smem[];
    const uint32_t sb = smem_u32(smem);
    const uint32_t aH = sb;
    const uint32_t aL = sb + APL;
    const uint32_t bH = sb + 2 * APL;
    const uint32_t bL = sb + 2 * APL + BPL;

    const int tid  = threadIdx.x;
    const int w    = tid >> 5;
    const int lane = tid & 31;
    const int b    = blockIdx.y;
    const int nbase = blockIdx.z * NT;

    const __nv_bfloat16* Ahi = g.Ahi;
    const __nv_bfloat16* Alo = g.Alo;
    float* C = g.C;
    __nv_bfloat16 *Chi = g.Chi, *Clo = g.Clo;
    int M = g.M, Apad = g.Apad, Cpad = g.Cpad;
    int bx = blockIdx.x;
    if (MODE == 0 && bx >= g.split) {
        Ahi = g.A2hi; Alo = g.A2lo; C = g.C2; Chi = g.C2hi; Clo = g.C2lo;
        M = g.M2; Apad = g.A2pad; Cpad = g.C2pad; bx -= g.split;
    }
    const int t0 = bx * MT;
    const int K  = g.K;
    const int NB = K / 64;
    const int wm = w >> 2;
    const int wn = w & 3;
    const int wn0 = wn * WN;

    float mean = 0.f, inv = 0.f;
    if (MODE == 1) {
        const int len = g.aux_len[b];
        double s = 0.0, q = 0.0;
        #pragma unroll
        for (int i = 0; i < 16; i++) {
            s += (double)g_glnp[(b * 16 + i) * 2 + 0];
            q += (double)g_glnp[(b * 16 + i) * 2 + 1];
        }
        const double n = (double)len * FDIM;
        double m = s / n;
        double var = q / n - m * m;
        mean = (float)m;
        inv  = (float)(1.0 / sqrt(var + 1e-5));
    }

    float acc[MI][NF][4];
    #pragma unroll
    for (int mi = 0; mi < MI; mi++)
        #pragma unroll
        for (int nj = 0; nj < NF; nj++)
            #pragma unroll
            for (int q = 0; q < 4; q++) acc[mi][nj][q] = 0.f;

    auto cpA = [&](int kb) {
        #pragma unroll
        for (int it = 0; it < 2; it++) {
            const int idx = tid + it * 256;
            const int r = idx >> 3, c = idx & 7;
            size_t off;
            if (MODE == 0)
                off = (size_t)b * Apad + (size_t)(t0 + r) * SHIFT + kb * 64 + c * 8;
            else
                off = ((size_t)b * Apad + (t0 + r)) * (size_t)K + kb * 64 + c * 8;
            const uint32_t so = SWZ(r, c);
            cp16(aH + so, Ahi + off);
            cp16(aL + so, Alo + off);
        }
    };
    auto cpB = [&](int kb) {
        for (int idx = tid; idx < NT * 8; idx += 256) {
            const int n = idx >> 3, c = idx & 7;
            const uint32_t so = SWZ(n, c);
            cp16(bH + so, g.Bhi + (size_t)(nbase + n) * K + kb * 64 + c * 8);
            cp16(bL + so, g.Blo + (size_t)(nbase + n) * K + kb * 64 + c * 8);
        }
    };
    auto compute = [&]() {
        #pragma unroll
        for (int ki = 0; ki < 4; ki++) {
            uint32_t bh[NF][2], bl[NF][2];
            #pragma unroll
            for (int p = 0; p < NF / 2; p++) {
                const int gq = lane >> 3;
                const int nrow = wn0 + p * 16 + ((gq >> 1) << 3) + (lane & 7);
                const int chunk = ki * 2 + (gq & 1);
                const uint32_t off = SWZ(nrow, chunk);
                uint32_t r4[4];
                ldmx4(r4, bH + off);
                bh[2*p][0]=r4[0]; bh[2*p][1]=r4[1]; bh[2*p+1][0]=r4[2]; bh[2*p+1][1]=r4[3];
                ldmx4(r4, bL + off);
                bl[2*p][0]=r4[0]; bl[2*p][1]=r4[1]; bl[2*p+1][0]=r4[2]; bl[2*p+1][1]=r4[3];
            }
            if (NF & 1) {
                const int nj = NF - 1;
                const int nrow = wn0 + nj * 8 + (lane & 7);
                const int chunk = ki * 2 + ((lane & 15) >> 3);
                const uint32_t off = SWZ(nrow, chunk);
                ldmx2(bh[nj], bH + off);
                ldmx2(bl[nj], bL + off);
            }
            #pragma unroll
            for (int mi = 0; mi < MI; mi++) {
                uint32_t ah[4], al[4];
                const int row = wm * 32 + mi * 16 + (lane & 15);
                const int chunk = ki * 2 + (lane >> 4);
                const uint32_t off = SWZ(row, chunk);
                ldmx4(ah, aH + off);
                ldmx4(al, aL + off);
                #pragma unroll
                for (int nj = 0; nj < NF; nj++) {
                    mma_bf16(acc[mi][nj], ah, bh[nj]);
                    mma_bf16(acc[mi][nj], ah, bl[nj]);
                    mma_bf16(acc[mi][nj], al, bh[nj]);
                }
            }
        }
    };

    for (int kb = 0; kb < NB; kb++) {
        cpA(kb);
        cpB(kb);
        cp_commit();
        cp_wait<0>();
        __syncthreads();
        compute();
        __syncthreads();
    }

    // ---- epilogue ----
    #pragma unroll
    for (int mi = 0; mi < MI; mi++) {
        #pragma unroll
        for (int half = 0; half < 2; half++) {
            const int r = wm * 32 + mi * 16 + (lane >> 2) + half * 8;
            const int t = t0 + r;
            if (t >= M) continue;
            #pragma unroll
            for (int nj = 0; nj < NF; nj++) {
                const int col = nbase + wn0 + nj * 8 + (lane & 3) * 2;
                float v0 = acc[mi][nj][half * 2 + 0];
                float v1 = acc[mi][nj][half * 2 + 1];
                float r0, r1;
                if (MODE == 0 || MODE == 3) {
                    r0 = v0 + g.e0[col]; r1 = v1 + g.e0[col + 1];
                } else if (MODE == 1) {
                    r0 = fmaxf(inv * v0 + g.e0[col]     + g_uv[col]     - inv * mean * g_uv[HDIM + col],     0.f);
                    r1 = fmaxf(inv * v1 + g.e0[col + 1] + g_uv[col + 1] - inv * mean * g_uv[HDIM + col + 1], 0.f);
                } else if (MODE == 2) {
                    float a0 = fmaxf(v0 + g_bias2[b * HDIM + col],     0.f);
                    float a1 = fmaxf(v1 + g_bias2[b * HDIM + col + 1], 0.f);
                    r0 = tanhf(a0 * g.e0[col]     + g.e1[col]);
                    r1 = tanhf(a1 * g.e0[col + 1] + g.e1[col + 1]);
                } else { // MODE 4
                    const float* ares = g.Ares + ((size_t)b * Apad + t) * (size_t)K + col;
                    const float* ev   = g_evec + ((size_t)g.arn_i * BDIM + b) * FDIM + col;
                    r0 = ares[0] + tanhf(v0 + ev[0] + g.e0[col]);
                    r1 = ares[1] + tanhf(v1 + ev[1] + g.e0[col + 1]);
                }
                const size_t co = ((size_t)b * Cpad + t) * (size_t)g.Nfull + col;
                if (HASC) *(float2*)(C + co) = make_float2(r0, r1);
                if (HASP) {
                    __nv_bfloat162 hp, lp;
                    hp.x = __float2bfloat16(r0);
                    hp.y = __float2bfloat16(r1);
                    lp.x = __float2bfloat16(r0 - __bfloat162float(hp.x));
                    lp.y = __float2bfloat16(r1 - __bfloat162float(hp.y));
                    *(__nv_bfloat162*)(Chi + co) = hp;
                    *(__nv_bfloat162*)(Clo + co) = lp;
                }
            }
        }
    }
}

// ---------------- GLN partials ----------------
__global__ __launch_bounds__(256) void k_gln_part(const int* __restrict__ aux_len)
{
    const int b = blockIdx.x, s = blockIdx.y;
    const int len = aux_len[b];
    const int tA = s * (TA / 16);
    const int tB = min(len, tA + TA / 16);
    float sum = 0.f, sq = 0.f;
    if (tB > tA) {
        const float* p = g_aux + ((size_t)b * MP_AX + tA) * FDIM;
        const int n = (tB - tA) * FDIM;
        for (int i = threadIdx.x; i < n; i += 256) {
            float v = p[i];
            sum += v; sq += v * v;
        }
    }
    __shared__ float ss[256], qq[256];
    ss[threadIdx.x] = sum; qq[threadIdx.x] = sq;
    __syncthreads();
    for (int st = 128; st > 0; st >>= 1) {
        if (threadIdx.x < st) { ss[threadIdx.x] += ss[threadIdx.x + st]; qq[threadIdx.x] += qq[threadIdx.x + st]; }
        __syncthreads();
    }
    if (threadIdx.x == 0) {
        g_glnp[(b * 16 + s) * 2 + 0] = ss[0];
        g_glnp[(b * 16 + s) * 2 + 1] = qq[0];
    }
}

// ---------------- h stats partials + combine ----------------
__global__ __launch_bounds__(256) void k_hpart(const int* __restrict__ aux_len)
{
    const int b = blockIdx.x, s = blockIdx.y, ch = threadIdx.x;
    const int len = aux_len[b];
    const int tA = s * SLC;
    const int tB = min(len, tA + SLC);
    float sum = 0.f, sq = 0.f;
    const float* p = g_h + ((size_t)b * MP_AX) * HDIM + ch;
    for (int t = tA; t < tB; t++) {
        float v = p[(size_t)t * HDIM];
        sum += v; sq += v * v;
    }
    float* o = g_hpart + (((size_t)b * NSLC + s) * HDIM + ch) * 2;
    o[0] = sum; o[1] = sq;
}
__global__ __launch_bounds__(256) void k_hcomb(const int* __restrict__ aux_len,
                                               const float* __restrict__ att_w1,
                                               const float* __restrict__ att_b1)
{
    const int b = blockIdx.x, ch = threadIdx.x;
    const int len = aux_len[b];
    __shared__ float sm[256], sstd[256];
    {
        float sum = 0.f, sq = 0.f;
        #pragma unroll
        for (int s = 0; s < NSLC; s++) {
            const float* o = g_hpart + (((size_t)b * NSLC + s) * HDIM + ch) * 2;
            sum += o[0]; sq += o[1];
        }
        const float n = (float)len;
        const float m = sum / n;
        const float var = (sq - n * m * m) / (n - 1.f);
        sm[ch] = m;
        sstd[ch] = sqrtf(fmaxf(var, 1e-4f));
    }
    __syncthreads();
    float acc = att_b1[ch];
    for (int k = 0; k < HDIM; k++) {
        acc += sm[k]   * att_w1[(size_t)(256 + k) * HDIM + ch]
             + sstd[k] * att_w1[(size_t)(512 + k) * HDIM + ch];
    }
    g_bias2[b * HDIM + ch] = acc;
}

// ---------------- pool partials + combine ----------------
__global__ __launch_bounds__(256) void k_ppart(const int* __restrict__ aux_len)
{
    const int b = blockIdx.x, s = blockIdx.y, ch = threadIdx.x;
    const int len = aux_len[b];
    const int tA = s * SLC;
    const int tB = min(len, tA + SLC);
    const float* lp = g_logits + (size_t)b * MP_AX * HDIM + ch;
    const float* hp = g_h      + (size_t)b * MP_AX * HDIM + ch;
    float mx = -1e30f, se = 0.f, s1 = 0.f, s2 = 0.f;
    for (int t = tA; t < tB; t++) {
        float l  = lp[(size_t)t * HDIM];
        float hv = hp[(size_t)t * HDIM];
        if (l > mx) {
            float sc = expf(mx - l);
            se *= sc; s1 *= sc; s2 *= sc;
            mx = l;
        }
        float e = expf(l - mx);
        se += e; s1 += hv * e; s2 += hv * hv * e;
    }
    float* o = g_ppart + (((size_t)b * NSLC + s) * HDIM + ch) * 4;
    o[0] = mx; o[1] = se; o[2] = s1; o[3] = s2;
}
__global__ __launch_bounds__(256) void k_pcomb(const float* __restrict__ bn5g,
                                               const float* __restrict__ bn5b,
                                               const float* __restrict__ fc6_w,
                                               const float* __restrict__ fc6_b,
                                               const float* __restrict__ bn6g,
                                               const float* __restrict__ bn6b,
                                               const float* __restrict__ cls_w,
                                               const float* __restrict__ cls_b,
                                               const float* __restrict__ arn_w2,
                                               float* __restrict__ out_cls, int write_cls)
{
    const int b = blockIdx.x, j = threadIdx.x;
    __shared__ float e[2 * HDIM];
    {
        float mx = -1e30f;
        float pm[NSLC];
        #pragma unroll
        for (int s = 0; s < NSLC; s++) {
            pm[s] = g_ppart[(((size_t)b * NSLC + s) * HDIM + j) * 4];
            mx = fmaxf(mx, pm[s]);
        }
        float se = 0.f, s1 = 0.f, s2 = 0.f;
        #pragma unroll
        for (int s = 0; s < NSLC; s++) {
            const float* o = g_ppart + (((size_t)b * NSLC + s) * HDIM + j) * 4;
            float sc = expf(pm[s] - mx);
            se += o[1] * sc; s1 += o[2] * sc; s2 += o[3] * sc;
        }
        float mu = s1 / se;
        float sg = sqrtf(fmaxf(s2 / se - mu * mu, 1e-4f));
        e[j]        = mu * bn5g[j]        + bn5b[j];
        e[j + HDIM] = sg * bn5g[HDIM + j] + bn5b[HDIM + j];
    }
    __syncthreads();
    float acc = fc6_b[j];
    for (int k = 0; k < 2 * HDIM; k++) acc += e[k] * fc6_w[(size_t)k * FDIM + j];
    const float em = acc * bn6g[j] + bn6b[j];
    g_emb[b * FDIM + j] = em;

    __shared__ float red[256];
    red[j] = em * em;
    __syncthreads();
    for (int st = 128; st > 0; st >>= 1) { if (j < st) red[j] += red[j + st]; __syncthreads(); }
    const float nrmv = fmaxf(sqrtf(red[0]), 1e-12f);
    __shared__ float emv[256];
    emv[j] = em;
    __syncthreads();
    if (write_cls && j < NCLS) {
        float c = cls_b[j];
        for (int k = 0; k < FDIM; k++) c += (emv[k] / nrmv) * cls_w[(size_t)k * NCLS + j];
        out_cls[b * NCLS + j] = c;
    }
    for (int i = 0; i < 4; i++) {
        const float* W = arn_w2 + (size_t)i * FDIM * FDIM;
        float a2 = 0.f;
        for (int k = 0; k < FDIM; k++) a2 += emv[k] * W[(size_t)k * FDIM + j];
        g_evec[((size_t)i * BDIM + b) * FDIM + j] = a2;
    }
}

__global__ __launch_bounds__(256) void k_ola(float* __restrict__ out)
{
    const int idx = blockIdx.x * blockDim.x + threadIdx.x;
    if (idx >= BDIM * LSIG) return;
    const int b = idx / LSIG;
    const int i = idx - b * LSIG;
    const int t = i / SHIFT;
    const int j = i - t * SHIFT;
    const float* yb = g_y + (size_t)b * MP_IN * FRAME;
    float v = yb[(size_t)t * FRAME + j];
    if (t > 0) { v += yb[(size_t)(t - 1) * FRAME + j + SHIFT]; v *= 0.5f; }
    out[idx] = v;
}

// ---------------- launch ----------------
extern "C" void kernel_launch(void* const* d_in, const int* in_sizes, int n_in,
                              void* d_out, int out_size)
{
    const float* input   = (const float*)d_in[0];
    const float* anchor  = (const float*)d_in[1];
    const int*   aux_len = (const int*)  d_in[2];
    const float* in_w    = (const float*)d_in[4];
    const float* in_b    = (const float*)d_in[5];
    const float* out_w   = (const float*)d_in[6];
    const float* out_b   = (const float*)d_in[7];
    const float* gln_g   = (const float*)d_in[8];
    const float* gln_b   = (const float*)d_in[9];
    const float* ecapa_w = (const float*)d_in[10];
    const float* ecapa_b = (const float*)d_in[11];
    const float* att_w1  = (const float*)d_in[12];
    const float* att_b1  = (const float*)d_in[13];
    const float* attbn_g = (const float*)d_in[14];
    const float* attbn_b = (const float*)d_in[15];
    const float* att_w2  = (const float*)d_in[16];
    const float* att_b2  = (const float*)d_in[17];
    const float* bn5_g   = (const float*)d_in[18];
    const float* bn5_b   = (const float*)d_in[19];
    const float* fc6_w   = (const float*)d_in[20];
    const float* fc6_b   = (const float*)d_in[21];
    const float* bn6_g   = (const float*)d_in[22];
    const float* bn6_b   = (const float*)d_in[23];
    const float* cls_w   = (const float*)d_in[24];
    const float* cls_b   = (const float*)d_in[25];
    const float* arn_w1  = (const float*)d_in[26];
    const float* arn_w2  = (const float*)d_in[27];
    const float* arn_b   = (const float*)d_in[28];

    float *p_out, *p_out2, *p_aux, *p_h, *p_logits, *p_y;
    cudaGetSymbolAddress((void**)&p_out,    g_out);
    cudaGetSymbolAddress((void**)&p_out2,   g_out2);
    cudaGetSymbolAddress((void**)&p_aux,    g_aux);
    cudaGetSymbolAddress((void**)&p_h,      g_h);
    cudaGetSymbolAddress((void**)&p_logits, g_logits);
    cudaGetSymbolAddress((void**)&p_y,      g_y);

    __nv_bfloat16 *sig_h, *sig_l, *anc_h, *anc_l;
    __nv_bfloat16 *o_h, *o_l, *o2_h, *o2_l, *ax_h, *ax_l, *h_h, *h_l, *aa_h, *aa_l;
    cudaGetSymbolAddress((void**)&sig_h, a_sig_hi); cudaGetSymbolAddress((void**)&sig_l, a_sig_lo);
    cudaGetSymbolAddress((void**)&anc_h, a_anc_hi); cudaGetSymbolAddress((void**)&anc_l, a_anc_lo);
    cudaGetSymbolAddress((void**)&o_h,  a_out_hi);  cudaGetSymbolAddress((void**)&o_l,  a_out_lo);
    cudaGetSymbolAddress((void**)&o2_h, a_out2_hi); cudaGetSymbolAddress((void**)&o2_l, a_out2_lo);
    cudaGetSymbolAddress((void**)&ax_h, a_aux_hi);  cudaGetSymbolAddress((void**)&ax_l, a_aux_lo);
    cudaGetSymbolAddress((void**)&h_h,  a_h_hi);    cudaGetSymbolAddress((void**)&h_l,  a_h_lo);
    cudaGetSymbolAddress((void**)&aa_h, a_a_hi);    cudaGetSymbolAddress((void**)&aa_l, a_a_lo);

    __nv_bfloat16 *pw_in_h, *pw_in_l, *pw_ec_h, *pw_ec_l, *pw_a1_h, *pw_a1_l,
                  *pw_a2_h, *pw_a2_l, *pw_ar_h, *pw_ar_l, *pw_ou_h, *pw_ou_l;
    cudaGetSymbolAddress((void**)&pw_in_h, w_in_hi);  cudaGetSymbolAddress((void**)&pw_in_l, w_in_lo);
    cudaGetSymbolAddress((void**)&pw_ec_h, w_ec_hi);  cudaGetSymbolAddress((void**)&pw_ec_l, w_ec_lo);
    cudaGetSymbolAddress((void**)&pw_a1_h, w_a1_hi);  cudaGetSymbolAddress((void**)&pw_a1_l, w_a1_lo);
    cudaGetSymbolAddress((void**)&pw_a2_h, w_a2_hi);  cudaGetSymbolAddress((void**)&pw_a2_l, w_a2_lo);
    cudaGetSymbolAddress((void**)&pw_ar_h, w_arn_hi); cudaGetSymbolAddress((void**)&pw_ar_l, w_arn_lo);
    cudaGetSymbolAddress((void**)&pw_ou_h, w_out_hi); cudaGetSymbolAddress((void**)&pw_ou_l, w_out_lo);

    // ---- prep ----
    PrepArgs pa;
    int toff = 0;
    auto rg = [&](int r, const float* s, const float* sc, __nv_bfloat16* h, __nv_bfloat16* l, int K, int N) {
        pa.src[r] = s; pa.scl[r] = sc; pa.hi[r] = h; pa.lo[r] = l; pa.K[r] = K; pa.N[r] = N;
        pa.toff[r] = toff; toff += (K / 32) * (N / 32);
    };
    rg(0, in_w,    nullptr, pw_in_h, pw_in_l, 320, 256);
    rg(1, ecapa_w, gln_g,   pw_ec_h, pw_ec_l, 256, 256);
    rg(2, att_w1,  nullptr, pw_a1_h, pw_a1_l, 256, 256);
    rg(3, att_w2,  nullptr, pw_a2_h, pw_a2_l, 256, 256);
    for (int i = 0; i < 4; i++)
        rg(4 + i, arn_w1 + (size_t)i * 65536, nullptr, pw_ar_h + (size_t)i * 65536,
           pw_ar_l + (size_t)i * 65536, 256, 256);
    rg(8, out_w, nullptr, pw_ou_h, pw_ou_l, 256, 320);
    pa.toff[9] = toff;
    pa.src[9] = out_w; pa.scl[9] = nullptr; pa.hi[9] = pw_ou_h; pa.lo[9] = pw_ou_l;
    pa.K[9] = 256; pa.N[9] = 320;
    pa.toff[10] = toff;
    k_prep_all<<<toff, 256>>>(pa);
    k_uv<<<1, 256>>>(ecapa_w, gln_g, gln_b);
    {
        int tot_s = BDIM * LS_PAD + 8192;
        int tot_a = BDIM * LA_PAD + 8192;
        k_sigprep<<<(tot_s + 255) / 256, 256>>>(input,  sig_h, sig_l, LSIG, LS_PAD, tot_s);
        k_sigprep<<<(tot_a + 255) / 256, 256>>>(anchor, anc_h, anc_l, LAUX, LA_PAD, tot_a);
    }

    // single-stage smem: 2 A planes + 2 B planes
    const int SM128 = 2 * 8192 + 2 * 128 * 128;   // 49152
    const int SM160 = 2 * 8192 + 2 * 160 * 128;   // 57344
    cudaFuncSetAttribute(k_tgemm<128,0>, cudaFuncAttributeMaxDynamicSharedMemorySize, SM128);
    cudaFuncSetAttribute(k_tgemm<128,1>, cudaFuncAttributeMaxDynamicSharedMemorySize, SM128);
    cudaFuncSetAttribute(k_tgemm<128,2>, cudaFuncAttributeMaxDynamicSharedMemorySize, SM128);
    cudaFuncSetAttribute(k_tgemm<128,3>, cudaFuncAttributeMaxDynamicSharedMemorySize, SM128);
    cudaFuncSetAttribute(k_tgemm<128,4>, cudaFuncAttributeMaxDynamicSharedMemorySize, SM128);
    cudaFuncSetAttribute(k_tgemm<160,3>, cudaFuncAttributeMaxDynamicSharedMemorySize, SM160);

    GArgs ga;
    memset(&ga, 0, sizeof(ga));
    ga.aux_len = aux_len;

    // 1. merged encoders
    ga.Ahi = sig_h; ga.Alo = sig_l; ga.Apad = LS_PAD;
    ga.Bhi = pw_in_h; ga.Blo = pw_in_l;
    ga.C = p_out; ga.Chi = o_h; ga.Clo = o_l; ga.Cpad = MP_IN;
    ga.e0 = in_b; ga.M = TIN; ga.K = FRAME; ga.Nfull = FDIM;
    ga.A2hi = anc_h; ga.A2lo = anc_l; ga.A2pad = LA_PAD;
    ga.C2 = p_aux; ga.C2hi = ax_h; ga.C2lo = ax_l; ga.C2pad = MP_AX;
    ga.M2 = TA; ga.split = 16;
    k_tgemm<128,0><<<dim3(23, 32, 2), 256, SM128>>>(ga);

    // 2. GLN partials
    k_gln_part<<<dim3(32, 16), 256>>>(aux_len);

    // 3. ecapa (folded GLN)
    GArgs gb1 = ga;
    gb1.Ahi = ax_h; gb1.Alo = ax_l; gb1.Apad = MP_AX;
    gb1.Bhi = pw_ec_h; gb1.Blo = pw_ec_l;
    gb1.C = p_h; gb1.Chi = h_h; gb1.Clo = h_l; gb1.Cpad = MP_AX;
    gb1.e0 = ecapa_b; gb1.M = TA; gb1.K = FDIM; gb1.Nfull = HDIM; gb1.split = 0;
    k_tgemm<128,1><<<dim3(7, 32, 2), 256, SM128>>>(gb1);

    // 4. h stats + attention bias
    k_hpart<<<dim3(32, NSLC), 256>>>(aux_len);
    k_hcomb<<<32, 256>>>(aux_len, att_w1, att_b1);

    // 5. att1
    GArgs gb2 = gb1;
    gb2.Ahi = h_h; gb2.Alo = h_l;
    gb2.Bhi = pw_a1_h; gb2.Blo = pw_a1_l;
    gb2.C = nullptr; gb2.Chi = aa_h; gb2.Clo = aa_l;
    gb2.e0 = attbn_g; gb2.e1 = attbn_b;
    k_tgemm<128,2><<<dim3(7, 32, 2), 256, SM128>>>(gb2);

    // 6. att2
    GArgs gb3 = gb2;
    gb3.Ahi = aa_h; gb3.Alo = aa_l;
    gb3.Bhi = pw_a2_h; gb3.Blo = pw_a2_l;
    gb3.C = p_logits; gb3.Chi = nullptr; gb3.Clo = nullptr;
    gb3.e0 = att_b2;
    k_tgemm<128,3><<<dim3(7, 32, 2), 256, SM128>>>(gb3);

    // 7. pool + emb + classifier + evec
    k_ppart<<<dim3(32, NSLC), 256>>>(aux_len);
    const int write_cls = (out_size >= BDIM * LSIG + BDIM * NCLS) ? 1 : 0;
    k_pcomb<<<32, 256>>>(bn5_g, bn5_b, fc6_w, fc6_b, bn6_g, bn6_b, cls_w, cls_b,
                         arn_w2, (float*)d_out + (size_t)BDIM * LSIG, write_cls);

    // 8-11. ARN blocks (ping-pong planes + fp32 residual)
    const __nv_bfloat16 *sa_h = o_h, *sa_l = o_l;
    const float* sres = p_out;
    __nv_bfloat16 *da_h = o2_h, *da_l = o2_l;
    float* dres = p_out2;
    for (int i = 0; i < 4; i++) {
        GArgs gr = ga;
        gr.Ahi = sa_h; gr.Alo = sa_l; gr.Ares = sres; gr.Apad = MP_IN;
        gr.Bhi = pw_ar_h + (size_t)i * 65536; gr.Blo = pw_ar_l + (size_t)i * 65536;
        gr.C = dres; gr.Chi = da_h; gr.Clo = da_l; gr.Cpad = MP_IN;
        gr.e0 = arn_b + i * FDIM; gr.M = TIN; gr.K = FDIM; gr.Nfull = FDIM;
        gr.arn_i = i; gr.split = 0;
        k_tgemm<128,4><<<dim3(16, 32, 2), 256, SM128>>>(gr);
        const __nv_bfloat16* th = sa_h; sa_h = da_h; da_h = (__nv_bfloat16*)th;
        const __nv_bfloat16* tl = sa_l; sa_l = da_l; da_l = (__nv_bfloat16*)tl;
        const float* tr = sres; sres = dres; dres = (float*)tr;
    }

    // 12. decoder
    GArgs gd = ga;
    gd.Ahi = sa_h; gd.Alo = sa_l; gd.Apad = MP_IN;
    gd.Bhi = pw_ou_h; gd.Blo = pw_ou_l;
    gd.C = p_y; gd.Chi = nullptr; gd.Clo = nullptr; gd.Cpad = MP_IN;
    gd.e0 = out_b; gd.M = TIN; gd.K = FDIM; gd.Nfull = FRAME; gd.split = 0;
    k_tgemm<160,3><<<dim3(16, 32, 2), 256, SM160>>>(gd);

    // 13. OLA
    k_ola<<<(BDIM * LSIG + 255) / 256, 256>>>((float*)d_out);
}

// round 13
// speedup vs baseline: 1.2822x; 1.2822x over previous
#include <cuda_runtime.h>
#include <cuda_bf16.h>
#include <math.h>
#include <stdint.h>

#define BDIM   32
#define TIN    1000
#define TA     400
#define FDIM   256
#define HDIM   256
#define FRAME  320
#define SHIFT  160
#define LSIG   160000
#define LAUX   64000
#define NCLS   101
#define NSLC   8
#define SLC    (TA / NSLC)
#define MP_IN  1024
#define MP_AX  448
#define LS_PAD 160256
#define LA_PAD 64256

// ---------------- fp32 scratch ----------------
__device__ float g_out   [BDIM * MP_IN * FDIM];
__device__ float g_out2  [BDIM * MP_IN * FDIM];
__device__ float g_aux   [BDIM * MP_AX * FDIM];
__device__ float g_h     [BDIM * MP_AX * HDIM];
__device__ float g_logits[BDIM * MP_AX * HDIM];
__device__ float g_y     [BDIM * MP_IN * FRAME];
__device__ float g_bias2 [BDIM * HDIM];
__device__ float g_emb   [BDIM * FDIM];
__device__ float g_evec  [4 * BDIM * FDIM];
__device__ float g_glnp  [BDIM * 16 * 2];
__device__ float g_hpart [BDIM * NSLC * HDIM * 2];
__device__ float g_ppart [BDIM * NSLC * HDIM * 4];
__device__ float g_uv    [2 * HDIM];

// ---------------- bf16 activation planes ----------------
__device__ __nv_bfloat16 a_sig_hi[BDIM * LS_PAD + 8192];
__device__ __nv_bfloat16 a_sig_lo[BDIM * LS_PAD + 8192];
__device__ __nv_bfloat16 a_anc_hi[BDIM * LA_PAD + 8192];
__device__ __nv_bfloat16 a_anc_lo[BDIM * LA_PAD + 8192];
__device__ __nv_bfloat16 a_out_hi [BDIM * MP_IN * FDIM];
__device__ __nv_bfloat16 a_out_lo [BDIM * MP_IN * FDIM];
__device__ __nv_bfloat16 a_out2_hi[BDIM * MP_IN * FDIM];
__device__ __nv_bfloat16 a_out2_lo[BDIM * MP_IN * FDIM];
__device__ __nv_bfloat16 a_aux_hi[BDIM * MP_AX * FDIM];
__device__ __nv_bfloat16 a_aux_lo[BDIM * MP_AX * FDIM];
__device__ __nv_bfloat16 a_h_hi  [BDIM * MP_AX * HDIM];
__device__ __nv_bfloat16 a_h_lo  [BDIM * MP_AX * HDIM];
__device__ __nv_bfloat16 a_a_hi  [BDIM * MP_AX * HDIM];
__device__ __nv_bfloat16 a_a_lo  [BDIM * MP_AX * HDIM];

// ---------------- bf16 split weight planes, layout [N][K] ----------------
__device__ __nv_bfloat16 w_in_hi [256 * 320];
__device__ __nv_bfloat16 w_in_lo [256 * 320];
__device__ __nv_bfloat16 w_ec_hi [256 * 256];
__device__ __nv_bfloat16 w_ec_lo [256 * 256];
__device__ __nv_bfloat16 w_a1_hi [256 * 256];
__device__ __nv_bfloat16 w_a1_lo [256 * 256];
__device__ __nv_bfloat16 w_a2_hi [256 * 256];
__device__ __nv_bfloat16 w_a2_lo [256 * 256];
__device__ __nv_bfloat16 w_arn_hi[4 * 256 * 256];
__device__ __nv_bfloat16 w_arn_lo[4 * 256 * 256];
__device__ __nv_bfloat16 w_out_hi[320 * 256];
__device__ __nv_bfloat16 w_out_lo[320 * 256];

// ---------------- helpers ----------------
__device__ __forceinline__ uint32_t smem_u32(const void* p) {
    uint32_t a;
    asm("{ .reg .u64 t; cvta.to.shared.u64 t, %1; cvt.u32.u64 %0, t; }" : "=r"(a) : "l"(p));
    return a;
}
__device__ __forceinline__ void ldmx4(uint32_t* r, uint32_t addr) {
    asm volatile("ldmatrix.sync.aligned.m8n8.x4.shared.b16 {%0,%1,%2,%3}, [%4];"
                 : "=r"(r[0]), "=r"(r[1]), "=r"(r[2]), "=r"(r[3]) : "r"(addr));
}
__device__ __forceinline__ void mma_bf16(float* c, const uint32_t* a, const uint32_t* b) {
    asm volatile("mma.sync.aligned.m16n8k16.row.col.f32.bf16.bf16.f32 "
                 "{%0,%1,%2,%3}, {%4,%5,%6,%7}, {%8,%9}, {%0,%1,%2,%3};"
                 : "+f"(c[0]), "+f"(c[1]), "+f"(c[2]), "+f"(c[3])
                 : "r"(a[0]), "r"(a[1]), "r"(a[2]), "r"(a[3]), "r"(b[0]), "r"(b[1]));
}
__device__ __forceinline__ void cp16(uint32_t saddr, const void* gaddr) {
    asm volatile("cp.async.ca.shared.global [%0], [%1], 16;" :: "r"(saddr), "l"(gaddr));
}
__device__ __forceinline__ void cp_commit() { asm volatile("cp.async.commit_group;" ::: "memory"); }
template<int W> __device__ __forceinline__ void cp_wait() {
    asm volatile("cp.async.wait_group %0;" :: "n"(W) : "memory");
}
__device__ __forceinline__ uint32_t SWZ(int row, int chunk) {
    return ((uint32_t)row << 7) + ((uint32_t)((chunk ^ (row & 7)) & 7) << 4);
}

// ---------------- weight prep ----------------
struct PrepArgs {
    const float* src[10];
    const float* scl[10];
    __nv_bfloat16* hi[10];
    __nv_bfloat16* lo[10];
    int K[10];
    int N[10];
    int toff[11];
};
__global__ __launch_bounds__(256) void k_prep_all(PrepArgs a)
{
    __shared__ float tile[32][33];
    int tb = blockIdx.x;
    int r = 0;
    while (tb >= a.toff[r + 1]) r++;
    int ti = tb - a.toff[r];
    const int K = a.K[r], N = a.N[r];
    const int ntn = N / 32;
    const int tk = ti / ntn, tn = ti - tk * ntn;
    const int ty = threadIdx.x >> 5, tx = threadIdx.x & 31;
    const float* scl = a.scl[r];
    #pragma unroll
    for (int q = 0; q < 4; q++) {
        const int k = tk * 32 + ty + q * 8;
        float x = a.src[r][(size_t)k * N + tn * 32 + tx];
        if (scl) x *= scl[k];
        tile[ty + q * 8][tx] = x;
    }
    __syncthreads();
    #pragma unroll
    for (int q = 0; q < 4; q++) {
        const int n = tn * 32 + ty + q * 8;
        float x = tile[tx][ty + q * 8];
        __nv_bfloat16 h = __float2bfloat16(x);
        const size_t o = (size_t)n * K + tk * 32 + tx;
        a.hi[r][o] = h;
        a.lo[r][o] = __float2bfloat16(x - __bfloat162float(h));
    }
}

// ---------------- u/v vectors for folded GLN ----------------
__global__ __launch_bounds__(256) void k_uv(const float* __restrict__ W,
                                            const float* __restrict__ gg,
                                            const float* __restrict__ gb)
{
    const int j = threadIdx.x;
    float u = 0.f, v = 0.f;
    for (int k = 0; k < FDIM; k++) {
        float w = W[(size_t)k * HDIM + j];
        u += gb[k] * w;
        v += gg[k] * w;
    }
    g_uv[j] = u;
    g_uv[HDIM + j] = v;
}

// ---------------- signal -> bf16 hi/lo planes ----------------
__global__ __launch_bounds__(256) void k_sigprep(const float* __restrict__ x,
                                                 __nv_bfloat16* __restrict__ hi,
                                                 __nv_bfloat16* __restrict__ lo,
                                                 int L, int LP, int total)
{
    int idx = blockIdx.x * 256 + threadIdx.x;
    if (idx >= total) return;
    float v = 0.f;
    if (idx < BDIM * LP) {
        int b = idx / LP, i = idx - b * LP;
        if (i < L) v = x[(size_t)b * L + i];
    }
    __nv_bfloat16 h = __float2bfloat16(v);
    hi[idx] = h;
    lo[idx] = __float2bfloat16(v - __bfloat162float(h));
}

// ---------------- GEMM args ----------------
struct GArgs {
    const __nv_bfloat16 *Ahi, *Alo;
    const float *Ares;
    const __nv_bfloat16 *Bhi, *Blo;
    float *C;
    __nv_bfloat16 *Chi, *Clo;
    const float *e0, *e1;
    const int *aux_len;
    int Apad, Cpad, M, K, Nfull, arn_i;
    const __nv_bfloat16 *A2hi, *A2lo;
    float *C2;
    __nv_bfloat16 *C2hi, *C2lo;
    int A2pad, C2pad, M2, split;
};

// ---------------- GEMM: 64x64 tile, double-buffered cp.async, 3 CTAs/SM ----------------
// warps: 2(m) x 4(n); MI=2, NF=2; NT=64 (z-split covers N)
template<int MODE>
__global__ void __launch_bounds__(256, 3) k_tgemm(GArgs g)
{
    constexpr int MT  = 64;
    constexpr int NT  = 64;
    constexpr int NF  = 2;
    constexpr int MI  = 2;
    constexpr int APL = MT * 128;            // 8192
    constexpr int BPL = NT * 128;            // 8192
    constexpr int SS  = 2 * APL + 2 * BPL;   // 32768 per stage
    constexpr bool HASC = (MODE != 2);
    constexpr bool HASP = (MODE == 0 || MODE == 1 || MODE == 2 || MODE == 4);

    extern __shared__ char smem[];
    const uint32_t sb = smem_u32(smem);

    const int tid  = threadIdx.x;
    const int w    = tid >> 5;
    const int lane = tid & 31;
    const int b    = blockIdx.y;
    const int nbase = blockIdx.z * NT;

    const __nv_bfloat16* Ahi = g.Ahi;
    const __nv_bfloat16* Alo = g.Alo;
    float* C = g.C;
    __nv_bfloat16 *Chi = g.Chi, *Clo = g.Clo;
    int M = g.M, Apad = g.Apad, Cpad = g.Cpad;
    int bx = blockIdx.x;
    if (MODE == 0 && bx >= g.split) {
        Ahi = g.A2hi; Alo = g.A2lo; C = g.C2; Chi = g.C2hi; Clo = g.C2lo;
        M = g.M2; Apad = g.A2pad; Cpad = g.C2pad; bx -= g.split;
    }
    const int t0 = bx * MT;
    const int K  = g.K;
    const int NB = K / 64;
    const int wm = w >> 2;
    const int wn = w & 3;
    const int wn0 = wn * 16;

    float mean = 0.f, inv = 0.f;
    if (MODE == 1) {
        const int len = g.aux_len[b];
        double s = 0.0, q = 0.0;
        #pragma unroll
        for (int i = 0; i < 16; i++) {
            s += (double)g_glnp[(b * 16 + i) * 2 + 0];
            q += (double)g_glnp[(b * 16 + i) * 2 + 1];
        }
        const double n = (double)len * FDIM;
        double m = s / n;
        double var = q / n - m * m;
        mean = (float)m;
        inv  = (float)(1.0 / sqrt(var + 1e-5));
    }

    float acc[MI][NF][4];
    #pragma unroll
    for (int mi = 0; mi < MI; mi++)
        #pragma unroll
        for (int nj = 0; nj < NF; nj++)
            #pragma unroll
            for (int q = 0; q < 4; q++) acc[mi][nj][q] = 0.f;

    auto cpA = [&](int kb, int buf) {
        const uint32_t aH = sb + (uint32_t)buf * SS;
        const uint32_t aL = aH + APL;
        #pragma unroll
        for (int it = 0; it < 2; it++) {
            const int idx = tid + it * 256;
            const int r = idx >> 3, c = idx & 7;
            size_t off;
            if (MODE == 0)
                off = (size_t)b * Apad + (size_t)(t0 + r) * SHIFT + kb * 64 + c * 8;
            else
                off = ((size_t)b * Apad + (t0 + r)) * (size_t)K + kb * 64 + c * 8;
            const uint32_t so = SWZ(r, c);
            cp16(aH + so, Ahi + off);
            cp16(aL + so, Alo + off);
        }
    };
    auto cpB = [&](int kb, int buf) {
        const uint32_t bH = sb + (uint32_t)buf * SS + 2 * APL;
        const uint32_t bL = bH + BPL;
        #pragma unroll
        for (int it = 0; it < 2; it++) {
            const int idx = tid + it * 256;
            const int n = idx >> 3, c = idx & 7;
            const uint32_t so = SWZ(n, c);
            cp16(bH + so, g.Bhi + (size_t)(nbase + n) * K + kb * 64 + c * 8);
            cp16(bL + so, g.Blo + (size_t)(nbase + n) * K + kb * 64 + c * 8);
        }
    };
    auto compute = [&](int buf) {
        const uint32_t aH = sb + (uint32_t)buf * SS;
        const uint32_t aL = aH + APL;
        const uint32_t bH = aH + 2 * APL;
        const uint32_t bL = bH + BPL;
        #pragma unroll
        for (int ki = 0; ki < 4; ki++) {
            uint32_t bh[NF][2], bl[NF][2];
            {
                const int gq = lane >> 3;
                const int nrow = wn0 + ((gq >> 1) << 3) + (lane & 7);
                const int chunk = ki * 2 + (gq & 1);
                const uint32_t off = SWZ(nrow, chunk);
                uint32_t r4[4];
                ldmx4(r4, bH + off);
                bh[0][0]=r4[0]; bh[0][1]=r4[1]; bh[1][0]=r4[2]; bh[1][1]=r4[3];
                ldmx4(r4, bL + off);
                bl[0][0]=r4[0]; bl[0][1]=r4[1]; bl[1][0]=r4[2]; bl[1][1]=r4[3];
            }
            #pragma unroll
            for (int mi = 0; mi < MI; mi++) {
                uint32_t ah[4], al[4];
                const int row = wm * 32 + mi * 16 + (lane & 15);
                const int chunk = ki * 2 + (lane >> 4);
                const uint32_t off = SWZ(row, chunk);
                ldmx4(ah, aH + off);
                ldmx4(al, aL + off);
                #pragma unroll
                for (int nj = 0; nj < NF; nj++) {
                    mma_bf16(acc[mi][nj], ah, bh[nj]);
                    mma_bf16(acc[mi][nj], ah, bl[nj]);
                    mma_bf16(acc[mi][nj], al, bh[nj]);
                }
            }
        }
    };

    cpA(0, 0);
    cpB(0, 0);
    cp_commit();
    for (int kb = 0; kb < NB; kb++) {
        const int buf = kb & 1;
        if (kb + 1 < NB) {
            cpA(kb + 1, buf ^ 1);
            cpB(kb + 1, buf ^ 1);
            cp_commit();
            cp_wait<1>();
        } else {
            cp_wait<0>();
        }
        __syncthreads();
        compute(buf);
        __syncthreads();
    }

    // ---- epilogue ----
    #pragma unroll
    for (int mi = 0; mi < MI; mi++) {
        #pragma unroll
        for (int half = 0; half < 2; half++) {
            const int r = wm * 32 + mi * 16 + (lane >> 2) + half * 8;
            const int t = t0 + r;
            if (t >= M) continue;
            #pragma unroll
            for (int nj = 0; nj < NF; nj++) {
                const int col = nbase + wn0 + nj * 8 + (lane & 3) * 2;
                float v0 = acc[mi][nj][half * 2 + 0];
                float v1 = acc[mi][nj][half * 2 + 1];
                float r0, r1;
                if (MODE == 0 || MODE == 3) {
                    r0 = v0 + g.e0[col]; r1 = v1 + g.e0[col + 1];
                } else if (MODE == 1) {
                    r0 = fmaxf(inv * v0 + g.e0[col]     + g_uv[col]     - inv * mean * g_uv[HDIM + col],     0.f);
                    r1 = fmaxf(inv * v1 + g.e0[col + 1] + g_uv[col + 1] - inv * mean * g_uv[HDIM + col + 1], 0.f);
                } else if (MODE == 2) {
                    float a0 = fmaxf(v0 + g_bias2[b * HDIM + col],     0.f);
                    float a1 = fmaxf(v1 + g_bias2[b * HDIM + col + 1], 0.f);
                    r0 = tanhf(a0 * g.e0[col]     + g.e1[col]);
                    r1 = tanhf(a1 * g.e0[col + 1] + g.e1[col + 1]);
                } else { // MODE 4
                    const float* ares = g.Ares + ((size_t)b * Apad + t) * (size_t)K + col;
                    const float* ev   = g_evec + ((size_t)g.arn_i * BDIM + b) * FDIM + col;
                    r0 = ares[0] + tanhf(v0 + ev[0] + g.e0[col]);
                    r1 = ares[1] + tanhf(v1 + ev[1] + g.e0[col + 1]);
                }
                const size_t co = ((size_t)b * Cpad + t) * (size_t)g.Nfull + col;
                if (HASC) *(float2*)(C + co) = make_float2(r0, r1);
                if (HASP) {
                    __nv_bfloat162 hp, lp;
                    hp.x = __float2bfloat16(r0);
                    hp.y = __float2bfloat16(r1);
                    lp.x = __float2bfloat16(r0 - __bfloat162float(hp.x));
                    lp.y = __float2bfloat16(r1 - __bfloat162float(hp.y));
                    *(__nv_bfloat162*)(Chi + co) = hp;
                    *(__nv_bfloat162*)(Clo + co) = lp;
                }
            }
        }
    }
}

// ---------------- GLN partials ----------------
__global__ __launch_bounds__(256) void k_gln_part(const int* __restrict__ aux_len)
{
    const int b = blockIdx.x, s = blockIdx.y;
    const int len = aux_len[b];
    const int tA = s * (TA / 16);
    const int tB = min(len, tA + TA / 16);
    float sum = 0.f, sq = 0.f;
    if (tB > tA) {
        const float* p = g_aux + ((size_t)b * MP_AX + tA) * FDIM;
        const int n = (tB - tA) * FDIM;
        for (int i = threadIdx.x; i < n; i += 256) {
            float v = p[i];
            sum += v; sq += v * v;
        }
    }
    __shared__ float ss[256], qq[256];
    ss[threadIdx.x] = sum; qq[threadIdx.x] = sq;
    __syncthreads();
    for (int st = 128; st > 0; st >>= 1) {
        if (threadIdx.x < st) { ss[threadIdx.x] += ss[threadIdx.x + st]; qq[threadIdx.x] += qq[threadIdx.x + st]; }
        __syncthreads();
    }
    if (threadIdx.x == 0) {
        g_glnp[(b * 16 + s) * 2 + 0] = ss[0];
        g_glnp[(b * 16 + s) * 2 + 1] = qq[0];
    }
}

// ---------------- h stats partials + combine ----------------
__global__ __launch_bounds__(256) void k_hpart(const int* __restrict__ aux_len)
{
    const int b = blockIdx.x, s = blockIdx.y, ch = threadIdx.x;
    const int len = aux_len[b];
    const int tA = s * SLC;
    const int tB = min(len, tA + SLC);
    float sum = 0.f, sq = 0.f;
    const float* p = g_h + ((size_t)b * MP_AX) * HDIM + ch;
    for (int t = tA; t < tB; t++) {
        float v = p[(size_t)t * HDIM];
        sum += v; sq += v * v;
    }
    float* o = g_hpart + (((size_t)b * NSLC + s) * HDIM + ch) * 2;
    o[0] = sum; o[1] = sq;
}
__global__ __launch_bounds__(256) void k_hcomb(const int* __restrict__ aux_len,
                                               const float* __restrict__ att_w1,
                                               const float* __restrict__ att_b1)
{
    const int b = blockIdx.x, ch = threadIdx.x;
    const int len = aux_len[b];
    __shared__ float sm[256], sstd[256];
    {
        float sum = 0.f, sq = 0.f;
        #pragma unroll
        for (int s = 0; s < NSLC; s++) {
            const float* o = g_hpart + (((size_t)b * NSLC + s) * HDIM + ch) * 2;
            sum += o[0]; sq += o[1];
        }
        const float n = (float)len;
        const float m = sum / n;
        const float var = (sq - n * m * m) / (n - 1.f);
        sm[ch] = m;
        sstd[ch] = sqrtf(fmaxf(var, 1e-4f));
    }
    __syncthreads();
    float acc = att_b1[ch];
    for (int k = 0; k < HDIM; k++) {
        acc += sm[k]   * att_w1[(size_t)(256 + k) * HDIM + ch]
             + sstd[k] * att_w1[(size_t)(512 + k) * HDIM + ch];
    }
    g_bias2[b * HDIM + ch] = acc;
}

// ---------------- pool partials + combine ----------------
__global__ __launch_bounds__(256) void k_ppart(const int* __restrict__ aux_len)
{
    const int b = blockIdx.x, s = blockIdx.y, ch = threadIdx.x;
    const int len = aux_len[b];
    const int tA = s * SLC;
    const int tB = min(len, tA + SLC);
    const float* lp = g_logits + (size_t)b * MP_AX * HDIM + ch;
    const float* hp = g_h      + (size_t)b * MP_AX * HDIM + ch;
    float mx = -1e30f, se = 0.f, s1 = 0.f, s2 = 0.f;
    for (int t = tA; t < tB; t++) {
        float l  = lp[(size_t)t * HDIM];
        float hv = hp[(size_t)t * HDIM];
        if (l > mx) {
            float sc = expf(mx - l);
            se *= sc; s1 *= sc; s2 *= sc;
            mx = l;
        }
        float e = expf(l - mx);
        se += e; s1 += hv * e; s2 += hv * hv * e;
    }
    float* o = g_ppart + (((size_t)b * NSLC + s) * HDIM + ch) * 4;
    o[0] = mx; o[1] = se; o[2] = s1; o[3] = s2;
}
__global__ __launch_bounds__(256) void k_pcomb(const float* __restrict__ bn5g,
                                               const float* __restrict__ bn5b,
                                               const float* __restrict__ fc6_w,
                                               const float* __restrict__ fc6_b,
                                               const float* __restrict__ bn6g,
                                               const float* __restrict__ bn6b,
                                               const float* __restrict__ cls_w,
                                               const float* __restrict__ cls_b,
                                               const float* __restrict__ arn_w2,
                                               float* __restrict__ out_cls, int write_cls)
{
    const int b = blockIdx.x, j = threadIdx.x;
    __shared__ float e[2 * HDIM];
    {
        float mx = -1e30f;
        float pm[NSLC];
        #pragma unroll
        for (int s = 0; s < NSLC; s++) {
            pm[s] = g_ppart[(((size_t)b * NSLC + s) * HDIM + j) * 4];
            mx = fmaxf(mx, pm[s]);
        }
        float se = 0.f, s1 = 0.f, s2 = 0.f;
        #pragma unroll
        for (int s = 0; s < NSLC; s++) {
            const float* o = g_ppart + (((size_t)b * NSLC + s) * HDIM + j) * 4;
            float sc = expf(pm[s] - mx);
            se += o[1] * sc; s1 += o[2] * sc; s2 += o[3] * sc;
        }
        float mu = s1 / se;
        float sg = sqrtf(fmaxf(s2 / se - mu * mu, 1e-4f));
        e[j]        = mu * bn5g[j]        + bn5b[j];
        e[j + HDIM] = sg * bn5g[HDIM + j] + bn5b[HDIM + j];
    }
    __syncthreads();
    float acc = fc6_b[j];
    for (int k = 0; k < 2 * HDIM; k++) acc += e[k] * fc6_w[(size_t)k * FDIM + j];
    const float em = acc * bn6g[j] + bn6b[j];
    g_emb[b * FDIM + j] = em;

    __shared__ float red[256];
    red[j] = em * em;
    __syncthreads();
    for (int st = 128; st > 0; st >>= 1) { if (j < st) red[j] += red[j + st]; __syncthreads(); }
    const float nrmv = fmaxf(sqrtf(red[0]), 1e-12f);
    __shared__ float emv[256];
    emv[j] = em;
    __syncthreads();
    if (write_cls && j < NCLS) {
        float c = cls_b[j];
        for (int k = 0; k < FDIM; k++) c += (emv[k] / nrmv) * cls_w[(size_t)k * NCLS + j];
        out_cls[b * NCLS + j] = c;
    }
    for (int i = 0; i < 4; i++) {
        const float* W = arn_w2 + (size_t)i * FDIM * FDIM;
        float a2 = 0.f;
        for (int k = 0; k < FDIM; k++) a2 += emv[k] * W[(size_t)k * FDIM + j];
        g_evec[((size_t)i * BDIM + b) * FDIM + j] = a2;
    }
}

__global__ __launch_bounds__(256) void k_ola(float* __restrict__ out)
{
    const int idx = blockIdx.x * blockDim.x + threadIdx.x;
    if (idx >= BDIM * LSIG) return;
    const int b = idx / LSIG;
    const int i = idx - b * LSIG;
    const int t = i / SHIFT;
    const int j = i - t * SHIFT;
    const float* yb = g_y + (size_t)b * MP_IN * FRAME;
    float v = yb[(size_t)t * FRAME + j];
    if (t > 0) { v += yb[(size_t)(t - 1) * FRAME + j + SHIFT]; v *= 0.5f; }
    out[idx] = v;
}

// ---------------- launch ----------------
extern "C" void kernel_launch(void* const* d_in, const int* in_sizes, int n_in,
                              void* d_out, int out_size)
{
    const float* input   = (const float*)d_in[0];
    const float* anchor  = (const float*)d_in[1];
    const int*   aux_len = (const int*)  d_in[2];
    const float* in_w    = (const float*)d_in[4];
    const float* in_b    = (const float*)d_in[5];
    const float* out_w   = (const float*)d_in[6];
    const float* out_b   = (const float*)d_in[7];
    const float* gln_g   = (const float*)d_in[8];
    const float* gln_b   = (const float*)d_in[9];
    const float* ecapa_w = (const float*)d_in[10];
    const float* ecapa_b = (const float*)d_in[11];
    const float* att_w1  = (const float*)d_in[12];
    const float* att_b1  = (const float*)d_in[13];
    const float* attbn_g = (const float*)d_in[14];
    const float* attbn_b = (const float*)d_in[15];
    const float* att_w2  = (const float*)d_in[16];
    const float* att_b2  = (const float*)d_in[17];
    const float* bn5_g   = (const float*)d_in[18];
    const float* bn5_b   = (const float*)d_in[19];
    const float* fc6_w   = (const float*)d_in[20];
    const float* fc6_b   = (const float*)d_in[21];
    const float* bn6_g   = (const float*)d_in[22];
    const float* bn6_b   = (const float*)d_in[23];
    const float* cls_w   = (const float*)d_in[24];
    const float* cls_b   = (const float*)d_in[25];
    const float* arn_w1  = (const float*)d_in[26];
    const float* arn_w2  = (const float*)d_in[27];
    const float* arn_b   = (const float*)d_in[28];

    float *p_out, *p_out2, *p_aux, *p_h, *p_logits, *p_y;
    cudaGetSymbolAddress((void**)&p_out,    g_out);
    cudaGetSymbolAddress((void**)&p_out2,   g_out2);
    cudaGetSymbolAddress((void**)&p_aux,    g_aux);
    cudaGetSymbolAddress((void**)&p_h,      g_h);
    cudaGetSymbolAddress((void**)&p_logits, g_logits);
    cudaGetSymbolAddress((void**)&p_y,      g_y);

    __nv_bfloat16 *sig_h, *sig_l, *anc_h, *anc_l;
    __nv_bfloat16 *o_h, *o_l, *o2_h, *o2_l, *ax_h, *ax_l, *h_h, *h_l, *aa_h, *aa_l;
    cudaGetSymbolAddress((void**)&sig_h, a_sig_hi); cudaGetSymbolAddress((void**)&sig_l, a_sig_lo);
    cudaGetSymbolAddress((void**)&anc_h, a_anc_hi); cudaGetSymbolAddress((void**)&anc_l, a_anc_lo);
    cudaGetSymbolAddress((void**)&o_h,  a_out_hi);  cudaGetSymbolAddress((void**)&o_l,  a_out_lo);
    cudaGetSymbolAddress((void**)&o2_h, a_out2_hi); cudaGetSymbolAddress((void**)&o2_l, a_out2_lo);
    cudaGetSymbolAddress((void**)&ax_h, a_aux_hi);  cudaGetSymbolAddress((void**)&ax_l, a_aux_lo);
    cudaGetSymbolAddress((void**)&h_h,  a_h_hi);    cudaGetSymbolAddress((void**)&h_l,  a_h_lo);
    cudaGetSymbolAddress((void**)&aa_h, a_a_hi);    cudaGetSymbolAddress((void**)&aa_l, a_a_lo);

    __nv_bfloat16 *pw_in_h, *pw_in_l, *pw_ec_h, *pw_ec_l, *pw_a1_h, *pw_a1_l,
                  *pw_a2_h, *pw_a2_l, *pw_ar_h, *pw_ar_l, *pw_ou_h, *pw_ou_l;
    cudaGetSymbolAddress((void**)&pw_in_h, w_in_hi);  cudaGetSymbolAddress((void**)&pw_in_l, w_in_lo);
    cudaGetSymbolAddress((void**)&pw_ec_h, w_ec_hi);  cudaGetSymbolAddress((void**)&pw_ec_l, w_ec_lo);
    cudaGetSymbolAddress((void**)&pw_a1_h, w_a1_hi);  cudaGetSymbolAddress((void**)&pw_a1_l, w_a1_lo);
    cudaGetSymbolAddress((void**)&pw_a2_h, w_a2_hi);  cudaGetSymbolAddress((void**)&pw_a2_l, w_a2_lo);
    cudaGetSymbolAddress((void**)&pw_ar_h, w_arn_hi); cudaGetSymbolAddress((void**)&pw_ar_l, w_arn_lo);
    cudaGetSymbolAddress((void**)&pw_ou_h, w_out_hi); cudaGetSymbolAddress((void**)&pw_ou_l, w_out_lo);

    // ---- prep ----
    PrepArgs pa;
    int toff = 0;
    auto rg = [&](int r, const float* s, const float* sc, __nv_bfloat16* h, __nv_bfloat16* l, int K, int N) {
        pa.src[r] = s; pa.scl[r] = sc; pa.hi[r] = h; pa.lo[r] = l; pa.K[r] = K; pa.N[r] = N;
        pa.toff[r] = toff; toff += (K / 32) * (N / 32);
    };
    rg(0, in_w,    nullptr, pw_in_h, pw_in_l, 320, 256);
    rg(1, ecapa_w, gln_g,   pw_ec_h, pw_ec_l, 256, 256);
    rg(2, att_w1,  nullptr, pw_a1_h, pw_a1_l, 256, 256);
    rg(3, att_w2,  nullptr, pw_a2_h, pw_a2_l, 256, 256);
    for (int i = 0; i < 4; i++)
        rg(4 + i, arn_w1 + (size_t)i * 65536, nullptr, pw_ar_h + (size_t)i * 65536,
           pw_ar_l + (size_t)i * 65536, 256, 256);
    rg(8, out_w, nullptr, pw_ou_h, pw_ou_l, 256, 320);
    pa.toff[9] = toff;
    pa.src[9] = out_w; pa.scl[9] = nullptr; pa.hi[9] = pw_ou_h; pa.lo[9] = pw_ou_l;
    pa.K[9] = 256; pa.N[9] = 320;
    pa.toff[10] = toff;
    k_prep_all<<<toff, 256>>>(pa);
    k_uv<<<1, 256>>>(ecapa_w, gln_g, gln_b);
    {
        int tot_s = BDIM * LS_PAD + 8192;
        int tot_a = BDIM * LA_PAD + 8192;
        k_sigprep<<<(tot_s + 255) / 256, 256>>>(input,  sig_h, sig_l, LSIG, LS_PAD, tot_s);
        k_sigprep<<<(tot_a + 255) / 256, 256>>>(anchor, anc_h, anc_l, LAUX, LA_PAD, tot_a);
    }

    // 2 pipeline stages x 32KB = 64KB -> 3 CTAs/SM
    const int SMEM = 2 * 32768;
    cudaFuncSetAttribute(k_tgemm<0>, cudaFuncAttributeMaxDynamicSharedMemorySize, SMEM);
    cudaFuncSetAttribute(k_tgemm<1>, cudaFuncAttributeMaxDynamicSharedMemorySize, SMEM);
    cudaFuncSetAttribute(k_tgemm<2>, cudaFuncAttributeMaxDynamicSharedMemorySize, SMEM);
    cudaFuncSetAttribute(k_tgemm<3>, cudaFuncAttributeMaxDynamicSharedMemorySize, SMEM);
    cudaFuncSetAttribute(k_tgemm<4>, cudaFuncAttributeMaxDynamicSharedMemorySize, SMEM);

    GArgs ga;
    memset(&ga, 0, sizeof(ga));
    ga.aux_len = aux_len;

    // 1. merged encoders  (z = 4 N-quarters of 64)
    ga.Ahi = sig_h; ga.Alo = sig_l; ga.Apad = LS_PAD;
    ga.Bhi = pw_in_h; ga.Blo = pw_in_l;
    ga.C = p_out; ga.Chi = o_h; ga.Clo = o_l; ga.Cpad = MP_IN;
    ga.e0 = in_b; ga.M = TIN; ga.K = FRAME; ga.Nfull = FDIM;
    ga.A2hi = anc_h; ga.A2lo = anc_l; ga.A2pad = LA_PAD;
    ga.C2 = p_aux; ga.C2hi = ax_h; ga.C2lo = ax_l; ga.C2pad = MP_AX;
    ga.M2 = TA; ga.split = 16;
    k_tgemm<0><<<dim3(23, 32, 4), 256, SMEM>>>(ga);

    // 2. GLN partials
    k_gln_part<<<dim3(32, 16), 256>>>(aux_len);

    // 3. ecapa (folded GLN)
    GArgs gb1 = ga;
    gb1.Ahi = ax_h; gb1.Alo = ax_l; gb1.Apad = MP_AX;
    gb1.Bhi = pw_ec_h; gb1.Blo = pw_ec_l;
    gb1.C = p_h; gb1.Chi = h_h; gb1.Clo = h_l; gb1.Cpad = MP_AX;
    gb1.e0 = ecapa_b; gb1.M = TA; gb1.K = FDIM; gb1.Nfull = HDIM; gb1.split = 0;
    k_tgemm<1><<<dim3(7, 32, 4), 256, SMEM>>>(gb1);

    // 4. h stats + attention bias
    k_hpart<<<dim3(32, NSLC), 256>>>(aux_len);
    k_hcomb<<<32, 256>>>(aux_len, att_w1, att_b1);

    // 5. att1
    GArgs gb2 = gb1;
    gb2.Ahi = h_h; gb2.Alo = h_l;
    gb2.Bhi = pw_a1_h; gb2.Blo = pw_a1_l;
    gb2.C = nullptr; gb2.Chi = aa_h; gb2.Clo = aa_l;
    gb2.e0 = attbn_g; gb2.e1 = attbn_b;
    k_tgemm<2><<<dim3(7, 32, 4), 256, SMEM>>>(gb2);

    // 6. att2
    GArgs gb3 = gb2;
    gb3.Ahi = aa_h; gb3.Alo = aa_l;
    gb3.Bhi = pw_a2_h; gb3.Blo = pw_a2_l;
    gb3.C = p_logits; gb3.Chi = nullptr; gb3.Clo = nullptr;
    gb3.e0 = att_b2;
    k_tgemm<3><<<dim3(7, 32, 4), 256, SMEM>>>(gb3);

    // 7. pool + emb + classifier + evec
    k_ppart<<<dim3(32, NSLC), 256>>>(aux_len);
    const int write_cls = (out_size >= BDIM * LSIG + BDIM * NCLS) ? 1 : 0;
    k_pcomb<<<32, 256>>>(bn5_g, bn5_b, fc6_w, fc6_b, bn6_g, bn6_b, cls_w, cls_b,
                         arn_w2, (float*)d_out + (size_t)BDIM * LSIG, write_cls);

    // 8-11. ARN blocks (ping-pong planes + fp32 residual)
    const __nv_bfloat16 *sa_h = o_h, *sa_l = o_l;
    const float* sres = p_out;
    __nv_bfloat16 *da_h = o2_h, *da_l = o2_l;
    float* dres = p_out2;
    for (int i = 0; i < 4; i++) {
        GArgs gr = ga;
        gr.Ahi = sa_h; gr.Alo = sa_l; gr.Ares = sres; gr.Apad = MP_IN;
        gr.Bhi = pw_ar_h + (size_t)i * 65536; gr.Blo = pw_ar_l + (size_t)i * 65536;
        gr.C = dres; gr.Chi = da_h; gr.Clo = da_l; gr.Cpad = MP_IN;
        gr.e0 = arn_b + i * FDIM; gr.M = TIN; gr.K = FDIM; gr.Nfull = FDIM;
        gr.arn_i = i; gr.split = 0;
        k_tgemm<4><<<dim3(16, 32, 4), 256, SMEM>>>(gr);
        const __nv_bfloat16* th = sa_h; sa_h = da_h; da_h = (__nv_bfloat16*)th;
        const __nv_bfloat16* tl = sa_l; sa_l = da_l; da_l = (__nv_bfloat16*)tl;
        const float* tr = sres; sres = dres; dres = (float*)tr;
    }

    // 12. decoder (N=320 as z=5 quarters of 64)
    GArgs gd = ga;
    gd.Ahi = sa_h; gd.Alo = sa_l; gd.Apad = MP_IN;
    gd.Bhi = pw_ou_h; gd.Blo = pw_ou_l;
    gd.C = p_y; gd.Chi = nullptr; gd.Clo = nullptr; gd.Cpad = MP_IN;
    gd.e0 = out_b; gd.M = TIN; gd.K = FDIM; gd.Nfull = FRAME; gd.split = 0;
    k_tgemm<3><<<dim3(16, 32, 5), 256, SMEM>>>(gd);

    // 13. OLA
    k_ola<<<(BDIM * LSIG + 255) / 256, 256>>>((float*)d_out);
}

// round 14
// speedup vs baseline: 1.4714x; 1.1476x over previous
#include <cuda_runtime.h>
#include <cuda_bf16.h>
#include <math.h>
#include <stdint.h>

#define BDIM   32
#define TIN    1000
#define TA     400
#define FDIM   256
#define HDIM   256
#define FRAME  320
#define SHIFT  160
#define LSIG   160000
#define LAUX   64000
#define NCLS   101
#define NSLC   8
#define SLC    (TA / NSLC)

// ---------------- scratch ----------------
__device__ float g_out   [BDIM * TIN * FDIM];
__device__ float g_out2  [BDIM * TIN * FDIM];
__device__ float g_aux   [BDIM * TA  * FDIM];
__device__ float g_h     [BDIM * TA  * HDIM];
__device__ float g_a     [BDIM * TA  * HDIM];
__device__ float g_logits[BDIM * TA  * HDIM];
__device__ float g_y     [BDIM * TIN * FRAME];
__device__ float g_bias2 [BDIM * HDIM];
__device__ float g_emb   [BDIM * FDIM];
__device__ float g_evec  [4 * BDIM * FDIM];
__device__ float g_glnp  [BDIM * 16 * 2];
__device__ float g_hpart [BDIM * NSLC * HDIM * 2];
__device__ float g_ppart [BDIM * NSLC * HDIM * 4];

// bf16 split weight planes, layout [N][K]
__device__ __nv_bfloat16 w_in_hi [256 * 320];
__device__ __nv_bfloat16 w_in_lo [256 * 320];
__device__ __nv_bfloat16 w_ec_hi [256 * 256];
__device__ __nv_bfloat16 w_ec_lo [256 * 256];
__device__ __nv_bfloat16 w_a1_hi [256 * 256];
__device__ __nv_bfloat16 w_a1_lo [256 * 256];
__device__ __nv_bfloat16 w_a2_hi [256 * 256];
__device__ __nv_bfloat16 w_a2_lo [256 * 256];
__device__ __nv_bfloat16 w_arn_hi[4 * 256 * 256];
__device__ __nv_bfloat16 w_arn_lo[4 * 256 * 256];
__device__ __nv_bfloat16 w_out_hi[320 * 256];
__device__ __nv_bfloat16 w_out_lo[320 * 256];

// ---------------- helpers ----------------
__device__ __forceinline__ uint32_t smem_u32(const void* p) {
    uint32_t a;
    asm("{ .reg .u64 t; cvta.to.shared.u64 t, %1; cvt.u32.u64 %0, t; }" : "=r"(a) : "l"(p));
    return a;
}
__device__ __forceinline__ void ldmx4(uint32_t* r, uint32_t addr) {
    asm volatile("ldmatrix.sync.aligned.m8n8.x4.shared.b16 {%0,%1,%2,%3}, [%4];"
                 : "=r"(r[0]), "=r"(r[1]), "=r"(r[2]), "=r"(r[3]) : "r"(addr));
}
__device__ __forceinline__ void ldmx2(uint32_t* r, uint32_t addr) {
    asm volatile("ldmatrix.sync.aligned.m8n8.x2.shared.b16 {%0,%1}, [%2];"
                 : "=r"(r[0]), "=r"(r[1]) : "r"(addr));
}
__device__ __forceinline__ void mma_bf16(float* c, const uint32_t* a, const uint32_t* b) {
    asm volatile("mma.sync.aligned.m16n8k16.row.col.f32.bf16.bf16.f32 "
                 "{%0,%1,%2,%3}, {%4,%5,%6,%7}, {%8,%9}, {%0,%1,%2,%3};"
                 : "+f"(c[0]), "+f"(c[1]), "+f"(c[2]), "+f"(c[3])
                 : "r"(a[0]), "r"(a[1]), "r"(a[2]), "r"(a[3]), "r"(b[0]), "r"(b[1]));
}
__device__ __forceinline__ void cp16(uint32_t saddr, const void* gaddr) {
    asm volatile("cp.async.ca.shared.global [%0], [%1], 16;" :: "r"(saddr), "l"(gaddr));
}
__device__ __forceinline__ void cp_commit() { asm volatile("cp.async.commit_group;" ::: "memory"); }
template<int W> __device__ __forceinline__ void cp_wait() {
    asm volatile("cp.async.wait_group %0;" :: "n"(W) : "memory");
}
// 128B rows, XOR swizzle on 16B chunks
__device__ __forceinline__ uint32_t SWZ(int row, int chunk) {
    return ((uint32_t)row << 7) + ((uint32_t)((chunk ^ (row & 7)) & 7) << 4);
}

// ---------------- weight prep: tiled transpose + split ----------------
struct PrepArgs {
    const float* src[10];
    __nv_bfloat16* hi[10];
    __nv_bfloat16* lo[10];
    int K[10];
    int N[10];
    int toff[11];
};
__global__ __launch_bounds__(256) void k_prep_all(PrepArgs a)
{
    __shared__ float tile[32][33];
    int tb = blockIdx.x;
    int r = 0;
    while (tb >= a.toff[r + 1]) r++;
    int ti = tb - a.toff[r];
    const int K = a.K[r], N = a.N[r];
    const int ntn = N / 32;
    const int tk = ti / ntn, tn = ti - tk * ntn;
    const int ty = threadIdx.x >> 5, tx = threadIdx.x & 31;
    #pragma unroll
    for (int q = 0; q < 4; q++) {
        const int k = tk * 32 + ty + q * 8;
        tile[ty + q * 8][tx] = a.src[r][(size_t)k * N + tn * 32 + tx];
    }
    __syncthreads();
    #pragma unroll
    for (int q = 0; q < 4; q++) {
        const int n = tn * 32 + ty + q * 8;
        float x = tile[tx][ty + q * 8];
        __nv_bfloat16 h = __float2bfloat16(x);
        const size_t o = (size_t)n * K + tk * 32 + tx;
        a.hi[r][o] = h;
        a.lo[r][o] = __float2bfloat16(x - __bfloat162float(h));
    }
}

// ---------------- tensor-core GEMM: MT=64, in-kernel A staging, occ 3 ----------------
// PIPE=true  (NT=128): B panel in two 64-row half-stages, double-buffered cp.async.
// PIPE=false (NT=160): R8 single-buffer full-panel loop (decoder).
template<int NT, int MODE, bool PIPE>
__global__ void __launch_bounds__(256, 3) k_tgemm(
    const float* __restrict__ Ain,
    const __nv_bfloat16* __restrict__ Bhi, const __nv_bfloat16* __restrict__ Blo,
    float* __restrict__ Cin,
    const float* __restrict__ e0, const float* __restrict__ e1, const float* __restrict__ e2,
    const int* __restrict__ aux_len, int Min, int K, int Nfull, int Lin, int arn_i,
    const float* A2, float* C2, int M2, int L2, int split)
{
    constexpr int MT   = 64;
    constexpr int WN   = NT / 4;          // 32 (PIPE) or 40
    constexpr int NF   = WN / 8;          // 4 or 5
    constexpr int MI   = 2;
    constexpr int APL  = MT * 128;        // 8192 per A plane
    constexpr int HBR  = 64;              // rows per B half stage (PIPE)
    constexpr int HBPL = HBR * 128;       // 8192 per B half plane

    extern __shared__ char smem[];
    const uint32_t sb = smem_u32(smem);
    const uint32_t aH = sb;
    const uint32_t aL = sb + APL;
    const uint32_t bbase = sb + 2 * APL;

    const int tid  = threadIdx.x;
    const int w    = tid >> 5;
    const int lane = tid & 31;
    const int b    = blockIdx.y;
    const int nbase = blockIdx.z * NT;

    const float* A = Ain;
    float* C = Cin;
    int M = Min, L = Lin;
    int bx = blockIdx.x;
    if (MODE == 0 && split > 0 && bx >= split) {
        A = A2; C = C2; M = M2; L = L2; bx -= split;
    }
    const int t0 = bx * MT;
    const int NB = K / 64;
    const int wm = w >> 2;
    const int wn = w & 3;

    int   len  = 0;
    float mean = 0.f, inv = 0.f;
    if (MODE == 1) {
        len = aux_len[b];
        double s = 0.0, q = 0.0;
        #pragma unroll
        for (int i = 0; i < 16; i++) {
            s += (double)g_glnp[(b * 16 + i) * 2 + 0];
            q += (double)g_glnp[(b * 16 + i) * 2 + 1];
        }
        const double n = (double)len * FDIM;
        double m = s / n;
        double var = q / n - m * m;
        mean = (float)m;
        inv  = (float)(1.0 / sqrt(var + 1e-5));
    }

    const int arow = tid >> 2;
    const int achk = (tid & 3) * 2;
    const int ac0  = achk * 8;

    float acc[MI][NF][4];
    #pragma unroll
    for (int mi = 0; mi < MI; mi++)
        #pragma unroll
        for (int nj = 0; nj < NF; nj++)
            #pragma unroll
            for (int q = 0; q < 4; q++) acc[mi][nj][q] = 0.f;

    // ---- A staging: LDG + MODE transform + bf16 split + swizzled STS ----
    auto stageA = [&](int kb) {
        const int t = t0 + arow;
        float va[16];
        if (MODE == 0) {
            if (t < M) {
                const float* src = A + (size_t)b * L;
                const int base = t * SHIFT + kb * 64 + ac0;
                #pragma unroll
                for (int q = 0; q < 4; q++) {
                    const int p = base + q * 4;
                    if (p + 3 < L) {
                        float4 f = *(const float4*)(src + p);
                        va[q*4+0]=f.x; va[q*4+1]=f.y; va[q*4+2]=f.z; va[q*4+3]=f.w;
                    } else {
                        #pragma unroll
                        for (int j = 0; j < 4; j++) va[q*4+j] = (p + j < L) ? src[p + j] : 0.f;
                    }
                }
            } else {
                #pragma unroll
                for (int j = 0; j < 16; j++) va[j] = 0.f;
            }
        } else {
            const bool valid = (MODE == 1) ? (t < len) : (t < M);
            if (valid) {
                const float* src = A + ((size_t)b * M + t) * K + kb * 64 + ac0;
                #pragma unroll
                for (int q = 0; q < 4; q++) {
                    float4 f = *(const float4*)(src + q * 4);
                    va[q*4+0]=f.x; va[q*4+1]=f.y; va[q*4+2]=f.z; va[q*4+3]=f.w;
                }
                if (MODE == 1) {
                    const int c0 = kb * 64 + ac0;
                    #pragma unroll
                    for (int q = 0; q < 4; q++) {
                        float4 gg = *(const float4*)(e0 + c0 + q * 4);
                        float4 gb = *(const float4*)(e1 + c0 + q * 4);
                        va[q*4+0] = gg.x * inv * (va[q*4+0] - mean) + gb.x;
                        va[q*4+1] = gg.y * inv * (va[q*4+1] - mean) + gb.y;
                        va[q*4+2] = gg.z * inv * (va[q*4+2] - mean) + gb.z;
                        va[q*4+3] = gg.w * inv * (va[q*4+3] - mean) + gb.w;
                    }
                }
            } else {
                #pragma unroll
                for (int j = 0; j < 16; j++) va[j] = 0.f;
            }
        }
        #pragma unroll
        for (int q = 0; q < 2; q++) {
            union { __nv_bfloat16 x[8]; uint4 v; } H, Lo;
            #pragma unroll
            for (int j = 0; j < 8; j++) {
                float f = va[q * 8 + j];
                __nv_bfloat16 hb = __float2bfloat16(f);
                H.x[j]  = hb;
                Lo.x[j] = __float2bfloat16(f - __bfloat162float(hb));
            }
            const uint32_t so = SWZ(arow, achk + q);
            *(uint4*)(smem + so)       = H.v;
            *(uint4*)(smem + APL + so) = Lo.v;
        }
    };

    if (PIPE) {
        // ---- pipelined: two 64-row B half-stages, double-buffered ----
        auto cpBh = [&](int kb, int h, int buf) {
            const uint32_t bH = bbase + (uint32_t)buf * 2 * HBPL;
            const uint32_t bL = bH + HBPL;
            #pragma unroll
            for (int it = 0; it < 2; it++) {
                const int idx = tid + it * 256;
                const int r = idx >> 3, c = idx & 7;
                const uint32_t so = SWZ(r, c);
                const size_t go = (size_t)(nbase + h * HBR + r) * K + kb * 64 + c * 8;
                cp16(bH + so, Bhi + go);
                cp16(bL + so, Blo + go);
            }
        };
        // warp wn owns cols wn*16..+16 within each half; acc frag nj = h*2 + j
        auto computeH = [&](int h, int buf) {
            const uint32_t bH = bbase + (uint32_t)buf * 2 * HBPL;
            const uint32_t bL = bH + HBPL;
            #pragma unroll
            for (int ki = 0; ki < 4; ki++) {
                uint32_t bh[2][2], bl[2][2];
                {
                    const int gq = lane >> 3;
                    const int nrow = wn * 16 + ((gq >> 1) << 3) + (lane & 7);
                    const int chunk = ki * 2 + (gq & 1);
                    const uint32_t off = SWZ(nrow, chunk);
                    uint32_t r4[4];
                    ldmx4(r4, bH + off);
                    bh[0][0]=r4[0]; bh[0][1]=r4[1]; bh[1][0]=r4[2]; bh[1][1]=r4[3];
                    ldmx4(r4, bL + off);
                    bl[0][0]=r4[0]; bl[0][1]=r4[1]; bl[1][0]=r4[2]; bl[1][1]=r4[3];
                }
                #pragma unroll
                for (int mi = 0; mi < MI; mi++) {
                    uint32_t ah[4], al[4];
                    const int row = wm * 32 + mi * 16 + (lane & 15);
                    const int chunk = ki * 2 + (lane >> 4);
                    const uint32_t off = SWZ(row, chunk);
                    ldmx4(ah, aH + off);
                    ldmx4(al, aL + off);
                    #pragma unroll
                    for (int j = 0; j < 2; j++) {
                        mma_bf16(acc[mi][h * 2 + j], ah, bh[j]);
                        mma_bf16(acc[mi][h * 2 + j], ah, bl[j]);
                        mma_bf16(acc[mi][h * 2 + j], al, bh[j]);
                    }
                }
            }
        };

        stageA(0);
        cpBh(0, 0, 0); cp_commit();
        cpBh(0, 1, 1); cp_commit();
        __syncthreads();
        for (int kb = 0; kb < NB; kb++) {
            // half 0 (buf 0)
            cp_wait<1>();
            __syncthreads();
            computeH(0, 0);
            __syncthreads();
            if (kb + 1 < NB) { cpBh(kb + 1, 0, 0); cp_commit(); }
            // half 1 (buf 1)
            if (kb + 1 < NB) cp_wait<1>(); else cp_wait<0>();
            __syncthreads();
            computeH(1, 1);
            __syncthreads();
            if (kb + 1 < NB) {
                cpBh(kb + 1, 1, 1); cp_commit();
                stageA(kb + 1);
            }
        }
    } else {
        // ---- R8 path: full B panel single stage ----
        const uint32_t bH = bbase;
        const uint32_t bL = bbase + NT * 128;
        auto cpB = [&](int kb) {
            for (int idx = tid; idx < NT * 8; idx += 256) {
                const int n = idx >> 3, c = idx & 7;
                const uint32_t so = SWZ(n, c);
                cp16(bH + so, Bhi + (size_t)(nbase + n) * K + kb * 64 + c * 8);
                cp16(bL + so, Blo + (size_t)(nbase + n) * K + kb * 64 + c * 8);
            }
        };
        const int wn0 = wn * WN;
        auto compute = [&]() {
            #pragma unroll
            for (int ki = 0; ki < 4; ki++) {
                uint32_t bh[NF][2], bl[NF][2];
                #pragma unroll
                for (int p = 0; p < NF / 2; p++) {
                    const int gq = lane >> 3;
                    const int nrow = wn0 + p * 16 + ((gq >> 1) << 3) + (lane & 7);
                    const int chunk = ki * 2 + (gq & 1);
                    const uint32_t off = SWZ(nrow, chunk);
                    uint32_t r4[4];
                    ldmx4(r4, bH + off);
                    bh[2*p][0]=r4[0]; bh[2*p][1]=r4[1]; bh[2*p+1][0]=r4[2]; bh[2*p+1][1]=r4[3];
                    ldmx4(r4, bL + off);
                    bl[2*p][0]=r4[0]; bl[2*p][1]=r4[1]; bl[2*p+1][0]=r4[2]; bl[2*p+1][1]=r4[3];
                }
                if (NF & 1) {
                    const int nj = NF - 1;
                    const int nrow = wn0 + nj * 8 + (lane & 7);
                    const int chunk = ki * 2 + ((lane & 15) >> 3);
                    const uint32_t off = SWZ(nrow, chunk);
                    ldmx2(bh[nj], bH + off);
                    ldmx2(bl[nj], bL + off);
                }
                #pragma unroll
                for (int mi = 0; mi < MI; mi++) {
                    uint32_t ah[4], al[4];
                    const int row = wm * 32 + mi * 16 + (lane & 15);
                    const int chunk = ki * 2 + (lane >> 4);
                    const uint32_t off = SWZ(row, chunk);
                    ldmx4(ah, aH + off);
                    ldmx4(al, aL + off);
                    #pragma unroll
                    for (int nj = 0; nj < NF; nj++) {
                        mma_bf16(acc[mi][nj], ah, bh[nj]);
                        mma_bf16(acc[mi][nj], ah, bl[nj]);
                        mma_bf16(acc[mi][nj], al, bh[nj]);
                    }
                }
            }
        };
        for (int kb = 0; kb < NB; kb++) {
            cpB(kb);
            cp_commit();
            stageA(kb);
            cp_wait<0>();
            __syncthreads();
            compute();
            __syncthreads();
        }
    }

    // ---- epilogue ----
    #pragma unroll
    for (int mi = 0; mi < MI; mi++) {
        #pragma unroll
        for (int half = 0; half < 2; half++) {
            const int r = wm * 32 + mi * 16 + (lane >> 2) + half * 8;
            const int t = t0 + r;
            if (t >= M) continue;
            #pragma unroll
            for (int nj = 0; nj < NF; nj++) {
                int col;
                if (PIPE) col = nbase + (nj >> 1) * 64 + wn * 16 + (nj & 1) * 8 + (lane & 3) * 2;
                else      col = nbase + wn * WN + nj * 8 + (lane & 3) * 2;
                float v0 = acc[mi][nj][half * 2 + 0];
                float v1 = acc[mi][nj][half * 2 + 1];
                float r0, r1;
                if (MODE == 0) {
                    r0 = v0 + e0[col]; r1 = v1 + e0[col + 1];
                } else if (MODE == 1) {
                    if (t < len) { r0 = fmaxf(v0 + e2[col], 0.f); r1 = fmaxf(v1 + e2[col + 1], 0.f); }
                    else         { r0 = 0.f; r1 = 0.f; }
                } else if (MODE == 2) {
                    float a0 = fmaxf(v0 + g_bias2[b * HDIM + col],     0.f);
                    float a1 = fmaxf(v1 + g_bias2[b * HDIM + col + 1], 0.f);
                    r0 = tanhf(a0 * e0[col]     + e1[col]);
                    r1 = tanhf(a1 * e0[col + 1] + e1[col + 1]);
                } else if (MODE == 3) {
                    r0 = v0 + e0[col]; r1 = v1 + e0[col + 1];
                } else {
                    const float* ares = A + ((size_t)b * M + t) * K + col;
                    const float* ev   = g_evec + ((size_t)arn_i * BDIM + b) * FDIM + col;
                    r0 = ares[0] + tanhf(v0 + ev[0] + e0[col]);
                    r1 = ares[1] + tanhf(v1 + ev[1] + e0[col + 1]);
                }
                *(float2*)(C + ((size_t)b * M + t) * Nfull + col) = make_float2(r0, r1);
            }
        }
    }
}

// ---------------- GLN partials ----------------
__global__ __launch_bounds__(256) void k_gln_part(const int* __restrict__ aux_len)
{
    const int b = blockIdx.x, s = blockIdx.y;
    const int len = aux_len[b];
    const int tA = s * (TA / 16);
    const int tB = min(len, tA + TA / 16);
    float sum = 0.f, sq = 0.f;
    if (tB > tA) {
        const float* p = g_aux + ((size_t)b * TA + tA) * FDIM;
        const int n = (tB - tA) * FDIM;
        for (int i = threadIdx.x; i < n; i += 256) {
            float v = p[i];
            sum += v; sq += v * v;
        }
    }
    __shared__ float ss[256], qq[256];
    ss[threadIdx.x] = sum; qq[threadIdx.x] = sq;
    __syncthreads();
    for (int st = 128; st > 0; st >>= 1) {
        if (threadIdx.x < st) { ss[threadIdx.x] += ss[threadIdx.x + st]; qq[threadIdx.x] += qq[threadIdx.x + st]; }
        __syncthreads();
    }
    if (threadIdx.x == 0) {
        g_glnp[(b * 16 + s) * 2 + 0] = ss[0];
        g_glnp[(b * 16 + s) * 2 + 1] = qq[0];
    }
}

// ---------------- h stats partials + combine ----------------
__global__ __launch_bounds__(256) void k_hpart(const int* __restrict__ aux_len)
{
    const int b = blockIdx.x, s = blockIdx.y, ch = threadIdx.x;
    const int len = aux_len[b];
    const int tA = s * SLC;
    const int tB = min(len, tA + SLC);
    float sum = 0.f, sq = 0.f;
    const float* p = g_h + ((size_t)b * TA) * HDIM + ch;
    for (int t = tA; t < tB; t++) {
        float v = p[(size_t)t * HDIM];
        sum += v; sq += v * v;
    }
    float* o = g_hpart + (((size_t)b * NSLC + s) * HDIM + ch) * 2;
    o[0] = sum; o[1] = sq;
}
__global__ __launch_bounds__(256) void k_hcomb(const int* __restrict__ aux_len,
                                               const float* __restrict__ att_w1,
                                               const float* __restrict__ att_b1)
{
    const int b = blockIdx.x, ch = threadIdx.x;
    const int len = aux_len[b];
    __shared__ float sm[256], sstd[256];
    {
        float sum = 0.f, sq = 0.f;
        #pragma unroll
        for (int s = 0; s < NSLC; s++) {
            const float* o = g_hpart + (((size_t)b * NSLC + s) * HDIM + ch) * 2;
            sum += o[0]; sq += o[1];
        }
        const float n = (float)len;
        const float m = sum / n;
        const float var = (sq - n * m * m) / (n - 1.f);
        sm[ch] = m;
        sstd[ch] = sqrtf(fmaxf(var, 1e-4f));
    }
    __syncthreads();
    float acc = att_b1[ch];
    for (int k = 0; k < HDIM; k++) {
        acc += sm[k]   * att_w1[(size_t)(256 + k) * HDIM + ch]
             + sstd[k] * att_w1[(size_t)(512 + k) * HDIM + ch];
    }
    g_bias2[b * HDIM + ch] = acc;
}

// ---------------- pool partials + combine ----------------
__global__ __launch_bounds__(256) void k_ppart(const int* __restrict__ aux_len)
{
    const int b = blockIdx.x, s = blockIdx.y, ch = threadIdx.x;
    const int len = aux_len[b];
    const int tA = s * SLC;
    const int tB = min(len, tA + SLC);
    const float* lp = g_logits + (size_t)b * TA * HDIM + ch;
    const float* hp = g_h      + (size_t)b * TA * HDIM + ch;
    float mx = -1e30f, se = 0.f, s1 = 0.f, s2 = 0.f;
    for (int t = tA; t < tB; t++) {
        float l  = lp[(size_t)t * HDIM];
        float hv = hp[(size_t)t * HDIM];
        if (l > mx) {
            float sc = expf(mx - l);
            se *= sc; s1 *= sc; s2 *= sc;
            mx = l;
        }
        float e = expf(l - mx);
        se += e; s1 += hv * e; s2 += hv * hv * e;
    }
    float* o = g_ppart + (((size_t)b * NSLC + s) * HDIM + ch) * 4;
    o[0] = mx; o[1] = se; o[2] = s1; o[3] = s2;
}
__global__ __launch_bounds__(256) void k_pcomb(const float* __restrict__ bn5g,
                                               const float* __restrict__ bn5b,
                                               const float* __restrict__ fc6_w,
                                               const float* __restrict__ fc6_b,
                                               const float* __restrict__ bn6g,
                                               const float* __restrict__ bn6b,
                                               const float* __restrict__ cls_w,
                                               const float* __restrict__ cls_b,
                                               const float* __restrict__ arn_w2,
                                               float* __restrict__ out_cls, int write_cls)
{
    const int b = blockIdx.x, j = threadIdx.x;
    __shared__ float e[2 * HDIM];
    {
        float mx = -1e30f;
        float pm[NSLC];
        #pragma unroll
        for (int s = 0; s < NSLC; s++) {
            pm[s] = g_ppart[(((size_t)b * NSLC + s) * HDIM + j) * 4];
            mx = fmaxf(mx, pm[s]);
        }
        float se = 0.f, s1 = 0.f, s2 = 0.f;
        #pragma unroll
        for (int s = 0; s < NSLC; s++) {
            const float* o = g_ppart + (((size_t)b * NSLC + s) * HDIM + j) * 4;
            float sc = expf(pm[s] - mx);
            se += o[1] * sc; s1 += o[2] * sc; s2 += o[3] * sc;
        }
        float mu = s1 / se;
        float sg = sqrtf(fmaxf(s2 / se - mu * mu, 1e-4f));
        e[j]        = mu * bn5g[j]        + bn5b[j];
        e[j + HDIM] = sg * bn5g[HDIM + j] + bn5b[HDIM + j];
    }
    __syncthreads();
    float acc = fc6_b[j];
    for (int k = 0; k < 2 * HDIM; k++) acc += e[k] * fc6_w[(size_t)k * FDIM + j];
    const float em = acc * bn6g[j] + bn6b[j];
    g_emb[b * FDIM + j] = em;

    __shared__ float red[256];
    red[j] = em * em;
    __syncthreads();
    for (int st = 128; st > 0; st >>= 1) { if (j < st) red[j] += red[j + st]; __syncthreads(); }
    const float nrmv = fmaxf(sqrtf(red[0]), 1e-12f);
    __shared__ float emv[256];
    emv[j] = em;
    __syncthreads();
    if (write_cls && j < NCLS) {
        float c = cls_b[j];
        for (int k = 0; k < FDIM; k++) c += (emv[k] / nrmv) * cls_w[(size_t)k * NCLS + j];
        out_cls[b * NCLS + j] = c;
    }
    for (int i = 0; i < 4; i++) {
        const float* W = arn_w2 + (size_t)i * FDIM * FDIM;
        float a2 = 0.f;
        for (int k = 0; k < FDIM; k++) a2 += emv[k] * W[(size_t)k * FDIM + j];
        g_evec[((size_t)i * BDIM + b) * FDIM + j] = a2;
    }
}

__global__ __launch_bounds__(256) void k_ola(float* __restrict__ out)
{
    const int idx = blockIdx.x * blockDim.x + threadIdx.x;
    if (idx >= BDIM * LSIG) return;
    const int b = idx / LSIG;
    const int i = idx - b * LSIG;
    const int t = i / SHIFT;
    const int j = i - t * SHIFT;
    const float* yb = g_y + (size_t)b * TIN * FRAME;
    float v = yb[(size_t)t * FRAME + j];
    if (t > 0) { v += yb[(size_t)(t - 1) * FRAME + j + SHIFT]; v *= 0.5f; }
    out[idx] = v;
}

// ---------------- launch ----------------
extern "C" void kernel_launch(void* const* d_in, const int* in_sizes, int n_in,
                              void* d_out, int out_size)
{
    const float* input   = (const float*)d_in[0];
    const float* anchor  = (const float*)d_in[1];
    const int*   aux_len = (const int*)  d_in[2];
    const float* in_w    = (const float*)d_in[4];
    const float* in_b    = (const float*)d_in[5];
    const float* out_w   = (const float*)d_in[6];
    const float* out_b   = (const float*)d_in[7];
    const float* gln_g   = (const float*)d_in[8];
    const float* gln_b   = (const float*)d_in[9];
    const float* ecapa_w = (const float*)d_in[10];
    const float* ecapa_b = (const float*)d_in[11];
    const float* att_w1  = (const float*)d_in[12];
    const float* att_b1  = (const float*)d_in[13];
    const float* attbn_g = (const float*)d_in[14];
    const float* attbn_b = (const float*)d_in[15];
    const float* att_w2  = (const float*)d_in[16];
    const float* att_b2  = (const float*)d_in[17];
    const float* bn5_g   = (const float*)d_in[18];
    const float* bn5_b   = (const float*)d_in[19];
    const float* fc6_w   = (const float*)d_in[20];
    const float* fc6_b   = (const float*)d_in[21];
    const float* bn6_g   = (const float*)d_in[22];
    const float* bn6_b   = (const float*)d_in[23];
    const float* cls_w   = (const float*)d_in[24];
    const float* cls_b   = (const float*)d_in[25];
    const float* arn_w1  = (const float*)d_in[26];
    const float* arn_w2  = (const float*)d_in[27];
    const float* arn_b   = (const float*)d_in[28];

    float *p_out, *p_out2, *p_aux, *p_h, *p_a, *p_logits, *p_y;
    cudaGetSymbolAddress((void**)&p_out,    g_out);
    cudaGetSymbolAddress((void**)&p_out2,   g_out2);
    cudaGetSymbolAddress((void**)&p_aux,    g_aux);
    cudaGetSymbolAddress((void**)&p_h,      g_h);
    cudaGetSymbolAddress((void**)&p_a,      g_a);
    cudaGetSymbolAddress((void**)&p_logits, g_logits);
    cudaGetSymbolAddress((void**)&p_y,      g_y);

    __nv_bfloat16 *pw_in_h, *pw_in_l, *pw_ec_h, *pw_ec_l, *pw_a1_h, *pw_a1_l,
                  *pw_a2_h, *pw_a2_l, *pw_ar_h, *pw_ar_l, *pw_ou_h, *pw_ou_l;
    cudaGetSymbolAddress((void**)&pw_in_h, w_in_hi);  cudaGetSymbolAddress((void**)&pw_in_l, w_in_lo);
    cudaGetSymbolAddress((void**)&pw_ec_h, w_ec_hi);  cudaGetSymbolAddress((void**)&pw_ec_l, w_ec_lo);
    cudaGetSymbolAddress((void**)&pw_a1_h, w_a1_hi);  cudaGetSymbolAddress((void**)&pw_a1_l, w_a1_lo);
    cudaGetSymbolAddress((void**)&pw_a2_h, w_a2_hi);  cudaGetSymbolAddress((void**)&pw_a2_l, w_a2_lo);
    cudaGetSymbolAddress((void**)&pw_ar_h, w_arn_hi); cudaGetSymbolAddress((void**)&pw_ar_l, w_arn_lo);
    cudaGetSymbolAddress((void**)&pw_ou_h, w_out_hi); cudaGetSymbolAddress((void**)&pw_ou_l, w_out_lo);

    // ---- single fused weight-prep (tiled transpose) ----
    PrepArgs pa;
    int toff = 0;
    auto reg = [&](int r, const float* s, __nv_bfloat16* h, __nv_bfloat16* l, int K, int N) {
        pa.src[r] = s; pa.hi[r] = h; pa.lo[r] = l; pa.K[r] = K; pa.N[r] = N;
        pa.toff[r] = toff; toff += (K / 32) * (N / 32);
    };
    reg(0, in_w,    pw_in_h, pw_in_l, 320, 256);
    reg(1, ecapa_w, pw_ec_h, pw_ec_l, 256, 256);
    reg(2, att_w1,  pw_a1_h, pw_a1_l, 256, 256);
    reg(3, att_w2,  pw_a2_h, pw_a2_l, 256, 256);
    for (int i = 0; i < 4; i++)
        reg(4 + i, arn_w1 + (size_t)i * 65536, pw_ar_h + (size_t)i * 65536,
            pw_ar_l + (size_t)i * 65536, 256, 256);
    reg(8, out_w, pw_ou_h, pw_ou_l, 256, 320);
    pa.toff[9] = toff;
    pa.src[9] = out_w; pa.hi[9] = pw_ou_h; pa.lo[9] = pw_ou_l; pa.K[9] = 256; pa.N[9] = 320;
    pa.toff[10] = toff;
    k_prep_all<<<toff, 256>>>(pa);

    const int SM128 = 2 * (64 * 128) + 4 * (64 * 128);    // 49152 (A 16K + 2 half-bufs 32K)
    const int SM160 = 2 * (64 * 128) + 2 * (160 * 128);   // 57344
    cudaFuncSetAttribute(k_tgemm<128,0,true>,  cudaFuncAttributeMaxDynamicSharedMemorySize, SM128);
    cudaFuncSetAttribute(k_tgemm<128,1,true>,  cudaFuncAttributeMaxDynamicSharedMemorySize, SM128);
    cudaFuncSetAttribute(k_tgemm<128,2,true>,  cudaFuncAttributeMaxDynamicSharedMemorySize, SM128);
    cudaFuncSetAttribute(k_tgemm<128,3,true>,  cudaFuncAttributeMaxDynamicSharedMemorySize, SM128);
    cudaFuncSetAttribute(k_tgemm<128,4,true>,  cudaFuncAttributeMaxDynamicSharedMemorySize, SM128);
    cudaFuncSetAttribute(k_tgemm<160,3,false>, cudaFuncAttributeMaxDynamicSharedMemorySize, SM160);

    // 1. merged encoders: x blocks [0,16) -> input, [16,23) -> anchor; z = 2 N-halves
    k_tgemm<128,0,true><<<dim3(23, 32, 2), 256, SM128>>>(input, pw_in_h, pw_in_l, p_out, in_b,
                                                         nullptr, nullptr, nullptr, TIN, FRAME, FDIM, LSIG, 0,
                                                         anchor, p_aux, TA, LAUX, 16);
    // 2. GLN partials (combine folded into next GEMM)
    k_gln_part<<<dim3(32, 16), 256>>>(aux_len);
    // 3. GLN + ecapa + relu
    k_tgemm<128,1,true><<<dim3(7, 32, 2), 256, SM128>>>(p_aux, pw_ec_h, pw_ec_l, p_h, gln_g, gln_b,
                                                        ecapa_b, aux_len, TA, FDIM, HDIM, 0, 0,
                                                        nullptr, nullptr, 0, 0, 0);
    // 4. h stats + attention bias
    k_hpart<<<dim3(32, NSLC), 256>>>(aux_len);
    k_hcomb<<<32, 256>>>(aux_len, att_w1, att_b1);
    // 5. attention conv1(+relu+bn+tanh)
    k_tgemm<128,2,true><<<dim3(7, 32, 2), 256, SM128>>>(p_h, pw_a1_h, pw_a1_l, p_a, attbn_g, attbn_b,
                                                        nullptr, nullptr, TA, HDIM, HDIM, 0, 0,
                                                        nullptr, nullptr, 0, 0, 0);
    // 6. attention conv2
    k_tgemm<128,3,true><<<dim3(7, 32, 2), 256, SM128>>>(p_a, pw_a2_h, pw_a2_l, p_logits, att_b2,
                                                        nullptr, nullptr, nullptr, TA, HDIM, HDIM, 0, 0,
                                                        nullptr, nullptr, 0, 0, 0);
    // 7. pool + emb + classifier + evec
    k_ppart<<<dim3(32, NSLC), 256>>>(aux_len);
    const int write_cls = (out_size >= BDIM * LSIG + BDIM * NCLS) ? 1 : 0;
    k_pcomb<<<32, 256>>>(bn5_g, bn5_b, fc6_w, fc6_b, bn6_g, bn6_b, cls_w, cls_b,
                         arn_w2, (float*)d_out + (size_t)BDIM * LSIG, write_cls);
    // 8-11. 4 ARN residual blocks (ping-pong)
    const float* src = p_out;
    float*       dst = p_out2;
    for (int i = 0; i < 4; i++) {
        k_tgemm<128,4,true><<<dim3(16, 32, 2), 256, SM128>>>(src, pw_ar_h + (size_t)i * 65536,
                                                             pw_ar_l + (size_t)i * 65536, dst,
                                                             arn_b + i * FDIM, nullptr, nullptr,
                                                             nullptr, TIN, FDIM, FDIM, 0, i,
                                                             nullptr, nullptr, 0, 0, 0);
        const float* tmp = dst; dst = (float*)src; src = tmp;
    }
    // 12. decoder (N=320 in two 160-col halves, unpipelined R8 path)
    k_tgemm<160,3,false><<<dim3(16, 32, 2), 256, SM160>>>(src, pw_ou_h, pw_ou_l, p_y, out_b,
                                                          nullptr, nullptr, nullptr, TIN, FDIM, FRAME, 0, 0,
                                                          nullptr, nullptr, 0, 0, 0);
    // 13. OLA
    k_ola<<<(BDIM * LSIG + 255) / 256, 256>>>((float*)d_out);
}

// round 15
// speedup vs baseline: 1.5517x; 1.0546x over previous
#include <cuda_runtime.h>
#include <cuda_bf16.h>
#include <math.h>
#include <stdint.h>

#define BDIM   32
#define TIN    1000
#define TA     400
#define FDIM   256
#define HDIM   256
#define FRAME  320
#define SHIFT  160
#define LSIG   160000
#define LAUX   64000
#define NCLS   101
#define NSLC   8
#define SLC    (TA / NSLC)

// ---------------- scratch ----------------
__device__ float g_out   [BDIM * TIN * FDIM];
__device__ float g_out2  [BDIM * TIN * FDIM];
__device__ float g_aux   [BDIM * TA  * FDIM];
__device__ float g_h     [BDIM * TA  * HDIM];
__device__ float g_a     [BDIM * TA  * HDIM];
__device__ float g_logits[BDIM * TA  * HDIM];
__device__ float g_y     [BDIM * TIN * FRAME];
__device__ float g_bias2 [BDIM * HDIM];
__device__ float g_emb   [BDIM * FDIM];
__device__ float g_evec  [4 * BDIM * FDIM];
__device__ float g_glnp  [BDIM * 16 * 2];
__device__ float g_hpart [BDIM * NSLC * HDIM * 2];
__device__ float g_ppart [BDIM * NSLC * HDIM * 4];

// bf16 split weight planes, layout [N][K]
__device__ __nv_bfloat16 w_in_hi [256 * 320];
__device__ __nv_bfloat16 w_in_lo [256 * 320];
__device__ __nv_bfloat16 w_ec_hi [256 * 256];
__device__ __nv_bfloat16 w_ec_lo [256 * 256];
__device__ __nv_bfloat16 w_a1_hi [256 * 256];
__device__ __nv_bfloat16 w_a1_lo [256 * 256];
__device__ __nv_bfloat16 w_a2_hi [256 * 256];
__device__ __nv_bfloat16 w_a2_lo [256 * 256];
__device__ __nv_bfloat16 w_arn_hi[4 * 256 * 256];
__device__ __nv_bfloat16 w_arn_lo[4 * 256 * 256];
__device__ __nv_bfloat16 w_out_hi[320 * 256];
__device__ __nv_bfloat16 w_out_lo[320 * 256];

// ---------------- helpers ----------------
__device__ __forceinline__ uint32_t smem_u32(const void* p) {
    uint32_t a;
    asm("{ .reg .u64 t; cvta.to.shared.u64 t, %1; cvt.u32.u64 %0, t; }" : "=r"(a) : "l"(p));
    return a;
}
__device__ __forceinline__ void ldmx4(uint32_t* r, uint32_t addr) {
    asm volatile("ldmatrix.sync.aligned.m8n8.x4.shared.b16 {%0,%1,%2,%3}, [%4];"
                 : "=r"(r[0]), "=r"(r[1]), "=r"(r[2]), "=r"(r[3]) : "r"(addr));
}
__device__ __forceinline__ void ldmx2(uint32_t* r, uint32_t addr) {
    asm volatile("ldmatrix.sync.aligned.m8n8.x2.shared.b16 {%0,%1}, [%2];"
                 : "=r"(r[0]), "=r"(r[1]) : "r"(addr));
}
__device__ __forceinline__ void mma_bf16(float* c, const uint32_t* a, const uint32_t* b) {
    asm volatile("mma.sync.aligned.m16n8k16.row.col.f32.bf16.bf16.f32 "
                 "{%0,%1,%2,%3}, {%4,%5,%6,%7}, {%8,%9}, {%0,%1,%2,%3};"
                 : "+f"(c[0]), "+f"(c[1]), "+f"(c[2]), "+f"(c[3])
                 : "r"(a[0]), "r"(a[1]), "r"(a[2]), "r"(a[3]), "r"(b[0]), "r"(b[1]));
}
__device__ __forceinline__ void cp16(uint32_t saddr, const void* gaddr) {
    asm volatile("cp.async.ca.shared.global [%0], [%1], 16;" :: "r"(saddr), "l"(gaddr));
}
__device__ __forceinline__ void cp_commit() { asm volatile("cp.async.commit_group;" ::: "memory"); }
template<int W> __device__ __forceinline__ void cp_wait() {
    asm volatile("cp.async.wait_group %0;" :: "n"(W) : "memory");
}
__device__ __forceinline__ uint32_t SWZ(int row, int chunk) {
    return ((uint32_t)row << 7) + ((uint32_t)((chunk ^ (row & 7)) & 7) << 4);
}

// ---------------- weight prep: tiled transpose + split ----------------
struct PrepArgs {
    const float* src[10];
    __nv_bfloat16* hi[10];
    __nv_bfloat16* lo[10];
    int K[10];
    int N[10];
    int toff[11];
};
__global__ __launch_bounds__(256) void k_prep_all(PrepArgs a)
{
    __shared__ float tile[32][33];
    int tb = blockIdx.x;
    int r = 0;
    while (tb >= a.toff[r + 1]) r++;
    int ti = tb - a.toff[r];
    const int K = a.K[r], N = a.N[r];
    const int ntn = N / 32;
    const int tk = ti / ntn, tn = ti - tk * ntn;
    const int ty = threadIdx.x >> 5, tx = threadIdx.x & 31;
    #pragma unroll
    for (int q = 0; q < 4; q++) {
        const int k = tk * 32 + ty + q * 8;
        tile[ty + q * 8][tx] = a.src[r][(size_t)k * N + tn * 32 + tx];
    }
    __syncthreads();
    #pragma unroll
    for (int q = 0; q < 4; q++) {
        const int n = tn * 32 + ty + q * 8;
        float x = tile[tx][ty + q * 8];
        __nv_bfloat16 h = __float2bfloat16(x);
        const size_t o = (size_t)n * K + tk * 32 + tx;
        a.hi[r][o] = h;
        a.lo[r][o] = __float2bfloat16(x - __bfloat162float(h));
    }
}

// ---------------- tensor-core GEMM: R8 base + term-major MMA ordering ----------------
template<int NT, int MODE>
__global__ void __launch_bounds__(256, 3) k_tgemm(
    const float* __restrict__ Ain,
    const __nv_bfloat16* __restrict__ Bhi, const __nv_bfloat16* __restrict__ Blo,
    float* __restrict__ Cin,
    const float* __restrict__ e0, const float* __restrict__ e1, const float* __restrict__ e2,
    const int* __restrict__ aux_len, int Min, int K, int Nfull, int Lin, int arn_i,
    const float* A2, float* C2, int M2, int L2, int split)
{
    constexpr int MT   = 64;
    constexpr int WN   = NT / 4;     // 32 or 40
    constexpr int NF   = WN / 8;     // 4 or 5
    constexpr int MI   = 2;
    constexpr int APL  = MT * 128;   // 8192 per A plane
    constexpr int BPL  = NT * 128;

    extern __shared__ char smem[];
    const uint32_t sb = smem_u32(smem);
    const uint32_t aH = sb;
    const uint32_t aL = sb + APL;
    const uint32_t bH = sb + 2 * APL;
    const uint32_t bL = sb + 2 * APL + BPL;

    const int tid  = threadIdx.x;
    const int w    = tid >> 5;
    const int lane = tid & 31;
    const int b    = blockIdx.y;
    const int nbase = blockIdx.z * NT;

    const float* A = Ain;
    float* C = Cin;
    int M = Min, L = Lin;
    int bx = blockIdx.x;
    if (MODE == 0 && split > 0 && bx >= split) {
        A = A2; C = C2; M = M2; L = L2; bx -= split;
    }
    const int t0 = bx * MT;
    const int NB = K / 64;
    const int wm = w >> 2;
    const int wn = w & 3;
    const int wn0 = wn * WN;

    int   len  = 0;
    float mean = 0.f, inv = 0.f;
    if (MODE == 1) {
        len = aux_len[b];
        double s = 0.0, q = 0.0;
        #pragma unroll
        for (int i = 0; i < 16; i++) {
            s += (double)g_glnp[(b * 16 + i) * 2 + 0];
            q += (double)g_glnp[(b * 16 + i) * 2 + 1];
        }
        const double n = (double)len * FDIM;
        double m = s / n;
        double var = q / n - m * m;
        mean = (float)m;
        inv  = (float)(1.0 / sqrt(var + 1e-5));
    }

    const int arow = tid >> 2;
    const int achk = (tid & 3) * 2;
    const int ac0  = achk * 8;

    float acc[MI][NF][4];
    #pragma unroll
    for (int mi = 0; mi < MI; mi++)
        #pragma unroll
        for (int nj = 0; nj < NF; nj++)
            #pragma unroll
            for (int q = 0; q < 4; q++) acc[mi][nj][q] = 0.f;

    auto stageA = [&](int kb) {
        const int t = t0 + arow;
        float va[16];
        if (MODE == 0) {
            if (t < M) {
                const float* src = A + (size_t)b * L;
                const int base = t * SHIFT + kb * 64 + ac0;
                #pragma unroll
                for (int q = 0; q < 4; q++) {
                    const int p = base + q * 4;
                    if (p + 3 < L) {
                        float4 f = *(const float4*)(src + p);
                        va[q*4+0]=f.x; va[q*4+1]=f.y; va[q*4+2]=f.z; va[q*4+3]=f.w;
                    } else {
                        #pragma unroll
                        for (int j = 0; j < 4; j++) va[q*4+j] = (p + j < L) ? src[p + j] : 0.f;
                    }
                }
            } else {
                #pragma unroll
                for (int j = 0; j < 16; j++) va[j] = 0.f;
            }
        } else {
            const bool valid = (MODE == 1) ? (t < len) : (t < M);
            if (valid) {
                const float* src = A + ((size_t)b * M + t) * K + kb * 64 + ac0;
                #pragma unroll
                for (int q = 0; q < 4; q++) {
                    float4 f = *(const float4*)(src + q * 4);
                    va[q*4+0]=f.x; va[q*4+1]=f.y; va[q*4+2]=f.z; va[q*4+3]=f.w;
                }
                if (MODE == 1) {
                    const int c0 = kb * 64 + ac0;
                    #pragma unroll
                    for (int q = 0; q < 4; q++) {
                        float4 gg = *(const float4*)(e0 + c0 + q * 4);
                        float4 gb = *(const float4*)(e1 + c0 + q * 4);
                        va[q*4+0] = gg.x * inv * (va[q*4+0] - mean) + gb.x;
                        va[q*4+1] = gg.y * inv * (va[q*4+1] - mean) + gb.y;
                        va[q*4+2] = gg.z * inv * (va[q*4+2] - mean) + gb.z;
                        va[q*4+3] = gg.w * inv * (va[q*4+3] - mean) + gb.w;
                    }
                }
            } else {
                #pragma unroll
                for (int j = 0; j < 16; j++) va[j] = 0.f;
            }
        }
        #pragma unroll
        for (int q = 0; q < 2; q++) {
            union { __nv_bfloat16 x[8]; uint4 v; } H, Lo;
            #pragma unroll
            for (int j = 0; j < 8; j++) {
                float f = va[q * 8 + j];
                __nv_bfloat16 hb = __float2bfloat16(f);
                H.x[j]  = hb;
                Lo.x[j] = __float2bfloat16(f - __bfloat162float(hb));
            }
            const uint32_t so = SWZ(arow, achk + q);
            *(uint4*)(smem + so)       = H.v;
            *(uint4*)(smem + APL + so) = Lo.v;
        }
    };
    auto cpB = [&](int kb) {
        for (int idx = tid; idx < NT * 8; idx += 256) {
            const int n = idx >> 3, c = idx & 7;
            const uint32_t so = SWZ(n, c);
            cp16(bH + so, Bhi + (size_t)(nbase + n) * K + kb * 64 + c * 8);
            cp16(bL + so, Blo + (size_t)(nbase + n) * K + kb * 64 + c * 8);
        }
    };
    // term-major compute: load all frags, then hh / hl / lh sweeps (8-apart RAW)
    auto compute = [&]() {
        #pragma unroll
        for (int ki = 0; ki < 4; ki++) {
            uint32_t bh[NF][2], bl[NF][2];
            #pragma unroll
            for (int p = 0; p < NF / 2; p++) {
                const int gq = lane >> 3;
                const int nrow = wn0 + p * 16 + ((gq >> 1) << 3) + (lane & 7);
                const int chunk = ki * 2 + (gq & 1);
                const uint32_t off = SWZ(nrow, chunk);
                uint32_t r4[4];
                ldmx4(r4, bH + off);
                bh[2*p][0]=r4[0]; bh[2*p][1]=r4[1]; bh[2*p+1][0]=r4[2]; bh[2*p+1][1]=r4[3];
                ldmx4(r4, bL + off);
                bl[2*p][0]=r4[0]; bl[2*p][1]=r4[1]; bl[2*p+1][0]=r4[2]; bl[2*p+1][1]=r4[3];
            }
            if (NF & 1) {
                const int nj = NF - 1;
                const int nrow = wn0 + nj * 8 + (lane & 7);
                const int chunk = ki * 2 + ((lane & 15) >> 3);
                const uint32_t off = SWZ(nrow, chunk);
                ldmx2(bh[nj], bH + off);
                ldmx2(bl[nj], bL + off);
            }
            uint32_t ah[MI][4], al[MI][4];
            #pragma unroll
            for (int mi = 0; mi < MI; mi++) {
                const int row = wm * 32 + mi * 16 + (lane & 15);
                const int chunk = ki * 2 + (lane >> 4);
                const uint32_t off = SWZ(row, chunk);
                ldmx4(ah[mi], aH + off);
                ldmx4(al[mi], aL + off);
            }
            // term 1: hi*hi
            #pragma unroll
            for (int mi = 0; mi < MI; mi++)
                #pragma unroll
                for (int nj = 0; nj < NF; nj++)
                    mma_bf16(acc[mi][nj], ah[mi], bh[nj]);
            // term 2: hi*lo
            #pragma unroll
            for (int mi = 0; mi < MI; mi++)
                #pragma unroll
                for (int nj = 0; nj < NF; nj++)
                    mma_bf16(acc[mi][nj], ah[mi], bl[nj]);
            // term 3: lo*hi
            #pragma unroll
            for (int mi = 0; mi < MI; mi++)
                #pragma unroll
                for (int nj = 0; nj < NF; nj++)
                    mma_bf16(acc[mi][nj], al[mi], bh[nj]);
        }
    };

    for (int kb = 0; kb < NB; kb++) {
        cpB(kb);
        cp_commit();
        stageA(kb);
        cp_wait<0>();
        __syncthreads();
        compute();
        __syncthreads();
    }

    // ---- epilogue ----
    #pragma unroll
    for (int mi = 0; mi < MI; mi++) {
        #pragma unroll
        for (int half = 0; half < 2; half++) {
            const int r = wm * 32 + mi * 16 + (lane >> 2) + half * 8;
            const int t = t0 + r;
            if (t >= M) continue;
            #pragma unroll
            for (int nj = 0; nj < NF; nj++) {
                const int col = nbase + wn0 + nj * 8 + (lane & 3) * 2;
                float v0 = acc[mi][nj][half * 2 + 0];
                float v1 = acc[mi][nj][half * 2 + 1];
                float r0, r1;
                if (MODE == 0) {
                    r0 = v0 + e0[col]; r1 = v1 + e0[col + 1];
                } else if (MODE == 1) {
                    if (t < len) { r0 = fmaxf(v0 + e2[col], 0.f); r1 = fmaxf(v1 + e2[col + 1], 0.f); }
                    else         { r0 = 0.f; r1 = 0.f; }
                } else if (MODE == 2) {
                    float a0 = fmaxf(v0 + g_bias2[b * HDIM + col],     0.f);
                    float a1 = fmaxf(v1 + g_bias2[b * HDIM + col + 1], 0.f);
                    r0 = tanhf(a0 * e0[col]     + e1[col]);
                    r1 = tanhf(a1 * e0[col + 1] + e1[col + 1]);
                } else if (MODE == 3) {
                    r0 = v0 + e0[col]; r1 = v1 + e0[col + 1];
                } else {
                    const float* ares = A + ((size_t)b * M + t) * K + col;
                    const float* ev   = g_evec + ((size_t)arn_i * BDIM + b) * FDIM + col;
                    r0 = ares[0] + tanhf(v0 + ev[0] + e0[col]);
                    r1 = ares[1] + tanhf(v1 + ev[1] + e0[col + 1]);
                }
                *(float2*)(C + ((size_t)b * M + t) * Nfull + col) = make_float2(r0, r1);
            }
        }
    }
}

// ---------------- GLN partials ----------------
__global__ __launch_bounds__(256) void k_gln_part(const int* __restrict__ aux_len)
{
    const int b = blockIdx.x, s = blockIdx.y;
    const int len = aux_len[b];
    const int tA = s * (TA / 16);
    const int tB = min(len, tA + TA / 16);
    float sum = 0.f, sq = 0.f;
    if (tB > tA) {
        const float* p = g_aux + ((size_t)b * TA + tA) * FDIM;
        const int n = (tB - tA) * FDIM;
        for (int i = threadIdx.x; i < n; i += 256) {
            float v = p[i];
            sum += v; sq += v * v;
        }
    }
    __shared__ float ss[256], qq[256];
    ss[threadIdx.x] = sum; qq[threadIdx.x] = sq;
    __syncthreads();
    for (int st = 128; st > 0; st >>= 1) {
        if (threadIdx.x < st) { ss[threadIdx.x] += ss[threadIdx.x + st]; qq[threadIdx.x] += qq[threadIdx.x + st]; }
        __syncthreads();
    }
    if (threadIdx.x == 0) {
        g_glnp[(b * 16 + s) * 2 + 0] = ss[0];
        g_glnp[(b * 16 + s) * 2 + 1] = qq[0];
    }
}

// ---------------- h stats partials + combine ----------------
__global__ __launch_bounds__(256) void k_hpart(const int* __restrict__ aux_len)
{
    const int b = blockIdx.x, s = blockIdx.y, ch = threadIdx.x;
    const int len = aux_len[b];
    const int tA = s * SLC;
    const int tB = min(len, tA + SLC);
    float sum = 0.f, sq = 0.f;
    const float* p = g_h + ((size_t)b * TA) * HDIM + ch;
    for (int t = tA; t < tB; t++) {
        float v = p[(size_t)t * HDIM];
        sum += v; sq += v * v;
    }
    float* o = g_hpart + (((size_t)b * NSLC + s) * HDIM + ch) * 2;
    o[0] = sum; o[1] = sq;
}
__global__ __launch_bounds__(256) void k_hcomb(const int* __restrict__ aux_len,
                                               const float* __restrict__ att_w1,
                                               const float* __restrict__ att_b1)
{
    const int b = blockIdx.x, ch = threadIdx.x;
    const int len = aux_len[b];
    __shared__ float sm[256], sstd[256];
    {
        float sum = 0.f, sq = 0.f;
        #pragma unroll
        for (int s = 0; s < NSLC; s++) {
            const float* o = g_hpart + (((size_t)b * NSLC + s) * HDIM + ch) * 2;
            sum += o[0]; sq += o[1];
        }
        const float n = (float)len;
        const float m = sum / n;
        const float var = (sq - n * m * m) / (n - 1.f);
        sm[ch] = m;
        sstd[ch] = sqrtf(fmaxf(var, 1e-4f));
    }
    __syncthreads();
    float acc = att_b1[ch];
    for (int k = 0; k < HDIM; k++) {
        acc += sm[k]   * att_w1[(size_t)(256 + k) * HDIM + ch]
             + sstd[k] * att_w1[(size_t)(512 + k) * HDIM + ch];
    }
    g_bias2[b * HDIM + ch] = acc;
}

// ---------------- pool partials + combine ----------------
__global__ __launch_bounds__(256) void k_ppart(const int* __restrict__ aux_len)
{
    const int b = blockIdx.x, s = blockIdx.y, ch = threadIdx.x;
    const int len = aux_len[b];
    const int tA = s * SLC;
    const int tB = min(len, tA + SLC);
    const float* lp = g_logits + (size_t)b * TA * HDIM + ch;
    const float* hp = g_h      + (size_t)b * TA * HDIM + ch;
    float mx = -1e30f, se = 0.f, s1 = 0.f, s2 = 0.f;
    for (int t = tA; t < tB; t++) {
        float l  = lp[(size_t)t * HDIM];
        float hv = hp[(size_t)t * HDIM];
        if (l > mx) {
            float sc = expf(mx - l);
            se *= sc; s1 *= sc; s2 *= sc;
            mx = l;
        }
        float e = expf(l - mx);
        se += e; s1 += hv * e; s2 += hv * hv * e;
    }
    float* o = g_ppart + (((size_t)b * NSLC + s) * HDIM + ch) * 4;
    o[0] = mx; o[1] = se; o[2] = s1; o[3] = s2;
}
__global__ __launch_bounds__(256) void k_pcomb(const float* __restrict__ bn5g,
                                               const float* __restrict__ bn5b,
                                               const float* __restrict__ fc6_w,
                                               const float* __restrict__ fc6_b,
                                               const float* __restrict__ bn6g,
                                               const float* __restrict__ bn6b,
                                               const float* __restrict__ cls_w,
                                               const float* __restrict__ cls_b,
                                               const float* __restrict__ arn_w2,
                                               float* __restrict__ out_cls, int write_cls)
{
    const int b = blockIdx.x, j = threadIdx.x;
    __shared__ float e[2 * HDIM];
    {
        float mx = -1e30f;
        float pm[NSLC];
        #pragma unroll
        for (int s = 0; s < NSLC; s++) {
            pm[s] = g_ppart[(((size_t)b * NSLC + s) * HDIM + j) * 4];
            mx = fmaxf(mx, pm[s]);
        }
        float se = 0.f, s1 = 0.f, s2 = 0.f;
        #pragma unroll
        for (int s = 0; s < NSLC; s++) {
            const float* o = g_ppart + (((size_t)b * NSLC + s) * HDIM + j) * 4;
            float sc = expf(pm[s] - mx);
            se += o[1] * sc; s1 += o[2] * sc; s2 += o[3] * sc;
        }
        float mu = s1 / se;
        float sg = sqrtf(fmaxf(s2 / se - mu * mu, 1e-4f));
        e[j]        = mu * bn5g[j]        + bn5b[j];
        e[j + HDIM] = sg * bn5g[HDIM + j] + bn5b[HDIM + j];
    }
    __syncthreads();
    float acc = fc6_b[j];
    for (int k = 0; k < 2 * HDIM; k++) acc += e[k] * fc6_w[(size_t)k * FDIM + j];
    const float em = acc * bn6g[j] + bn6b[j];
    g_emb[b * FDIM + j] = em;

    __shared__ float red[256];
    red[j] = em * em;
    __syncthreads();
    for (int st = 128; st > 0; st >>= 1) { if (j < st) red[j] += red[j + st]; __syncthreads(); }
    const float nrmv = fmaxf(sqrtf(red[0]), 1e-12f);
    __shared__ float emv[256];
    emv[j] = em;
    __syncthreads();
    if (write_cls && j < NCLS) {
        float c = cls_b[j];
        for (int k = 0; k < FDIM; k++) c += (emv[k] / nrmv) * cls_w[(size_t)k * NCLS + j];
        out_cls[b * NCLS + j] = c;
    }
    for (int i = 0; i < 4; i++) {
        const float* W = arn_w2 + (size_t)i * FDIM * FDIM;
        float a2 = 0.f;
        for (int k = 0; k < FDIM; k++) a2 += emv[k] * W[(size_t)k * FDIM + j];
        g_evec[((size_t)i * BDIM + b) * FDIM + j] = a2;
    }
}

__global__ __launch_bounds__(256) void k_ola(float* __restrict__ out)
{
    const int idx = blockIdx.x * blockDim.x + threadIdx.x;
    if (idx >= BDIM * LSIG) return;
    const int b = idx / LSIG;
    const int i = idx - b * LSIG;
    const int t = i / SHIFT;
    const int j = i - t * SHIFT;
    const float* yb = g_y + (size_t)b * TIN * FRAME;
    float v = yb[(size_t)t * FRAME + j];
    if (t > 0) { v += yb[(size_t)(t - 1) * FRAME + j + SHIFT]; v *= 0.5f; }
    out[idx] = v;
}

// ---------------- launch ----------------
extern "C" void kernel_launch(void* const* d_in, const int* in_sizes, int n_in,
                              void* d_out, int out_size)
{
    const float* input   = (const float*)d_in[0];
    const float* anchor  = (const float*)d_in[1];
    const int*   aux_len = (const int*)  d_in[2];
    const float* in_w    = (const float*)d_in[4];
    const float* in_b    = (const float*)d_in[5];
    const float* out_w   = (const float*)d_in[6];
    const float* out_b   = (const float*)d_in[7];
    const float* gln_g   = (const float*)d_in[8];
    const float* gln_b   = (const float*)d_in[9];
    const float* ecapa_w = (const float*)d_in[10];
    const float* ecapa_b = (const float*)d_in[11];
    const float* att_w1  = (const float*)d_in[12];
    const float* att_b1  = (const float*)d_in[13];
    const float* attbn_g = (const float*)d_in[14];
    const float* attbn_b = (const float*)d_in[15];
    const float* att_w2  = (const float*)d_in[16];
    const float* att_b2  = (const float*)d_in[17];
    const float* bn5_g   = (const float*)d_in[18];
    const float* bn5_b   = (const float*)d_in[19];
    const float* fc6_w   = (const float*)d_in[20];
    const float* fc6_b   = (const float*)d_in[21];
    const float* bn6_g   = (const float*)d_in[22];
    const float* bn6_b   = (const float*)d_in[23];
    const float* cls_w   = (const float*)d_in[24];
    const float* cls_b   = (const float*)d_in[25];
    const float* arn_w1  = (const float*)d_in[26];
    const float* arn_w2  = (const float*)d_in[27];
    const float* arn_b   = (const float*)d_in[28];

    float *p_out, *p_out2, *p_aux, *p_h, *p_a, *p_logits, *p_y;
    cudaGetSymbolAddress((void**)&p_out,    g_out);
    cudaGetSymbolAddress((void**)&p_out2,   g_out2);
    cudaGetSymbolAddress((void**)&p_aux,    g_aux);
    cudaGetSymbolAddress((void**)&p_h,      g_h);
    cudaGetSymbolAddress((void**)&p_a,      g_a);
    cudaGetSymbolAddress((void**)&p_logits, g_logits);
    cudaGetSymbolAddress((void**)&p_y,      g_y);

    __nv_bfloat16 *pw_in_h, *pw_in_l, *pw_ec_h, *pw_ec_l, *pw_a1_h, *pw_a1_l,
                  *pw_a2_h, *pw_a2_l, *pw_ar_h, *pw_ar_l, *pw_ou_h, *pw_ou_l;
    cudaGetSymbolAddress((void**)&pw_in_h, w_in_hi);  cudaGetSymbolAddress((void**)&pw_in_l, w_in_lo);
    cudaGetSymbolAddress((void**)&pw_ec_h, w_ec_hi);  cudaGetSymbolAddress((void**)&pw_ec_l, w_ec_lo);
    cudaGetSymbolAddress((void**)&pw_a1_h, w_a1_hi);  cudaGetSymbolAddress((void**)&pw_a1_l, w_a1_lo);
    cudaGetSymbolAddress((void**)&pw_a2_h, w_a2_hi);  cudaGetSymbolAddress((void**)&pw_a2_l, w_a2_lo);
    cudaGetSymbolAddress((void**)&pw_ar_h, w_arn_hi); cudaGetSymbolAddress((void**)&pw_ar_l, w_arn_lo);
    cudaGetSymbolAddress((void**)&pw_ou_h, w_out_hi); cudaGetSymbolAddress((void**)&pw_ou_l, w_out_lo);

    // ---- single fused weight-prep (tiled transpose) ----
    PrepArgs pa;
    int toff = 0;
    auto reg = [&](int r, const float* s, __nv_bfloat16* h, __nv_bfloat16* l, int K, int N) {
        pa.src[r] = s; pa.hi[r] = h; pa.lo[r] = l; pa.K[r] = K; pa.N[r] = N;
        pa.toff[r] = toff; toff += (K / 32) * (N / 32);
    };
    reg(0, in_w,    pw_in_h, pw_in_l, 320, 256);
    reg(1, ecapa_w, pw_ec_h, pw_ec_l, 256, 256);
    reg(2, att_w1,  pw_a1_h, pw_a1_l, 256, 256);
    reg(3, att_w2,  pw_a2_h, pw_a2_l, 256, 256);
    for (int i = 0; i < 4; i++)
        reg(4 + i, arn_w1 + (size_t)i * 65536, pw_ar_h + (size_t)i * 65536,
            pw_ar_l + (size_t)i * 65536, 256, 256);
    reg(8, out_w, pw_ou_h, pw_ou_l, 256, 320);
    pa.toff[9] = toff;
    pa.src[9] = out_w; pa.hi[9] = pw_ou_h; pa.lo[9] = pw_ou_l; pa.K[9] = 256; pa.N[9] = 320;
    pa.toff[10] = toff;
    k_prep_all<<<toff, 256>>>(pa);

    const int SM128 = 2 * (64 * 128) + 2 * (128 * 128);   // 49152
    const int SM160 = 2 * (64 * 128) + 2 * (160 * 128);   // 57344
    cudaFuncSetAttribute(k_tgemm<128,0>, cudaFuncAttributeMaxDynamicSharedMemorySize, SM128);
    cudaFuncSetAttribute(k_tgemm<128,1>, cudaFuncAttributeMaxDynamicSharedMemorySize, SM128);
    cudaFuncSetAttribute(k_tgemm<128,2>, cudaFuncAttributeMaxDynamicSharedMemorySize, SM128);
    cudaFuncSetAttribute(k_tgemm<128,3>, cudaFuncAttributeMaxDynamicSharedMemorySize, SM128);
    cudaFuncSetAttribute(k_tgemm<128,4>, cudaFuncAttributeMaxDynamicSharedMemorySize, SM128);
    cudaFuncSetAttribute(k_tgemm<160,3>, cudaFuncAttributeMaxDynamicSharedMemorySize, SM160);

    // 1. merged encoders: x blocks [0,16) -> input, [16,23) -> anchor; z = 2 N-halves
    k_tgemm<128,0><<<dim3(23, 32, 2), 256, SM128>>>(input, pw_in_h, pw_in_l, p_out, in_b,
                                                    nullptr, nullptr, nullptr, TIN, FRAME, FDIM, LSIG, 0,
                                                    anchor, p_aux, TA, LAUX, 16);
    // 2. GLN partials (combine folded into next GEMM)
    k_gln_part<<<dim3(32, 16), 256>>>(aux_len);
    // 3. GLN + ecapa + relu
    k_tgemm<128,1><<<dim3(7, 32, 2), 256, SM128>>>(p_aux, pw_ec_h, pw_ec_l, p_h, gln_g, gln_b,
                                                   ecapa_b, aux_len, TA, FDIM, HDIM, 0, 0,
                                                   nullptr, nullptr, 0, 0, 0);
    // 4. h stats + attention bias
    k_hpart<<<dim3(32, NSLC), 256>>>(aux_len);
    k_hcomb<<<32, 256>>>(aux_len, att_w1, att_b1);
    // 5. attention conv1(+relu+bn+tanh)
    k_tgemm<128,2><<<dim3(7, 32, 2), 256, SM128>>>(p_h, pw_a1_h, pw_a1_l, p_a, attbn_g, attbn_b,
                                                   nullptr, nullptr, TA, HDIM, HDIM, 0, 0,
                                                   nullptr, nullptr, 0, 0, 0);
    // 6. attention conv2
    k_tgemm<128,3><<<dim3(7, 32, 2), 256, SM128>>>(p_a, pw_a2_h, pw_a2_l, p_logits, att_b2,
                                                   nullptr, nullptr, nullptr, TA, HDIM, HDIM, 0, 0,
                                                   nullptr, nullptr, 0, 0, 0);
    // 7. pool + emb + classifier + evec
    k_ppart<<<dim3(32, NSLC), 256>>>(aux_len);
    const int write_cls = (out_size >= BDIM * LSIG + BDIM * NCLS) ? 1 : 0;
    k_pcomb<<<32, 256>>>(bn5_g, bn5_b, fc6_w, fc6_b, bn6_g, bn6_b, cls_w, cls_b,
                         arn_w2, (float*)d_out + (size_t)BDIM * LSIG, write_cls);
    // 8-11. 4 ARN residual blocks (ping-pong)
    const float* src = p_out;
    float*       dst = p_out2;
    for (int i = 0; i < 4; i++) {
        k_tgemm<128,4><<<dim3(16, 32, 2), 256, SM128>>>(src, pw_ar_h + (size_t)i * 65536,
                                                        pw_ar_l + (size_t)i * 65536, dst,
                                                        arn_b + i * FDIM, nullptr, nullptr,
                                                        nullptr, TIN, FDIM, FDIM, 0, i,
                                                        nullptr, nullptr, 0, 0, 0);
        const float* tmp = dst; dst = (float*)src; src = tmp;
    }
    // 12. decoder (N=320 in two 160-col halves)
    k_tgemm<160,3><<<dim3(16, 32, 2), 256, SM160>>>(src, pw_ou_h, pw_ou_l, p_y, out_b,
                                                    nullptr, nullptr, nullptr, TIN, FDIM, FRAME, 0, 0,
                                                    nullptr, nullptr, 0, 0, 0);
    // 13. OLA
    k_ola<<<(BDIM * LSIG + 255) / 256, 256>>>((float*)d_out);
}

// round 16
// speedup vs baseline: 1.8403x; 1.1860x over previous
#include <cuda_runtime.h>
#include <cuda_fp16.h>
#include <math.h>
#include <stdint.h>

#define BDIM   32
#define TIN    1000
#define TA     400
#define FDIM   256
#define HDIM   256
#define FRAME  320
#define SHIFT  160
#define LSIG   160000
#define LAUX   64000
#define NCLS   101
#define NSLC   8
#define SLC    (TA / NSLC)

// ---------------- scratch ----------------
__device__ float g_out   [BDIM * TIN * FDIM];
__device__ float g_out2  [BDIM * TIN * FDIM];
__device__ float g_aux   [BDIM * TA  * FDIM];
__device__ float g_h     [BDIM * TA  * HDIM];
__device__ float g_a     [BDIM * TA  * HDIM];
__device__ float g_logits[BDIM * TA  * HDIM];
__device__ float g_y     [BDIM * TIN * FRAME];
__device__ float g_bias2 [BDIM * HDIM];
__device__ float g_emb   [BDIM * FDIM];
__device__ float g_evec  [4 * BDIM * FDIM];
__device__ float g_glnp  [BDIM * 16 * 2];
__device__ float g_hpart [BDIM * NSLC * HDIM * 2];
__device__ float g_ppart [BDIM * NSLC * HDIM * 4];

// fp16 weight planes, layout [N][K]
__device__ __half w_in_f [256 * 320];
__device__ __half w_ec_f [256 * 256];
__device__ __half w_a1_f [256 * 256];
__device__ __half w_a2_f [256 * 256];
__device__ __half w_arn_f[4 * 256 * 256];
__device__ __half w_out_f[320 * 256];

// ---------------- helpers ----------------
__device__ __forceinline__ uint32_t smem_u32(const void* p) {
    uint32_t a;
    asm("{ .reg .u64 t; cvta.to.shared.u64 t, %1; cvt.u32.u64 %0, t; }" : "=r"(a) : "l"(p));
    return a;
}
__device__ __forceinline__ void ldmx4(uint32_t* r, uint32_t addr) {
    asm volatile("ldmatrix.sync.aligned.m8n8.x4.shared.b16 {%0,%1,%2,%3}, [%4];"
                 : "=r"(r[0]), "=r"(r[1]), "=r"(r[2]), "=r"(r[3]) : "r"(addr));
}
__device__ __forceinline__ void ldmx2(uint32_t* r, uint32_t addr) {
    asm volatile("ldmatrix.sync.aligned.m8n8.x2.shared.b16 {%0,%1}, [%2];"
                 : "=r"(r[0]), "=r"(r[1]) : "r"(addr));
}
__device__ __forceinline__ void mma_f16(float* c, const uint32_t* a, const uint32_t* b) {
    asm volatile("mma.sync.aligned.m16n8k16.row.col.f32.f16.f16.f32 "
                 "{%0,%1,%2,%3}, {%4,%5,%6,%7}, {%8,%9}, {%0,%1,%2,%3};"
                 : "+f"(c[0]), "+f"(c[1]), "+f"(c[2]), "+f"(c[3])
                 : "r"(a[0]), "r"(a[1]), "r"(a[2]), "r"(a[3]), "r"(b[0]), "r"(b[1]));
}
__device__ __forceinline__ void cp16(uint32_t saddr, const void* gaddr) {
    asm volatile("cp.async.ca.shared.global [%0], [%1], 16;" :: "r"(saddr), "l"(gaddr));
}
__device__ __forceinline__ void cp_commit() { asm volatile("cp.async.commit_group;" ::: "memory"); }
template<int W> __device__ __forceinline__ void cp_wait() {
    asm volatile("cp.async.wait_group %0;" :: "n"(W) : "memory");
}
__device__ __forceinline__ uint32_t SWZ(int row, int chunk) {
    return ((uint32_t)row << 7) + ((uint32_t)((chunk ^ (row & 7)) & 7) << 4);
}

// ---------------- weight prep: tiled transpose -> fp16 [N][K] ----------------
struct PrepArgs {
    const float* src[10];
    __half* dst[10];
    int K[10];
    int N[10];
    int toff[11];
};
__global__ __launch_bounds__(256) void k_prep_all(PrepArgs a)
{
    __shared__ float tile[32][33];
    int tb = blockIdx.x;
    int r = 0;
    while (tb >= a.toff[r + 1]) r++;
    int ti = tb - a.toff[r];
    const int K = a.K[r], N = a.N[r];
    const int ntn = N / 32;
    const int tk = ti / ntn, tn = ti - tk * ntn;
    const int ty = threadIdx.x >> 5, tx = threadIdx.x & 31;
    #pragma unroll
    for (int q = 0; q < 4; q++) {
        const int k = tk * 32 + ty + q * 8;
        tile[ty + q * 8][tx] = a.src[r][(size_t)k * N + tn * 32 + tx];
    }
    __syncthreads();
    #pragma unroll
    for (int q = 0; q < 4; q++) {
        const int n = tn * 32 + ty + q * 8;
        a.dst[r][(size_t)n * K + tk * 32 + tx] = __float2half(tile[tx][ty + q * 8]);
    }
}

// ---------------- fp16 tensor-core GEMM ----------------
// MODE 0: framed signal. +e0. MODE 1: GLN+relu. MODE 2: att1 tanh. MODE 3: +e0. MODE 4: ARN.
template<int NT, int MODE>
__global__ void __launch_bounds__(256, 3) k_tgemm(
    const float* __restrict__ Ain,
    const __half* __restrict__ Bf,
    float* __restrict__ Cin,
    const float* __restrict__ e0, const float* __restrict__ e1, const float* __restrict__ e2,
    const int* __restrict__ aux_len, int Min, int K, int Nfull, int Lin, int arn_i,
    const float* A2, float* C2, int M2, int L2, int split)
{
    constexpr int MT   = 64;
    constexpr int WN   = NT / 4;     // 32 or 40
    constexpr int NF   = WN / 8;     // 4 or 5
    constexpr int MI   = 2;
    constexpr int APL  = MT * 128;   // 8192 (A fp16 plane)

    extern __shared__ char smem[];
    const uint32_t sb = smem_u32(smem);
    const uint32_t aF = sb;
    const uint32_t bF = sb + APL;

    const int tid  = threadIdx.x;
    const int w    = tid >> 5;
    const int lane = tid & 31;
    const int b    = blockIdx.y;
    const int nbase = blockIdx.z * NT;

    const float* A = Ain;
    float* C = Cin;
    int M = Min, L = Lin;
    int bx = blockIdx.x;
    if (MODE == 0 && split > 0 && bx >= split) {
        A = A2; C = C2; M = M2; L = L2; bx -= split;
    }
    const int t0 = bx * MT;
    const int NB = K / 64;
    const int wm = w >> 2;
    const int wn = w & 3;
    const int wn0 = wn * WN;

    int   len  = 0;
    float mean = 0.f, inv = 0.f;
    if (MODE == 1) {
        len = aux_len[b];
        double s = 0.0, q = 0.0;
        #pragma unroll
        for (int i = 0; i < 16; i++) {
            s += (double)g_glnp[(b * 16 + i) * 2 + 0];
            q += (double)g_glnp[(b * 16 + i) * 2 + 1];
        }
        const double n = (double)len * FDIM;
        double m = s / n;
        double var = q / n - m * m;
        mean = (float)m;
        inv  = (float)(1.0 / sqrt(var + 1e-5));
    }

    const int arow = tid >> 2;
    const int achk = (tid & 3) * 2;
    const int ac0  = achk * 8;

    float acc[MI][NF][4];
    #pragma unroll
    for (int mi = 0; mi < MI; mi++)
        #pragma unroll
        for (int nj = 0; nj < NF; nj++)
            #pragma unroll
            for (int q = 0; q < 4; q++) acc[mi][nj][q] = 0.f;

    auto stageA = [&](int kb) {
        const int t = t0 + arow;
        float va[16];
        if (MODE == 0) {
            if (t < M) {
                const float* src = A + (size_t)b * L;
                const int base = t * SHIFT + kb * 64 + ac0;
                #pragma unroll
                for (int q = 0; q < 4; q++) {
                    const int p = base + q * 4;
                    if (p + 3 < L) {
                        float4 f = *(const float4*)(src + p);
                        va[q*4+0]=f.x; va[q*4+1]=f.y; va[q*4+2]=f.z; va[q*4+3]=f.w;
                    } else {
                        #pragma unroll
                        for (int j = 0; j < 4; j++) va[q*4+j] = (p + j < L) ? src[p + j] : 0.f;
                    }
                }
            } else {
                #pragma unroll
                for (int j = 0; j < 16; j++) va[j] = 0.f;
            }
        } else {
            const bool valid = (MODE == 1) ? (t < len) : (t < M);
            if (valid) {
                const float* src = A + ((size_t)b * M + t) * K + kb * 64 + ac0;
                #pragma unroll
                for (int q = 0; q < 4; q++) {
                    float4 f = *(const float4*)(src + q * 4);
                    va[q*4+0]=f.x; va[q*4+1]=f.y; va[q*4+2]=f.z; va[q*4+3]=f.w;
                }
                if (MODE == 1) {
                    const int c0 = kb * 64 + ac0;
                    #pragma unroll
                    for (int q = 0; q < 4; q++) {
                        float4 gg = *(const float4*)(e0 + c0 + q * 4);
                        float4 gb = *(const float4*)(e1 + c0 + q * 4);
                        va[q*4+0] = gg.x * inv * (va[q*4+0] - mean) + gb.x;
                        va[q*4+1] = gg.y * inv * (va[q*4+1] - mean) + gb.y;
                        va[q*4+2] = gg.z * inv * (va[q*4+2] - mean) + gb.z;
                        va[q*4+3] = gg.w * inv * (va[q*4+3] - mean) + gb.w;
                    }
                }
            } else {
                #pragma unroll
                for (int j = 0; j < 16; j++) va[j] = 0.f;
            }
        }
        #pragma unroll
        for (int q = 0; q < 2; q++) {
            union { __half x[8]; uint4 v; } H;
            #pragma unroll
            for (int j = 0; j < 8; j++) H.x[j] = __float2half(va[q * 8 + j]);
            *(uint4*)(smem + SWZ(arow, achk + q)) = H.v;
        }
    };
    auto cpB = [&](int kb) {
        for (int idx = tid; idx < NT * 8; idx += 256) {
            const int n = idx >> 3, c = idx & 7;
            cp16(bF + SWZ(n, c), Bf + (size_t)(nbase + n) * K + kb * 64 + c * 8);
        }
    };
    auto compute = [&]() {
        #pragma unroll
        for (int ki = 0; ki < 4; ki++) {
            uint32_t bfr[NF][2];
            #pragma unroll
            for (int p = 0; p < NF / 2; p++) {
                const int gq = lane >> 3;
                const int nrow = wn0 + p * 16 + ((gq >> 1) << 3) + (lane & 7);
                const int chunk = ki * 2 + (gq & 1);
                uint32_t r4[4];
                ldmx4(r4, bF + SWZ(nrow, chunk));
                bfr[2*p][0]=r4[0]; bfr[2*p][1]=r4[1]; bfr[2*p+1][0]=r4[2]; bfr[2*p+1][1]=r4[3];
            }
            if (NF & 1) {
                const int nj = NF - 1;
                const int nrow = wn0 + nj * 8 + (lane & 7);
                const int chunk = ki * 2 + ((lane & 15) >> 3);
                ldmx2(bfr[nj], bF + SWZ(nrow, chunk));
            }
            #pragma unroll
            for (int mi = 0; mi < MI; mi++) {
                uint32_t af[4];
                const int row = wm * 32 + mi * 16 + (lane & 15);
                const int chunk = ki * 2 + (lane >> 4);
                ldmx4(af, aF + SWZ(row, chunk));
                #pragma unroll
                for (int nj = 0; nj < NF; nj++)
                    mma_f16(acc[mi][nj], af, bfr[nj]);
            }
        }
    };

    for (int kb = 0; kb < NB; kb++) {
        cpB(kb);
        cp_commit();
        stageA(kb);
        cp_wait<0>();
        __syncthreads();
        compute();
        __syncthreads();
    }

    // ---- epilogue ----
    #pragma unroll
    for (int mi = 0; mi < MI; mi++) {
        #pragma unroll
        for (int half = 0; half < 2; half++) {
            const int r = wm * 32 + mi * 16 + (lane >> 2) + half * 8;
            const int t = t0 + r;
            if (t >= M) continue;
            #pragma unroll
            for (int nj = 0; nj < NF; nj++) {
                const int col = nbase + wn0 + nj * 8 + (lane & 3) * 2;
                float v0 = acc[mi][nj][half * 2 + 0];
                float v1 = acc[mi][nj][half * 2 + 1];
                float r0, r1;
                if (MODE == 0) {
                    r0 = v0 + e0[col]; r1 = v1 + e0[col + 1];
                } else if (MODE == 1) {
                    if (t < len) { r0 = fmaxf(v0 + e2[col], 0.f); r1 = fmaxf(v1 + e2[col + 1], 0.f); }
                    else         { r0 = 0.f; r1 = 0.f; }
                } else if (MODE == 2) {
                    float a0 = fmaxf(v0 + g_bias2[b * HDIM + col],     0.f);
                    float a1 = fmaxf(v1 + g_bias2[b * HDIM + col + 1], 0.f);
                    r0 = tanhf(a0 * e0[col]     + e1[col]);
                    r1 = tanhf(a1 * e0[col + 1] + e1[col + 1]);
                } else if (MODE == 3) {
                    r0 = v0 + e0[col]; r1 = v1 + e0[col + 1];
                } else {
                    const float* ares = A + ((size_t)b * M + t) * K + col;
                    const float* ev   = g_evec + ((size_t)arn_i * BDIM + b) * FDIM + col;
                    r0 = ares[0] + tanhf(v0 + ev[0] + e0[col]);
                    r1 = ares[1] + tanhf(v1 + ev[1] + e0[col + 1]);
                }
                *(float2*)(C + ((size_t)b * M + t) * Nfull + col) = make_float2(r0, r1);
            }
        }
    }
}

// ---------------- GLN partials ----------------
__global__ __launch_bounds__(256) void k_gln_part(const int* __restrict__ aux_len)
{
    const int b = blockIdx.x, s = blockIdx.y;
    const int len = aux_len[b];
    const int tA = s * (TA / 16);
    const int tB = min(len, tA + TA / 16);
    float sum = 0.f, sq = 0.f;
    if (tB > tA) {
        const float* p = g_aux + ((size_t)b * TA + tA) * FDIM;
        const int n = (tB - tA) * FDIM;
        for (int i = threadIdx.x; i < n; i += 256) {
            float v = p[i];
            sum += v; sq += v * v;
        }
    }
    __shared__ float ss[256], qq[256];
    ss[threadIdx.x] = sum; qq[threadIdx.x] = sq;
    __syncthreads();
    for (int st = 128; st > 0; st >>= 1) {
        if (threadIdx.x < st) { ss[threadIdx.x] += ss[threadIdx.x + st]; qq[threadIdx.x] += qq[threadIdx.x + st]; }
        __syncthreads();
    }
    if (threadIdx.x == 0) {
        g_glnp[(b * 16 + s) * 2 + 0] = ss[0];
        g_glnp[(b * 16 + s) * 2 + 1] = qq[0];
    }
}

// ---------------- h stats partials + combine ----------------
__global__ __launch_bounds__(256) void k_hpart(const int* __restrict__ aux_len)
{
    const int b = blockIdx.x, s = blockIdx.y, ch = threadIdx.x;
    const int len = aux_len[b];
    const int tA = s * SLC;
    const int tB = min(len, tA + SLC);
    float sum = 0.f, sq = 0.f;
    const float* p = g_h + ((size_t)b * TA) * HDIM + ch;
    for (int t = tA; t < tB; t++) {
        float v = p[(size_t)t * HDIM];
        sum += v; sq += v * v;
    }
    float* o = g_hpart + (((size_t)b * NSLC + s) * HDIM + ch) * 2;
    o[0] = sum; o[1] = sq;
}
__global__ __launch_bounds__(256) void k_hcomb(const int* __restrict__ aux_len,
                                               const float* __restrict__ att_w1,
                                               const float* __restrict__ att_b1)
{
    const int b = blockIdx.x, ch = threadIdx.x;
    const int len = aux_len[b];
    __shared__ float sm[256], sstd[256];
    {
        float sum = 0.f, sq = 0.f;
        #pragma unroll
        for (int s = 0; s < NSLC; s++) {
            const float* o = g_hpart + (((size_t)b * NSLC + s) * HDIM + ch) * 2;
            sum += o[0]; sq += o[1];
        }
        const float n = (float)len;
        const float m = sum / n;
        const float var = (sq - n * m * m) / (n - 1.f);
        sm[ch] = m;
        sstd[ch] = sqrtf(fmaxf(var, 1e-4f));
    }
    __syncthreads();
    float acc = att_b1[ch];
    for (int k = 0; k < HDIM; k++) {
        acc += sm[k]   * att_w1[(size_t)(256 + k) * HDIM + ch]
             + sstd[k] * att_w1[(size_t)(512 + k) * HDIM + ch];
    }
    g_bias2[b * HDIM + ch] = acc;
}

// ---------------- pool partials + combine ----------------
__global__ __launch_bounds__(256) void k_ppart(const int* __restrict__ aux_len)
{
    const int b = blockIdx.x, s = blockIdx.y, ch = threadIdx.x;
    const int len = aux_len[b];
    const int tA = s * SLC;
    const int tB = min(len, tA + SLC);
    const float* lp = g_logits + (size_t)b * TA * HDIM + ch;
    const float* hp = g_h      + (size_t)b * TA * HDIM + ch;
    float mx = -1e30f, se = 0.f, s1 = 0.f, s2 = 0.f;
    for (int t = tA; t < tB; t++) {
        float l  = lp[(size_t)t * HDIM];
        float hv = hp[(size_t)t * HDIM];
        if (l > mx) {
            float sc = expf(mx - l);
            se *= sc; s1 *= sc; s2 *= sc;
            mx = l;
        }
        float e = expf(l - mx);
        se += e; s1 += hv * e; s2 += hv * hv * e;
    }
    float* o = g_ppart + (((size_t)b * NSLC + s) * HDIM + ch) * 4;
    o[0] = mx; o[1] = se; o[2] = s1; o[3] = s2;
}
__global__ __launch_bounds__(256) void k_pcomb(const float* __restrict__ bn5g,
                                               const float* __restrict__ bn5b,
                                               const float* __restrict__ fc6_w,
                                               const float* __restrict__ fc6_b,
                                               const float* __restrict__ bn6g,
                                               const float* __restrict__ bn6b,
                                               const float* __restrict__ cls_w,
                                               const float* __restrict__ cls_b,
                                               const float* __restrict__ arn_w2,
                                               float* __restrict__ out_cls, int write_cls)
{
    const int b = blockIdx.x, j = threadIdx.x;
    __shared__ float e[2 * HDIM];
    {
        float mx = -1e30f;
        float pm[NSLC];
        #pragma unroll
        for (int s = 0; s < NSLC; s++) {
            pm[s] = g_ppart[(((size_t)b * NSLC + s) * HDIM + j) * 4];
            mx = fmaxf(mx, pm[s]);
        }
        float se = 0.f, s1 = 0.f, s2 = 0.f;
        #pragma unroll
        for (int s = 0; s < NSLC; s++) {
            const float* o = g_ppart + (((size_t)b * NSLC + s) * HDIM + j) * 4;
            float sc = expf(pm[s] - mx);
            se += o[1] * sc; s1 += o[2] * sc; s2 += o[3] * sc;
        }
        float mu = s1 / se;
        float sg = sqrtf(fmaxf(s2 / se - mu * mu, 1e-4f));
        e[j]        = mu * bn5g[j]        + bn5b[j];
        e[j + HDIM] = sg * bn5g[HDIM + j] + bn5b[HDIM + j];
    }
    __syncthreads();
    float acc = fc6_b[j];
    for (int k = 0; k < 2 * HDIM; k++) acc += e[k] * fc6_w[(size_t)k * FDIM + j];
    const float em = acc * bn6g[j] + bn6b[j];
    g_emb[b * FDIM + j] = em;

    __shared__ float red[256];
    red[j] = em * em;
    __syncthreads();
    for (int st = 128; st > 0; st >>= 1) { if (j < st) red[j] += red[j + st]; __syncthreads(); }
    const float nrmv = fmaxf(sqrtf(red[0]), 1e-12f);
    __shared__ float emv[256];
    emv[j] = em;
    __syncthreads();
    if (write_cls && j < NCLS) {
        float c = cls_b[j];
        for (int k = 0; k < FDIM; k++) c += (emv[k] / nrmv) * cls_w[(size_t)k * NCLS + j];
        out_cls[b * NCLS + j] = c;
    }
    for (int i = 0; i < 4; i++) {
        const float* W = arn_w2 + (size_t)i * FDIM * FDIM;
        float a2 = 0.f;
        for (int k = 0; k < FDIM; k++) a2 += emv[k] * W[(size_t)k * FDIM + j];
        g_evec[((size_t)i * BDIM + b) * FDIM + j] = a2;
    }
}

__global__ __launch_bounds__(256) void k_ola(float* __restrict__ out)
{
    const int idx = blockIdx.x * blockDim.x + threadIdx.x;
    if (idx >= BDIM * LSIG) return;
    const int b = idx / LSIG;
    const int i = idx - b * LSIG;
    const int t = i / SHIFT;
    const int j = i - t * SHIFT;
    const float* yb = g_y + (size_t)b * TIN * FRAME;
    float v = yb[(size_t)t * FRAME + j];
    if (t > 0) { v += yb[(size_t)(t - 1) * FRAME + j + SHIFT]; v *= 0.5f; }
    out[idx] = v;
}

// ---------------- launch ----------------
extern "C" void kernel_launch(void* const* d_in, const int* in_sizes, int n_in,
                              void* d_out, int out_size)
{
    const float* input   = (const float*)d_in[0];
    const float* anchor  = (const float*)d_in[1];
    const int*   aux_len = (const int*)  d_in[2];
    const float* in_w    = (const float*)d_in[4];
    const float* in_b    = (const float*)d_in[5];
    const float* out_w   = (const float*)d_in[6];
    const float* out_b   = (const float*)d_in[7];
    const float* gln_g   = (const float*)d_in[8];
    const float* gln_b   = (const float*)d_in[9];
    const float* ecapa_w = (const float*)d_in[10];
    const float* ecapa_b = (const float*)d_in[11];
    const float* att_w1  = (const float*)d_in[12];
    const float* att_b1  = (const float*)d_in[13];
    const float* attbn_g = (const float*)d_in[14];
    const float* attbn_b = (const float*)d_in[15];
    const float* att_w2  = (const float*)d_in[16];
    const float* att_b2  = (const float*)d_in[17];
    const float* bn5_g   = (const float*)d_in[18];
    const float* bn5_b   = (const float*)d_in[19];
    const float* fc6_w   = (const float*)d_in[20];
    const float* fc6_b   = (const float*)d_in[21];
    const float* bn6_g   = (const float*)d_in[22];
    const float* bn6_b   = (const float*)d_in[23];
    const float* cls_w   = (const float*)d_in[24];
    const float* cls_b   = (const float*)d_in[25];
    const float* arn_w1  = (const float*)d_in[26];
    const float* arn_w2  = (const float*)d_in[27];
    const float* arn_b   = (const float*)d_in[28];

    float *p_out, *p_out2, *p_aux, *p_h, *p_a, *p_logits, *p_y;
    cudaGetSymbolAddress((void**)&p_out,    g_out);
    cudaGetSymbolAddress((void**)&p_out2,   g_out2);
    cudaGetSymbolAddress((void**)&p_aux,    g_aux);
    cudaGetSymbolAddress((void**)&p_h,      g_h);
    cudaGetSymbolAddress((void**)&p_a,      g_a);
    cudaGetSymbolAddress((void**)&p_logits, g_logits);
    cudaGetSymbolAddress((void**)&p_y,      g_y);

    __half *pw_in, *pw_ec, *pw_a1, *pw_a2, *pw_ar, *pw_ou;
    cudaGetSymbolAddress((void**)&pw_in, w_in_f);
    cudaGetSymbolAddress((void**)&pw_ec, w_ec_f);
    cudaGetSymbolAddress((void**)&pw_a1, w_a1_f);
    cudaGetSymbolAddress((void**)&pw_a2, w_a2_f);
    cudaGetSymbolAddress((void**)&pw_ar, w_arn_f);
    cudaGetSymbolAddress((void**)&pw_ou, w_out_f);

    // ---- single fused weight-prep (tiled transpose -> fp16) ----
    PrepArgs pa;
    int toff = 0;
    auto reg = [&](int r, const float* s, __half* d, int K, int N) {
        pa.src[r] = s; pa.dst[r] = d; pa.K[r] = K; pa.N[r] = N;
        pa.toff[r] = toff; toff += (K / 32) * (N / 32);
    };
    reg(0, in_w,    pw_in, 320, 256);
    reg(1, ecapa_w, pw_ec, 256, 256);
    reg(2, att_w1,  pw_a1, 256, 256);
    reg(3, att_w2,  pw_a2, 256, 256);
    for (int i = 0; i < 4; i++)
        reg(4 + i, arn_w1 + (size_t)i * 65536, pw_ar + (size_t)i * 65536, 256, 256);
    reg(8, out_w, pw_ou, 256, 320);
    pa.toff[9] = toff;
    pa.src[9] = out_w; pa.dst[9] = pw_ou; pa.K[9] = 256; pa.N[9] = 320;
    pa.toff[10] = toff;
    k_prep_all<<<toff, 256>>>(pa);

    const int SM128 = 64 * 128 + 128 * 128;   // 24576
    const int SM160 = 64 * 128 + 160 * 128;   // 28672
    cudaFuncSetAttribute(k_tgemm<128,0>, cudaFuncAttributeMaxDynamicSharedMemorySize, SM128);
    cudaFuncSetAttribute(k_tgemm<128,1>, cudaFuncAttributeMaxDynamicSharedMemorySize, SM128);
    cudaFuncSetAttribute(k_tgemm<128,2>, cudaFuncAttributeMaxDynamicSharedMemorySize, SM128);
    cudaFuncSetAttribute(k_tgemm<128,3>, cudaFuncAttributeMaxDynamicSharedMemorySize, SM128);
    cudaFuncSetAttribute(k_tgemm<128,4>, cudaFuncAttributeMaxDynamicSharedMemorySize, SM128);
    cudaFuncSetAttribute(k_tgemm<160,3>, cudaFuncAttributeMaxDynamicSharedMemorySize, SM160);

    // 1. merged encoders: x blocks [0,16) -> input, [16,23) -> anchor; z = 2 N-halves
    k_tgemm<128,0><<<dim3(23, 32, 2), 256, SM128>>>(input, pw_in, p_out, in_b,
                                                    nullptr, nullptr, nullptr, TIN, FRAME, FDIM, LSIG, 0,
                                                    anchor, p_aux, TA, LAUX, 16);
    // 2. GLN partials (combine folded into next GEMM)
    k_gln_part<<<dim3(32, 16), 256>>>(aux_len);
    // 3. GLN + ecapa + relu
    k_tgemm<128,1><<<dim3(7, 32, 2), 256, SM128>>>(p_aux, pw_ec, p_h, gln_g, gln_b,
                                                   ecapa_b, aux_len, TA, FDIM, HDIM, 0, 0,
                                                   nullptr, nullptr, 0, 0, 0);
    // 4. h stats + attention bias
    k_hpart<<<dim3(32, NSLC), 256>>>(aux_len);
    k_hcomb<<<32, 256>>>(aux_len, att_w1, att_b1);
    // 5. attention conv1(+relu+bn+tanh)
    k_tgemm<128,2><<<dim3(7, 32, 2), 256, SM128>>>(p_h, pw_a1, p_a, attbn_g, attbn_b,
                                                   nullptr, nullptr, TA, HDIM, HDIM, 0, 0,
                                                   nullptr, nullptr, 0, 0, 0);
    // 6. attention conv2
    k_tgemm<128,3><<<dim3(7, 32, 2), 256, SM128>>>(p_a, pw_a2, p_logits, att_b2,
                                                   nullptr, nullptr, nullptr, TA, HDIM, HDIM, 0, 0,
                                                   nullptr, nullptr, 0, 0, 0);
    // 7. pool + emb + classifier + evec
    k_ppart<<<dim3(32, NSLC), 256>>>(aux_len);
    const int write_cls = (out_size >= BDIM * LSIG + BDIM * NCLS) ? 1 : 0;
    k_pcomb<<<32, 256>>>(bn5_g, bn5_b, fc6_w, fc6_b, bn6_g, bn6_b, cls_w, cls_b,
                         arn_w2, (float*)d_out + (size_t)BDIM * LSIG, write_cls);
    // 8-11. 4 ARN residual blocks (ping-pong)
    const float* src = p_out;
    float*       dst = p_out2;
    for (int i = 0; i < 4; i++) {
        k_tgemm<128,4><<<dim3(16, 32, 2), 256, SM128>>>(src, pw_ar + (size_t)i * 65536, dst,
                                                        arn_b + i * FDIM, nullptr, nullptr,
                                                        nullptr, TIN, FDIM, FDIM, 0, i,
                                                        nullptr, nullptr, 0, 0, 0);
        const float* tmp = dst; dst = (float*)src; src = tmp;
    }
    // 12. decoder (N=320 in two 160-col halves)
    k_tgemm<160,3><<<dim3(16, 32, 2), 256, SM160>>>(src, pw_ou, p_y, out_b,
                                                    nullptr, nullptr, nullptr, TIN, FDIM, FRAME, 0, 0,
                                                    nullptr, nullptr, 0, 0, 0);
    // 13. OLA
    k_ola<<<(BDIM * LSIG + 255) / 256, 256>>>((float*)d_out);
}

// round 17
// speedup vs baseline: 1.8831x; 1.0232x over previous
#include <cuda_runtime.h>
#include <cuda_fp16.h>
#include <math.h>
#include <stdint.h>

#define BDIM   32
#define TIN    1000
#define TA     400
#define FDIM   256
#define HDIM   256
#define FRAME  320
#define SHIFT  160
#define LSIG   160000
#define LAUX   64000
#define NCLS   101
#define NSLC   8
#define SLC    (TA / NSLC)

// ---------------- scratch ----------------
__device__ float g_out   [BDIM * TIN * FDIM];
__device__ float g_out2  [BDIM * TIN * FDIM];
__device__ float g_aux   [BDIM * TA  * FDIM];
__device__ float g_h     [BDIM * TA  * HDIM];
__device__ float g_a     [BDIM * TA  * HDIM];
__device__ float g_logits[BDIM * TA  * HDIM];
__device__ float g_y     [BDIM * TIN * FRAME];
__device__ float g_bias2 [BDIM * HDIM];
__device__ float g_emb   [BDIM * FDIM];
__device__ float g_evec  [4 * BDIM * FDIM];
__device__ float g_glnp  [BDIM * 16 * 2];
__device__ float g_hpart [BDIM * NSLC * HDIM * 2];
__device__ float g_ppart [BDIM * NSLC * HDIM * 4];

// fp16 weight planes, layout [N][K]
__device__ __half w_in_f [256 * 320];
__device__ __half w_ec_f [256 * 256];
__device__ __half w_a1_f [256 * 256];
__device__ __half w_a2_f [256 * 256];
__device__ __half w_arn_f[4 * 256 * 256];
__device__ __half w_out_f[320 * 256];

// ---------------- helpers ----------------
__device__ __forceinline__ uint32_t smem_u32(const void* p) {
    uint32_t a;
    asm("{ .reg .u64 t; cvta.to.shared.u64 t, %1; cvt.u32.u64 %0, t; }" : "=r"(a) : "l"(p));
    return a;
}
__device__ __forceinline__ void ldmx4(uint32_t* r, uint32_t addr) {
    asm volatile("ldmatrix.sync.aligned.m8n8.x4.shared.b16 {%0,%1,%2,%3}, [%4];"
                 : "=r"(r[0]), "=r"(r[1]), "=r"(r[2]), "=r"(r[3]) : "r"(addr));
}
__device__ __forceinline__ void ldmx2(uint32_t* r, uint32_t addr) {
    asm volatile("ldmatrix.sync.aligned.m8n8.x2.shared.b16 {%0,%1}, [%2];"
                 : "=r"(r[0]), "=r"(r[1]) : "r"(addr));
}
__device__ __forceinline__ void mma_f16(float* c, const uint32_t* a, const uint32_t* b) {
    asm volatile("mma.sync.aligned.m16n8k16.row.col.f32.f16.f16.f32 "
                 "{%0,%1,%2,%3}, {%4,%5,%6,%7}, {%8,%9}, {%0,%1,%2,%3};"
                 : "+f"(c[0]), "+f"(c[1]), "+f"(c[2]), "+f"(c[3])
                 : "r"(a[0]), "r"(a[1]), "r"(a[2]), "r"(a[3]), "r"(b[0]), "r"(b[1]));
}
__device__ __forceinline__ void cp16(uint32_t saddr, const void* gaddr) {
    asm volatile("cp.async.ca.shared.global [%0], [%1], 16;" :: "r"(saddr), "l"(gaddr));
}
__device__ __forceinline__ void cp_commit() { asm volatile("cp.async.commit_group;" ::: "memory"); }
template<int W> __device__ __forceinline__ void cp_wait() {
    asm volatile("cp.async.wait_group %0;" :: "n"(W) : "memory");
}
__device__ __forceinline__ uint32_t SWZ(int row, int chunk) {
    return ((uint32_t)row << 7) + ((uint32_t)((chunk ^ (row & 7)) & 7) << 4);
}

// ---------------- weight prep: tiled transpose -> fp16 [N][K] ----------------
struct PrepArgs {
    const float* src[10];
    __half* dst[10];
    int K[10];
    int N[10];
    int toff[11];
};
__global__ __launch_bounds__(256) void k_prep_all(PrepArgs a)
{
    __shared__ float tile[32][33];
    int tb = blockIdx.x;
    int r = 0;
    while (tb >= a.toff[r + 1]) r++;
    int ti = tb - a.toff[r];
    const int K = a.K[r], N = a.N[r];
    const int ntn = N / 32;
    const int tk = ti / ntn, tn = ti - tk * ntn;
    const int ty = threadIdx.x >> 5, tx = threadIdx.x & 31;
    #pragma unroll
    for (int q = 0; q < 4; q++) {
        const int k = tk * 32 + ty + q * 8;
        tile[ty + q * 8][tx] = a.src[r][(size_t)k * N + tn * 32 + tx];
    }
    __syncthreads();
    #pragma unroll
    for (int q = 0; q < 4; q++) {
        const int n = tn * 32 + ty + q * 8;
        a.dst[r][(size_t)n * K + tk * 32 + tx] = __float2half(tile[tx][ty + q * 8]);
    }
}

// ---------------- fp16 tensor-core GEMM, double-buffered A+B, occ 3 ----------------
template<int NT, int MODE>
__global__ void __launch_bounds__(256, 3) k_tgemm(
    const float* __restrict__ Ain,
    const __half* __restrict__ Bf,
    float* __restrict__ Cin,
    const float* __restrict__ e0, const float* __restrict__ e1, const float* __restrict__ e2,
    const int* __restrict__ aux_len, int Min, int K, int Nfull, int Lin, int arn_i,
    const float* A2, float* C2, int M2, int L2, int split)
{
    constexpr int MT   = 64;
    constexpr int WN   = NT / 4;     // 32 or 40
    constexpr int NF   = WN / 8;     // 4 or 5
    constexpr int MI   = 2;
    constexpr int APL  = MT * 128;   // 8192 per A buffer
    constexpr int BPL  = NT * 128;   // per B buffer

    extern __shared__ char smem[];
    const uint32_t sb = smem_u32(smem);

    const int tid  = threadIdx.x;
    const int w    = tid >> 5;
    const int lane = tid & 31;
    const int b    = blockIdx.y;
    const int nbase = blockIdx.z * NT;

    const float* A = Ain;
    float* C = Cin;
    int M = Min, L = Lin;
    int bx = blockIdx.x;
    if (MODE == 0 && split > 0 && bx >= split) {
        A = A2; C = C2; M = M2; L = L2; bx -= split;
    }
    const int t0 = bx * MT;
    const int NB = K / 64;
    const int wm = w >> 2;
    const int wn = w & 3;
    const int wn0 = wn * WN;

    int   len  = 0;
    float mean = 0.f, inv = 0.f;
    if (MODE == 1) {
        len = aux_len[b];
        double s = 0.0, q = 0.0;
        #pragma unroll
        for (int i = 0; i < 16; i++) {
            s += (double)g_glnp[(b * 16 + i) * 2 + 0];
            q += (double)g_glnp[(b * 16 + i) * 2 + 1];
        }
        const double n = (double)len * FDIM;
        double m = s / n;
        double var = q / n - m * m;
        mean = (float)m;
        inv  = (float)(1.0 / sqrt(var + 1e-5));
    }

    const int arow = tid >> 2;
    const int achk = (tid & 3) * 2;
    const int ac0  = achk * 8;

    float acc[MI][NF][4];
    #pragma unroll
    for (int mi = 0; mi < MI; mi++)
        #pragma unroll
        for (int nj = 0; nj < NF; nj++)
            #pragma unroll
            for (int q = 0; q < 4; q++) acc[mi][nj][q] = 0.f;

    float va[16];

    // LDG + MODE transform into va (no SMEM write)
    auto prefA = [&](int kb) {
        const int t = t0 + arow;
        if (MODE == 0) {
            if (t < M) {
                const float* src = A + (size_t)b * L;
                const int base = t * SHIFT + kb * 64 + ac0;
                #pragma unroll
                for (int q = 0; q < 4; q++) {
                    const int p = base + q * 4;
                    if (p + 3 < L) {
                        float4 f = *(const float4*)(src + p);
                        va[q*4+0]=f.x; va[q*4+1]=f.y; va[q*4+2]=f.z; va[q*4+3]=f.w;
                    } else {
                        #pragma unroll
                        for (int j = 0; j < 4; j++) va[q*4+j] = (p + j < L) ? src[p + j] : 0.f;
                    }
                }
            } else {
                #pragma unroll
                for (int j = 0; j < 16; j++) va[j] = 0.f;
            }
        } else {
            const bool valid = (MODE == 1) ? (t < len) : (t < M);
            if (valid) {
                const float* src = A + ((size_t)b * M + t) * K + kb * 64 + ac0;
                #pragma unroll
                for (int q = 0; q < 4; q++) {
                    float4 f = *(const float4*)(src + q * 4);
                    va[q*4+0]=f.x; va[q*4+1]=f.y; va[q*4+2]=f.z; va[q*4+3]=f.w;
                }
                if (MODE == 1) {
                    const int c0 = kb * 64 + ac0;
                    #pragma unroll
                    for (int q = 0; q < 4; q++) {
                        float4 gg = *(const float4*)(e0 + c0 + q * 4);
                        float4 gb = *(const float4*)(e1 + c0 + q * 4);
                        va[q*4+0] = gg.x * inv * (va[q*4+0] - mean) + gb.x;
                        va[q*4+1] = gg.y * inv * (va[q*4+1] - mean) + gb.y;
                        va[q*4+2] = gg.z * inv * (va[q*4+2] - mean) + gb.z;
                        va[q*4+3] = gg.w * inv * (va[q*4+3] - mean) + gb.w;
                    }
                }
            } else {
                #pragma unroll
                for (int j = 0; j < 16; j++) va[j] = 0.f;
            }
        }
    };
    // cvt + STS into A buffer `buf`
    auto convA = [&](int buf) {
        char* base = smem + (size_t)buf * APL;
        #pragma unroll
        for (int q = 0; q < 2; q++) {
            union { __half x[8]; uint4 v; } H;
            #pragma unroll
            for (int j = 0; j < 8; j++) H.x[j] = __float2half(va[q * 8 + j]);
            *(uint4*)(base + SWZ(arow, achk + q)) = H.v;
        }
    };
    auto cpB = [&](int kb, int buf) {
        const uint32_t bF = sb + 2 * APL + (uint32_t)buf * BPL;
        for (int idx = tid; idx < NT * 8; idx += 256) {
            const int n = idx >> 3, c = idx & 7;
            cp16(bF + SWZ(n, c), Bf + (size_t)(nbase + n) * K + kb * 64 + c * 8);
        }
    };
    auto compute = [&](int buf) {
        const uint32_t aF = sb + (uint32_t)buf * APL;
        const uint32_t bF = sb + 2 * APL + (uint32_t)buf * BPL;
        #pragma unroll
        for (int ki = 0; ki < 4; ki++) {
            uint32_t bfr[NF][2];
            #pragma unroll
            for (int p = 0; p < NF / 2; p++) {
                const int gq = lane >> 3;
                const int nrow = wn0 + p * 16 + ((gq >> 1) << 3) + (lane & 7);
                const int chunk = ki * 2 + (gq & 1);
                uint32_t r4[4];
                ldmx4(r4, bF + SWZ(nrow, chunk));
                bfr[2*p][0]=r4[0]; bfr[2*p][1]=r4[1]; bfr[2*p+1][0]=r4[2]; bfr[2*p+1][1]=r4[3];
            }
            if (NF & 1) {
                const int nj = NF - 1;
                const int nrow = wn0 + nj * 8 + (lane & 7);
                const int chunk = ki * 2 + ((lane & 15) >> 3);
                ldmx2(bfr[nj], bF + SWZ(nrow, chunk));
            }
            #pragma unroll
            for (int mi = 0; mi < MI; mi++) {
                uint32_t af[4];
                const int row = wm * 32 + mi * 16 + (lane & 15);
                const int chunk = ki * 2 + (lane >> 4);
                ldmx4(af, aF + SWZ(row, chunk));
                #pragma unroll
                for (int nj = 0; nj < NF; nj++)
                    mma_f16(acc[mi][nj], af, bfr[nj]);
            }
        }
    };

    // prologue: stage k-block 0 into buffer 0
    prefA(0);
    convA(0);
    cpB(0, 0);
    cp_commit();
    for (int kb = 0; kb < NB; kb++) {
        const int buf = kb & 1;
        if (kb + 1 < NB) {
            prefA(kb + 1);              // LDGs in flight, consumed after compute
            cpB(kb + 1, buf ^ 1);
            cp_commit();
            cp_wait<1>();               // wait only for stage kb (prefetched last iter)
        } else {
            cp_wait<0>();
        }
        __syncthreads();
        compute(buf);
        if (kb + 1 < NB) convA(buf ^ 1);  // LDG latency covered by compute
        __syncthreads();
    }

    // ---- epilogue ----
    #pragma unroll
    for (int mi = 0; mi < MI; mi++) {
        #pragma unroll
        for (int half = 0; half < 2; half++) {
            const int r = wm * 32 + mi * 16 + (lane >> 2) + half * 8;
            const int t = t0 + r;
            if (t >= M) continue;
            #pragma unroll
            for (int nj = 0; nj < NF; nj++) {
                const int col = nbase + wn0 + nj * 8 + (lane & 3) * 2;
                float v0 = acc[mi][nj][half * 2 + 0];
                float v1 = acc[mi][nj][half * 2 + 1];
                float r0, r1;
                if (MODE == 0) {
                    r0 = v0 + e0[col]; r1 = v1 + e0[col + 1];
                } else if (MODE == 1) {
                    if (t < len) { r0 = fmaxf(v0 + e2[col], 0.f); r1 = fmaxf(v1 + e2[col + 1], 0.f); }
                    else         { r0 = 0.f; r1 = 0.f; }
                } else if (MODE == 2) {
                    float a0 = fmaxf(v0 + g_bias2[b * HDIM + col],     0.f);
                    float a1 = fmaxf(v1 + g_bias2[b * HDIM + col + 1], 0.f);
                    r0 = tanhf(a0 * e0[col]     + e1[col]);
                    r1 = tanhf(a1 * e0[col + 1] + e1[col + 1]);
                } else if (MODE == 3) {
                    r0 = v0 + e0[col]; r1 = v1 + e0[col + 1];
                } else {
                    const float* ares = A + ((size_t)b * M + t) * K + col;
                    const float* ev   = g_evec + ((size_t)arn_i * BDIM + b) * FDIM + col;
                    r0 = ares[0] + tanhf(v0 + ev[0] + e0[col]);
                    r1 = ares[1] + tanhf(v1 + ev[1] + e0[col + 1]);
                }
                *(float2*)(C + ((size_t)b * M + t) * Nfull + col) = make_float2(r0, r1);
            }
        }
    }
}

// ---------------- GLN partials ----------------
__global__ __launch_bounds__(256) void k_gln_part(const int* __restrict__ aux_len)
{
    const int b = blockIdx.x, s = blockIdx.y;
    const int len = aux_len[b];
    const int tA = s * (TA / 16);
    const int tB = min(len, tA + TA / 16);
    float sum = 0.f, sq = 0.f;
    if (tB > tA) {
        const float* p = g_aux + ((size_t)b * TA + tA) * FDIM;
        const int n = (tB - tA) * FDIM;
        for (int i = threadIdx.x; i < n; i += 256) {
            float v = p[i];
            sum += v; sq += v * v;
        }
    }
    __shared__ float ss[256], qq[256];
    ss[threadIdx.x] = sum; qq[threadIdx.x] = sq;
    __syncthreads();
    for (int st = 128; st > 0; st >>= 1) {
        if (threadIdx.x < st) { ss[threadIdx.x] += ss[threadIdx.x + st]; qq[threadIdx.x] += qq[threadIdx.x + st]; }
        __syncthreads();
    }
    if (threadIdx.x == 0) {
        g_glnp[(b * 16 + s) * 2 + 0] = ss[0];
        g_glnp[(b * 16 + s) * 2 + 1] = qq[0];
    }
}

// ---------------- h stats partials + combine ----------------
__global__ __launch_bounds__(256) void k_hpart(const int* __restrict__ aux_len)
{
    const int b = blockIdx.x, s = blockIdx.y, ch = threadIdx.x;
    const int len = aux_len[b];
    const int tA = s * SLC;
    const int tB = min(len, tA + SLC);
    float sum = 0.f, sq = 0.f;
    const float* p = g_h + ((size_t)b * TA) * HDIM + ch;
    for (int t = tA; t < tB; t++) {
        float v = p[(size_t)t * HDIM];
        sum += v; sq += v * v;
    }
    float* o = g_hpart + (((size_t)b * NSLC + s) * HDIM + ch) * 2;
    o[0] = sum; o[1] = sq;
}
__global__ __launch_bounds__(256) void k_hcomb(const int* __restrict__ aux_len,
                                               const float* __restrict__ att_w1,
                                               const float* __restrict__ att_b1)
{
    const int b = blockIdx.x, ch = threadIdx.x;
    const int len = aux_len[b];
    __shared__ float sm[256], sstd[256];
    {
        float sum = 0.f, sq = 0.f;
        #pragma unroll
        for (int s = 0; s < NSLC; s++) {
            const float* o = g_hpart + (((size_t)b * NSLC + s) * HDIM + ch) * 2;
            sum += o[0]; sq += o[1];
        }
        const float n = (float)len;
        const float m = sum / n;
        const float var = (sq - n * m * m) / (n - 1.f);
        sm[ch] = m;
        sstd[ch] = sqrtf(fmaxf(var, 1e-4f));
    }
    __syncthreads();
    float acc = att_b1[ch];
    for (int k = 0; k < HDIM; k++) {
        acc += sm[k]   * att_w1[(size_t)(256 + k) * HDIM + ch]
             + sstd[k] * att_w1[(size_t)(512 + k) * HDIM + ch];
    }
    g_bias2[b * HDIM + ch] = acc;
}

// ---------------- pool partials + combine ----------------
__global__ __launch_bounds__(256) void k_ppart(const int* __restrict__ aux_len)
{
    const int b = blockIdx.x, s = blockIdx.y, ch = threadIdx.x;
    const int len = aux_len[b];
    const int tA = s * SLC;
    const int tB = min(len, tA + SLC);
    const float* lp = g_logits + (size_t)b * TA * HDIM + ch;
    const float* hp = g_h      + (size_t)b * TA * HDIM + ch;
    float mx = -1e30f, se = 0.f, s1 = 0.f, s2 = 0.f;
    for (int t = tA; t < tB; t++) {
        float l  = lp[(size_t)t * HDIM];
        float hv = hp[(size_t)t * HDIM];
        if (l > mx) {
            float sc = expf(mx - l);
            se *= sc; s1 *= sc; s2 *= sc;
            mx = l;
        }
        float e = expf(l - mx);
        se += e; s1 += hv * e; s2 += hv * hv * e;
    }
    float* o = g_ppart + (((size_t)b * NSLC + s) * HDIM + ch) * 4;
    o[0] = mx; o[1] = se; o[2] = s1; o[3] = s2;
}
__global__ __launch_bounds__(256) void k_pcomb(const float* __restrict__ bn5g,
                                               const float* __restrict__ bn5b,
                                               const float* __restrict__ fc6_w,
                                               const float* __restrict__ fc6_b,
                                               const float* __restrict__ bn6g,
                                               const float* __restrict__ bn6b,
                                               const float* __restrict__ cls_w,
                                               const float* __restrict__ cls_b,
                                               const float* __restrict__ arn_w2,
                                               float* __restrict__ out_cls, int write_cls)
{
    const int b = blockIdx.x, j = threadIdx.x;
    __shared__ float e[2 * HDIM];
    {
        float mx = -1e30f;
        float pm[NSLC];
        #pragma unroll
        for (int s = 0; s < NSLC; s++) {
            pm[s] = g_ppart[(((size_t)b * NSLC + s) * HDIM + j) * 4];
            mx = fmaxf(mx, pm[s]);
        }
        float se = 0.f, s1 = 0.f, s2 = 0.f;
        #pragma unroll
        for (int s = 0; s < NSLC; s++) {
            const float* o = g_ppart + (((size_t)b * NSLC + s) * HDIM + j) * 4;
            float sc = expf(pm[s] - mx);
            se += o[1] * sc; s1 += o[2] * sc; s2 += o[3] * sc;
        }
        float mu = s1 / se;
        float sg = sqrtf(fmaxf(s2 / se - mu * mu, 1e-4f));
        e[j]        = mu * bn5g[j]        + bn5b[j];
        e[j + HDIM] = sg * bn5g[HDIM + j] + bn5b[HDIM + j];
    }
    __syncthreads();
    float acc = fc6_b[j];
    for (int k = 0; k < 2 * HDIM; k++) acc += e[k] * fc6_w[(size_t)k * FDIM + j];
    const float em = acc * bn6g[j] + bn6b[j];
    g_emb[b * FDIM + j] = em;

    __shared__ float red[256];
    red[j] = em * em;
    __syncthreads();
    for (int st = 128; st > 0; st >>= 1) { if (j < st) red[j] += red[j + st]; __syncthreads(); }
    const float nrmv = fmaxf(sqrtf(red[0]), 1e-12f);
    __shared__ float emv[256];
    emv[j] = em;
    __syncthreads();
    if (write_cls && j < NCLS) {
        float c = cls_b[j];
        for (int k = 0; k < FDIM; k++) c += (emv[k] / nrmv) * cls_w[(size_t)k * NCLS + j];
        out_cls[b * NCLS + j] = c;
    }
    for (int i = 0; i < 4; i++) {
        const float* W = arn_w2 + (size_t)i * FDIM * FDIM;
        float a2 = 0.f;
        for (int k = 0; k < FDIM; k++) a2 += emv[k] * W[(size_t)k * FDIM + j];
        g_evec[((size_t)i * BDIM + b) * FDIM + j] = a2;
    }
}

__global__ __launch_bounds__(256) void k_ola(float* __restrict__ out)
{
    const int idx = blockIdx.x * blockDim.x + threadIdx.x;
    if (idx >= BDIM * LSIG) return;
    const int b = idx / LSIG;
    const int i = idx - b * LSIG;
    const int t = i / SHIFT;
    const int j = i - t * SHIFT;
    const float* yb = g_y + (size_t)b * TIN * FRAME;
    float v = yb[(size_t)t * FRAME + j];
    if (t > 0) { v += yb[(size_t)(t - 1) * FRAME + j + SHIFT]; v *= 0.5f; }
    out[idx] = v;
}

// ---------------- launch ----------------
extern "C" void kernel_launch(void* const* d_in, const int* in_sizes, int n_in,
                              void* d_out, int out_size)
{
    const float* input   = (const float*)d_in[0];
    const float* anchor  = (const float*)d_in[1];
    const int*   aux_len = (const int*)  d_in[2];
    const float* in_w    = (const float*)d_in[4];
    const float* in_b    = (const float*)d_in[5];
    const float* out_w   = (const float*)d_in[6];
    const float* out_b   = (const float*)d_in[7];
    const float* gln_g   = (const float*)d_in[8];
    const float* gln_b   = (const float*)d_in[9];
    const float* ecapa_w = (const float*)d_in[10];
    const float* ecapa_b = (const float*)d_in[11];
    const float* att_w1  = (const float*)d_in[12];
    const float* att_b1  = (const float*)d_in[13];
    const float* attbn_g = (const float*)d_in[14];
    const float* attbn_b = (const float*)d_in[15];
    const float* att_w2  = (const float*)d_in[16];
    const float* att_b2  = (const float*)d_in[17];
    const float* bn5_g   = (const float*)d_in[18];
    const float* bn5_b   = (const float*)d_in[19];
    const float* fc6_w   = (const float*)d_in[20];
    const float* fc6_b   = (const float*)d_in[21];
    const float* bn6_g   = (const float*)d_in[22];
    const float* bn6_b   = (const float*)d_in[23];
    const float* cls_w   = (const float*)d_in[24];
    const float* cls_b   = (const float*)d_in[25];
    const float* arn_w1  = (const float*)d_in[26];
    const float* arn_w2  = (const float*)d_in[27];
    const float* arn_b   = (const float*)d_in[28];

    float *p_out, *p_out2, *p_aux, *p_h, *p_a, *p_logits, *p_y;
    cudaGetSymbolAddress((void**)&p_out,    g_out);
    cudaGetSymbolAddress((void**)&p_out2,   g_out2);
    cudaGetSymbolAddress((void**)&p_aux,    g_aux);
    cudaGetSymbolAddress((void**)&p_h,      g_h);
    cudaGetSymbolAddress((void**)&p_a,      g_a);
    cudaGetSymbolAddress((void**)&p_logits, g_logits);
    cudaGetSymbolAddress((void**)&p_y,      g_y);

    __half *pw_in, *pw_ec, *pw_a1, *pw_a2, *pw_ar, *pw_ou;
    cudaGetSymbolAddress((void**)&pw_in, w_in_f);
    cudaGetSymbolAddress((void**)&pw_ec, w_ec_f);
    cudaGetSymbolAddress((void**)&pw_a1, w_a1_f);
    cudaGetSymbolAddress((void**)&pw_a2, w_a2_f);
    cudaGetSymbolAddress((void**)&pw_ar, w_arn_f);
    cudaGetSymbolAddress((void**)&pw_ou, w_out_f);

    // ---- single fused weight-prep (tiled transpose -> fp16) ----
    PrepArgs pa;
    int toff = 0;
    auto reg = [&](int r, const float* s, __half* d, int K, int N) {
        pa.src[r] = s; pa.dst[r] = d; pa.K[r] = K; pa.N[r] = N;
        pa.toff[r] = toff; toff += (K / 32) * (N / 32);
    };
    reg(0, in_w,    pw_in, 320, 256);
    reg(1, ecapa_w, pw_ec, 256, 256);
    reg(2, att_w1,  pw_a1, 256, 256);
    reg(3, att_w2,  pw_a2, 256, 256);
    for (int i = 0; i < 4; i++)
        reg(4 + i, arn_w1 + (size_t)i * 65536, pw_ar + (size_t)i * 65536, 256, 256);
    reg(8, out_w, pw_ou, 256, 320);
    pa.toff[9] = toff;
    pa.src[9] = out_w; pa.dst[9] = pw_ou; pa.K[9] = 256; pa.N[9] = 320;
    pa.toff[10] = toff;
    k_prep_all<<<toff, 256>>>(pa);

    // double-buffered: A 2x8KB + B 2xNT*128B
    const int SM128 = 2 * 8192 + 2 * 128 * 128;   // 49152
    const int SM160 = 2 * 8192 + 2 * 160 * 128;   // 57344
    cudaFuncSetAttribute(k_tgemm<128,0>, cudaFuncAttributeMaxDynamicSharedMemorySize, SM128);
    cudaFuncSetAttribute(k_tgemm<128,1>, cudaFuncAttributeMaxDynamicSharedMemorySize, SM128);
    cudaFuncSetAttribute(k_tgemm<128,2>, cudaFuncAttributeMaxDynamicSharedMemorySize, SM128);
    cudaFuncSetAttribute(k_tgemm<128,3>, cudaFuncAttributeMaxDynamicSharedMemorySize, SM128);
    cudaFuncSetAttribute(k_tgemm<128,4>, cudaFuncAttributeMaxDynamicSharedMemorySize, SM128);
    cudaFuncSetAttribute(k_tgemm<160,3>, cudaFuncAttributeMaxDynamicSharedMemorySize, SM160);

    // 1. merged encoders: x blocks [0,16) -> input, [16,23) -> anchor; z = 2 N-halves
    k_tgemm<128,0><<<dim3(23, 32, 2), 256, SM128>>>(input, pw_in, p_out, in_b,
                                                    nullptr, nullptr, nullptr, TIN, FRAME, FDIM, LSIG, 0,
                                                    anchor, p_aux, TA, LAUX, 16);
    // 2. GLN partials (combine folded into next GEMM)
    k_gln_part<<<dim3(32, 16), 256>>>(aux_len);
    // 3. GLN + ecapa + relu
    k_tgemm<128,1><<<dim3(7, 32, 2), 256, SM128>>>(p_aux, pw_ec, p_h, gln_g, gln_b,
                                                   ecapa_b, aux_len, TA, FDIM, HDIM, 0, 0,
                                                   nullptr, nullptr, 0, 0, 0);
    // 4. h stats + attention bias
    k_hpart<<<dim3(32, NSLC), 256>>>(aux_len);
    k_hcomb<<<32, 256>>>(aux_len, att_w1, att_b1);
    // 5. attention conv1(+relu+bn+tanh)
    k_tgemm<128,2><<<dim3(7, 32, 2), 256, SM128>>>(p_h, pw_a1, p_a, attbn_g, attbn_b,
                                                   nullptr, nullptr, TA, HDIM, HDIM, 0, 0,
                                                   nullptr, nullptr, 0, 0, 0);
    // 6. attention conv2
    k_tgemm<128,3><<<dim3(7, 32, 2), 256, SM128>>>(p_a, pw_a2, p_logits, att_b2,
                                                   nullptr, nullptr, nullptr, TA, HDIM, HDIM, 0, 0,
                                                   nullptr, nullptr, 0, 0, 0);
    // 7. pool + emb + classifier + evec
    k_ppart<<<dim3(32, NSLC), 256>>>(aux_len);
    const int write_cls = (out_size >= BDIM * LSIG + BDIM * NCLS) ? 1 : 0;
    k_pcomb<<<32, 256>>>(bn5_g, bn5_b, fc6_w, fc6_b, bn6_g, bn6_b, cls_w, cls_b,
                         arn_w2, (float*)d_out + (size_t)BDIM * LSIG, write_cls);
    // 8-11. 4 ARN residual blocks (ping-pong)
    const float* src = p_out;
    float*       dst = p_out2;
    for (int i = 0; i < 4; i++) {
        k_tgemm<128,4><<<dim3(16, 32, 2), 256, SM128>>>(src, pw_ar + (size_t)i * 65536, dst,
                                                        arn_b + i * FDIM, nullptr, nullptr,
                                                        nullptr, TIN, FDIM, FDIM, 0, i,
                                                        nullptr, nullptr, 0, 0, 0);
        const float* tmp = dst; dst = (float*)src; src = tmp;
    }
    // 12. decoder (N=320 in two 160-col halves)
    k_tgemm<160,3><<<dim3(16, 32, 2), 256, SM160>>>(src, pw_ou, p_y, out_b,
                                                    nullptr, nullptr, nullptr, TIN, FDIM, FRAME, 0, 0,
                                                    nullptr, nullptr, 0, 0, 0);
    // 13. OLA
    k_ola<<<(BDIM * LSIG + 255) / 256, 256>>>((float*)d_out);
}